// round 1
// baseline (speedup 1.0000x reference)
#include <cuda_runtime.h>
#include <math.h>

#define DIMN 2048
#define NHEADS 16
#define HDIM 128
#define BATCH 2
#define LQ 4096
#define LCTX 769
#define IMG_T 257
#define TXT_T 512
#define EPS_F 1e-6f
#define ATT_SCALE 0.08838834764831845f  /* 1/sqrt(128) */

// ---------------- scratch (device globals; no allocs allowed) --------------
__device__ float g_Q   [BATCH * LQ    * DIMN];
__device__ float g_Ktxt[BATCH * TXT_T * DIMN];
__device__ float g_Vtxt[BATCH * TXT_T * DIMN];
__device__ float g_Kimg[BATCH * IMG_T * DIMN];
__device__ float g_Vimg[BATCH * IMG_T * DIMN];
__device__ float g_attn[BATCH * LQ    * DIMN];

// ---------------- GEMM: C[M,N] = A[M,K] @ W[N,K]^T + bias ------------------
// A rows are remapped: logical row m -> batch bb = m / rows_pb,
// physical row = bb*bstride + roff + (m - bb*rows_pb). Lets us slice
// context[:, :257] and context[:, 257:] without copies.
#define GBM 128
#define GBN 128
#define GBK 16
#define LDT 132   // padded smem stride

__global__ __launch_bounds__(256, 2)
void gemm_nt_bias(const float* __restrict__ A, const float* __restrict__ W,
                  const float* __restrict__ bias, float* __restrict__ C,
                  int M, int rows_pb, int bstride, int roff)
{
    const int K = DIMN, N = DIMN;
    __shared__ float As[GBK * LDT];
    __shared__ float Bs[GBK * LDT];

    const int tid = threadIdx.x;
    const int m0 = blockIdx.y * GBM;
    const int n0 = blockIdx.x * GBN;
    const int ty = tid >> 4;      // 0..15
    const int tx = tid & 15;      // 0..15

    float acc[8][8];
#pragma unroll
    for (int i = 0; i < 8; i++)
#pragma unroll
        for (int j = 0; j < 8; j++) acc[i][j] = 0.f;

    for (int k0 = 0; k0 < K; k0 += GBK) {
#pragma unroll
        for (int i = 0; i < 2; i++) {
            const int f  = tid + i * 256;   // 0..511
            const int r  = f >> 2;          // 0..127
            const int c4 = f & 3;           // 0..3

            // A tile (transposed into smem)
            const int m = m0 + r;
            float4 va = make_float4(0.f, 0.f, 0.f, 0.f);
            if (m < M) {
                const int bb = m / rows_pb;
                const long arow = (long)bb * bstride + roff + (m - bb * rows_pb);
                va = *(const float4*)(A + arow * (long)K + k0 + c4 * 4);
            }
            As[(c4 * 4 + 0) * LDT + r] = va.x;
            As[(c4 * 4 + 1) * LDT + r] = va.y;
            As[(c4 * 4 + 2) * LDT + r] = va.z;
            As[(c4 * 4 + 3) * LDT + r] = va.w;

            // W tile (N always multiple of 128 here -> no guard)
            const int n = n0 + r;
            const float4 vb = *(const float4*)(W + (long)n * K + k0 + c4 * 4);
            Bs[(c4 * 4 + 0) * LDT + r] = vb.x;
            Bs[(c4 * 4 + 1) * LDT + r] = vb.y;
            Bs[(c4 * 4 + 2) * LDT + r] = vb.z;
            Bs[(c4 * 4 + 3) * LDT + r] = vb.w;
        }
        __syncthreads();

#pragma unroll
        for (int k = 0; k < GBK; k++) {
            const float4 a0 = *(const float4*)&As[k * LDT + ty * 8];
            const float4 a1 = *(const float4*)&As[k * LDT + ty * 8 + 4];
            const float4 b0 = *(const float4*)&Bs[k * LDT + tx * 8];
            const float4 b1 = *(const float4*)&Bs[k * LDT + tx * 8 + 4];
            const float a[8] = {a0.x, a0.y, a0.z, a0.w, a1.x, a1.y, a1.z, a1.w};
            const float b[8] = {b0.x, b0.y, b0.z, b0.w, b1.x, b1.y, b1.z, b1.w};
#pragma unroll
            for (int i = 0; i < 8; i++)
#pragma unroll
                for (int j = 0; j < 8; j++) acc[i][j] += a[i] * b[j];
        }
        __syncthreads();
    }

    const float4 bb0 = *(const float4*)&bias[n0 + tx * 8];
    const float4 bb1 = *(const float4*)&bias[n0 + tx * 8 + 4];
#pragma unroll
    for (int i = 0; i < 8; i++) {
        const int m = m0 + ty * 8 + i;
        if (m < M) {
            float4 o0 = make_float4(acc[i][0] + bb0.x, acc[i][1] + bb0.y,
                                    acc[i][2] + bb0.z, acc[i][3] + bb0.w);
            float4 o1 = make_float4(acc[i][4] + bb1.x, acc[i][5] + bb1.y,
                                    acc[i][6] + bb1.z, acc[i][7] + bb1.w);
            *(float4*)(C + (long)m * N + n0 + tx * 8)     = o0;
            *(float4*)(C + (long)m * N + n0 + tx * 8 + 4) = o1;
        }
    }
}

// ---------------- RMS norm over last dim (2048), in place ------------------
__global__ __launch_bounds__(256)
void rmsnorm_kernel(float* __restrict__ X, const float* __restrict__ g)
{
    const int row = blockIdx.x;
    float* xr = X + (long)row * DIMN;
    const int t = threadIdx.x;

    float4 v0 = *(float4*)&xr[t * 4];
    float4 v1 = *(float4*)&xr[1024 + t * 4];
    float ss = v0.x * v0.x + v0.y * v0.y + v0.z * v0.z + v0.w * v0.w
             + v1.x * v1.x + v1.y * v1.y + v1.z * v1.z + v1.w * v1.w;

#pragma unroll
    for (int o = 16; o > 0; o >>= 1) ss += __shfl_xor_sync(0xffffffffu, ss, o);

    __shared__ float red[8];
    if ((t & 31) == 0) red[t >> 5] = ss;
    __syncthreads();
    float total = 0.f;
#pragma unroll
    for (int i = 0; i < 8; i++) total += red[i];

    const float scale = rsqrtf(total * (1.0f / DIMN) + EPS_F);

    const float4 g0 = *(const float4*)&g[t * 4];
    const float4 g1 = *(const float4*)&g[1024 + t * 4];
    v0.x *= scale * g0.x; v0.y *= scale * g0.y; v0.z *= scale * g0.z; v0.w *= scale * g0.w;
    v1.x *= scale * g1.x; v1.y *= scale * g1.y; v1.z *= scale * g1.z; v1.w *= scale * g1.w;
    *(float4*)&xr[t * 4]        = v0;
    *(float4*)&xr[1024 + t * 4] = v1;
}

// ---------------- dual attention (img + txt), exact softmax ----------------
// Block: (q-tile of 64, head, batch). Full score rows in smem (max 512 keys).
#define LDQ 132
#define LDK 132
#define LDS 516
#define SMEM_FLOATS (64 * LDQ + 64 * LDK + 64 * LDS)

#define DOT4(A, Bv) ((A).x * (Bv).x + (A).y * (Bv).y + (A).z * (Bv).z + (A).w * (Bv).w)

__global__ __launch_bounds__(256, 1)
void attn_kernel(const int* __restrict__ lens)
{
    extern __shared__ float smem[];
    float* Qs = smem;                 // [64][LDQ]
    float* Ks = Qs + 64 * LDQ;        // [64][LDK]  (also reused for V chunks)
    float* Ss = Ks + 64 * LDK;        // [64][LDS]

    const int qt = blockIdx.x, h = blockIdx.y, b = blockIdx.z;
    const int tid = threadIdx.x;
    const int q0 = qt * 64;

    // load Q tile: rows b*LQ+q0..+63, cols h*128..h*128+127
    for (int f = tid; f < 64 * 32; f += 256) {
        const int r = f >> 5, d4 = f & 31;
        const float4 v = *(const float4*)&g_Q[((long)(b * LQ + q0 + r)) * DIMN + h * HDIM + d4 * 4];
        *(float4*)&Qs[r * LDQ + d4 * 4] = v;
    }

    float o[4][8];
#pragma unroll
    for (int a = 0; a < 4; a++)
#pragma unroll
        for (int j = 0; j < 8; j++) o[a][j] = 0.f;

    const int ty = tid >> 4;  // 0..15
    const int tx = tid & 15;  // 0..15

    for (int ph = 0; ph < 2; ph++) {
        const float* Kp; const float* Vp; int Lk, valid;
        if (ph == 0) {
            Kp = g_Kimg + (long)b * IMG_T * DIMN;
            Vp = g_Vimg + (long)b * IMG_T * DIMN;
            Lk = IMG_T; valid = IMG_T;
        } else {
            Kp = g_Ktxt + (long)b * TXT_T * DIMN;
            Vp = g_Vtxt + (long)b * TXT_T * DIMN;
            Lk = TXT_T;
            valid = lens[b];
            if (valid > TXT_T) valid = TXT_T;
        }
        const int nch = (Lk + 63) >> 6;
        const int padded = nch * 64;

        // ---- scores ----
        for (int c = 0; c < nch; c++) {
            __syncthreads();   // protect Ks/Ss reuse
            for (int f = tid; f < 64 * 32; f += 256) {
                const int r = f >> 5, d4 = f & 31;
                const int kr = c * 64 + r;
                float4 v = make_float4(0.f, 0.f, 0.f, 0.f);
                if (kr < Lk)
                    v = *(const float4*)&Kp[(long)kr * DIMN + h * HDIM + d4 * 4];
                *(float4*)&Ks[r * LDK + d4 * 4] = v;
            }
            __syncthreads();

            float s[4][4];
#pragma unroll
            for (int a = 0; a < 4; a++)
#pragma unroll
                for (int cc = 0; cc < 4; cc++) s[a][cc] = 0.f;

#pragma unroll
            for (int d4 = 0; d4 < 32; d4++) {
                float4 qv[4], kv[4];
#pragma unroll
                for (int a = 0; a < 4; a++)
                    qv[a] = *(const float4*)&Qs[(ty + a * 16) * LDQ + d4 * 4];
#pragma unroll
                for (int cc = 0; cc < 4; cc++)
                    kv[cc] = *(const float4*)&Ks[(tx + cc * 16) * LDK + d4 * 4];
#pragma unroll
                for (int a = 0; a < 4; a++)
#pragma unroll
                    for (int cc = 0; cc < 4; cc++)
                        s[a][cc] += DOT4(qv[a], kv[cc]);
            }
#pragma unroll
            for (int a = 0; a < 4; a++)
#pragma unroll
                for (int cc = 0; cc < 4; cc++)
                    Ss[(ty + a * 16) * LDS + c * 64 + tx + cc * 16] = s[a][cc];
        }
        __syncthreads();

        // ---- softmax (each row owned by a 4-lane group) ----
        {
            const int row = tid >> 2;
            const int lane = tid & 3;
            float* Sr = Ss + row * LDS;
            float mx = -1e30f;
            for (int j = lane; j < valid; j += 4) mx = fmaxf(mx, Sr[j]);
            mx = fmaxf(mx, __shfl_xor_sync(0xffffffffu, mx, 1));
            mx = fmaxf(mx, __shfl_xor_sync(0xffffffffu, mx, 2));
            mx *= ATT_SCALE;
            float sum = 0.f;
            for (int j = lane; j < padded; j += 4) {
                float e = 0.f;
                if (j < valid) e = __expf(Sr[j] * ATT_SCALE - mx);
                Sr[j] = e;
                sum += e;
            }
            sum += __shfl_xor_sync(0xffffffffu, sum, 1);
            sum += __shfl_xor_sync(0xffffffffu, sum, 2);
            const float inv = 1.0f / sum;
            for (int j = lane; j < padded; j += 4) Sr[j] *= inv;
        }
        __syncthreads();

        // ---- P @ V ----
        for (int c = 0; c < nch; c++) {
            for (int f = tid; f < 64 * 32; f += 256) {
                const int r = f >> 5, d4 = f & 31;
                const int kr = c * 64 + r;
                float4 v = make_float4(0.f, 0.f, 0.f, 0.f);
                if (kr < Lk)
                    v = *(const float4*)&Vp[(long)kr * DIMN + h * HDIM + d4 * 4];
                *(float4*)&Ks[r * LDK + d4 * 4] = v;
            }
            __syncthreads();

            const int cb = c * 64;
#pragma unroll 8
            for (int kj = 0; kj < 64; kj++) {
                const float p0 = Ss[(ty)      * LDS + cb + kj];
                const float p1 = Ss[(ty + 16) * LDS + cb + kj];
                const float p2 = Ss[(ty + 32) * LDS + cb + kj];
                const float p3 = Ss[(ty + 48) * LDS + cb + kj];
                const float4 v0 = *(const float4*)&Ks[kj * LDK + tx * 8];
                const float4 v1 = *(const float4*)&Ks[kj * LDK + tx * 8 + 4];
#define PV_ACC(a, p)                                                      \
                o[a][0] += (p) * v0.x; o[a][1] += (p) * v0.y;             \
                o[a][2] += (p) * v0.z; o[a][3] += (p) * v0.w;             \
                o[a][4] += (p) * v1.x; o[a][5] += (p) * v1.y;             \
                o[a][6] += (p) * v1.z; o[a][7] += (p) * v1.w;
                PV_ACC(0, p0) PV_ACC(1, p1) PV_ACC(2, p2) PV_ACC(3, p3)
#undef PV_ACC
            }
            __syncthreads();
        }
    }

    // write accumulated (img + txt) output
#pragma unroll
    for (int a = 0; a < 4; a++) {
        const long row = (long)(b * LQ + q0 + ty + a * 16);
        float4 w0 = make_float4(o[a][0], o[a][1], o[a][2], o[a][3]);
        float4 w1 = make_float4(o[a][4], o[a][5], o[a][6], o[a][7]);
        *(float4*)&g_attn[row * DIMN + h * HDIM + tx * 8]     = w0;
        *(float4*)&g_attn[row * DIMN + h * HDIM + tx * 8 + 4] = w1;
    }
}

// ---------------------------- launch ---------------------------------------
extern "C" void kernel_launch(void* const* d_in, const int* in_sizes, int n_in,
                              void* d_out, int out_size)
{
    const float* x        = (const float*)d_in[0];
    const float* context  = (const float*)d_in[1];
    const int*   lens     = (const int*)  d_in[2];
    const float* w_q      = (const float*)d_in[3];
    const float* b_q      = (const float*)d_in[4];
    const float* w_k      = (const float*)d_in[5];
    const float* b_k      = (const float*)d_in[6];
    const float* w_v      = (const float*)d_in[7];
    const float* b_v      = (const float*)d_in[8];
    const float* w_k_img  = (const float*)d_in[9];
    const float* b_k_img  = (const float*)d_in[10];
    const float* w_v_img  = (const float*)d_in[11];
    const float* b_v_img  = (const float*)d_in[12];
    const float* w_o      = (const float*)d_in[13];
    const float* b_o      = (const float*)d_in[14];
    const float* g_q      = (const float*)d_in[15];
    const float* g_k      = (const float*)d_in[16];
    const float* g_k_img  = (const float*)d_in[17];
    float* out = (float*)d_out;

    float *Qb, *Ktb, *Vtb, *Kib, *Vib, *Ab;
    cudaGetSymbolAddress((void**)&Qb,  g_Q);
    cudaGetSymbolAddress((void**)&Ktb, g_Ktxt);
    cudaGetSymbolAddress((void**)&Vtb, g_Vtxt);
    cudaGetSymbolAddress((void**)&Kib, g_Kimg);
    cudaGetSymbolAddress((void**)&Vib, g_Vimg);
    cudaGetSymbolAddress((void**)&Ab,  g_attn);

    const dim3 gemm_block(256);

    // Q = rmsnorm(x @ w_q^T + b_q)
    gemm_nt_bias<<<dim3(16, 64), gemm_block>>>(x, w_q, b_q, Qb,
                                               BATCH * LQ, BATCH * LQ, 0, 0);
    rmsnorm_kernel<<<BATCH * LQ, 256>>>(Qb, g_q);

    // K_txt / V_txt from context[:, 257:769]
    gemm_nt_bias<<<dim3(16, 8), gemm_block>>>(context, w_k, b_k, Ktb,
                                              BATCH * TXT_T, TXT_T, LCTX, IMG_T);
    rmsnorm_kernel<<<BATCH * TXT_T, 256>>>(Ktb, g_k);
    gemm_nt_bias<<<dim3(16, 8), gemm_block>>>(context, w_v, b_v, Vtb,
                                              BATCH * TXT_T, TXT_T, LCTX, IMG_T);

    // K_img / V_img from context[:, :257]
    gemm_nt_bias<<<dim3(16, 5), gemm_block>>>(context, w_k_img, b_k_img, Kib,
                                              BATCH * IMG_T, IMG_T, LCTX, 0);
    rmsnorm_kernel<<<BATCH * IMG_T, 256>>>(Kib, g_k_img);
    gemm_nt_bias<<<dim3(16, 5), gemm_block>>>(context, w_v_img, b_v_img, Vib,
                                              BATCH * IMG_T, IMG_T, LCTX, 0);

    // attention (img + txt) -> g_attn
    const int smem_bytes = SMEM_FLOATS * (int)sizeof(float);
    cudaFuncSetAttribute(attn_kernel, cudaFuncAttributeMaxDynamicSharedMemorySize, smem_bytes);
    attn_kernel<<<dim3(LQ / 64, NHEADS, BATCH), 256, smem_bytes>>>(lens);

    // out = attn @ w_o^T + b_o
    gemm_nt_bias<<<dim3(16, 64), gemm_block>>>(Ab, w_o, b_o, out,
                                               BATCH * LQ, BATCH * LQ, 0, 0);
}

// round 3
// speedup vs baseline: 1.8369x; 1.8369x over previous
#include <cuda_runtime.h>
#include <cuda_bf16.h>
#include <math.h>
#include <stdint.h>

#define DIMN 2048
#define NHEADS 16
#define HDIM 128
#define BATCH 2
#define LQ 4096
#define LCTX 769
#define IMG_T 257
#define TXT_T 512
#define EPS_F 1e-6f
#define ATT_SCALE 0.08838834764831845f  /* 1/sqrt(128) */

// ---------------- scratch (device globals; no allocs allowed) --------------
__device__ float g_Q   [BATCH * LQ    * DIMN];
__device__ float g_Ktxt[BATCH * TXT_T * DIMN];
__device__ float g_Vtxt[BATCH * TXT_T * DIMN];
__device__ float g_Kimg[BATCH * IMG_T * DIMN];
__device__ float g_Vimg[BATCH * IMG_T * DIMN];
__device__ float g_attn[BATCH * LQ    * DIMN];

// bf16 hi/lo split buffers
#define MPAD_IMG 640
__device__ __nv_bfloat16 g_xh [BATCH * LQ * DIMN];
__device__ __nv_bfloat16 g_xl [BATCH * LQ * DIMN];
__device__ __nv_bfloat16 g_ah [BATCH * LQ * DIMN];
__device__ __nv_bfloat16 g_al [BATCH * LQ * DIMN];
__device__ __nv_bfloat16 g_cth[BATCH * TXT_T * DIMN];
__device__ __nv_bfloat16 g_ctl[BATCH * TXT_T * DIMN];
__device__ __nv_bfloat16 g_cih[MPAD_IMG * DIMN];
__device__ __nv_bfloat16 g_cil[MPAD_IMG * DIMN];
__device__ __nv_bfloat16 g_wqh [DIMN * DIMN], g_wql [DIMN * DIMN];
__device__ __nv_bfloat16 g_wkh [DIMN * DIMN], g_wkl [DIMN * DIMN];
__device__ __nv_bfloat16 g_wvh [DIMN * DIMN], g_wvl [DIMN * DIMN];
__device__ __nv_bfloat16 g_wkih[DIMN * DIMN], g_wkil[DIMN * DIMN];
__device__ __nv_bfloat16 g_wvih[DIMN * DIMN], g_wvil[DIMN * DIMN];
__device__ __nv_bfloat16 g_woh [DIMN * DIMN], g_wol [DIMN * DIMN];

// ---------------------------- helpers ---------------------------------------
__device__ __forceinline__ uint32_t smem_u32(const void* p) {
    uint32_t a;
    asm("{ .reg .u64 t; cvta.to.shared.u64 t, %1; cvt.u32.u64 %0, t; }"
        : "=r"(a) : "l"(p));
    return a;
}

__device__ __forceinline__ void mma16816(float* d, const uint32_t* a,
                                         const uint32_t b0, const uint32_t b1) {
    asm volatile(
        "mma.sync.aligned.m16n8k16.row.col.f32.bf16.bf16.f32 "
        "{%0,%1,%2,%3}, {%4,%5,%6,%7}, {%8,%9}, {%0,%1,%2,%3};"
        : "+f"(d[0]), "+f"(d[1]), "+f"(d[2]), "+f"(d[3])
        : "r"(a[0]), "r"(a[1]), "r"(a[2]), "r"(a[3]), "r"(b0), "r"(b1));
}

// -------------- fp32 -> bf16 hi/lo split (with row remap + pad) ------------
__global__ __launch_bounds__(256)
void cvt_split(const float* __restrict__ src,
               __nv_bfloat16* __restrict__ hi, __nv_bfloat16* __restrict__ lo,
               int Mvalid, int rows_pb, int bstride, int roff)
{
    const long i4 = (long)blockIdx.x * 256 + threadIdx.x;
    const long e  = i4 * 4;
    const int  m  = (int)(e >> 11);
    const int  col = (int)(e & 2047);

    float4 v = make_float4(0.f, 0.f, 0.f, 0.f);
    if (m < Mvalid) {
        const int bb = m / rows_pb;
        const long srow = (long)bb * bstride + roff + (m - bb * rows_pb);
        v = *(const float4*)(src + srow * DIMN + col);
    }
    __nv_bfloat16 h0 = __float2bfloat16(v.x);
    __nv_bfloat16 h1 = __float2bfloat16(v.y);
    __nv_bfloat16 h2 = __float2bfloat16(v.z);
    __nv_bfloat16 h3 = __float2bfloat16(v.w);
    __nv_bfloat16 l0 = __float2bfloat16(v.x - __bfloat162float(h0));
    __nv_bfloat16 l1 = __float2bfloat16(v.y - __bfloat162float(h1));
    __nv_bfloat16 l2 = __float2bfloat16(v.z - __bfloat162float(h2));
    __nv_bfloat16 l3 = __float2bfloat16(v.w - __bfloat162float(h3));
    ushort4 H = make_ushort4(__bfloat16_as_ushort(h0), __bfloat16_as_ushort(h1),
                             __bfloat16_as_ushort(h2), __bfloat16_as_ushort(h3));
    ushort4 L = make_ushort4(__bfloat16_as_ushort(l0), __bfloat16_as_ushort(l1),
                             __bfloat16_as_ushort(l2), __bfloat16_as_ushort(l3));
    *(ushort4*)(hi + e) = H;
    *(ushort4*)(lo + e) = L;
}

// ------------- HMMA GEMM: C = (Ah+Al)(Bh+Bl)^T + bias (3 terms) ------------
// Block 128x128, 8 warps (4x2), warp tile 32x64, K-chunk 32, double-buffered.
#define GT_KC 32
#define NCHUNK (DIMN / GT_KC)      /* 64 */
#define LDAB 40                    /* smem row stride in bf16 (80 B) */
#define TILE_ELE (128 * LDAB)      /* bf16 elems per tile */
#define BUF_ELE  (4 * TILE_ELE)
#define GEMM_SMEM (2 * BUF_ELE * 2)  /* bytes */

__global__ __launch_bounds__(256, 2)
void gemm_tc(const __nv_bfloat16* __restrict__ Ah, const __nv_bfloat16* __restrict__ Al,
             const __nv_bfloat16* __restrict__ Bh, const __nv_bfloat16* __restrict__ Bl,
             const float* __restrict__ bias, float* __restrict__ C, int Mvalid)
{
    extern __shared__ __nv_bfloat16 sm[];

    const int tid = threadIdx.x;
    const int wid = tid >> 5;
    const int lane = tid & 31;
    const int m0 = blockIdx.y * 128;
    const int n0 = blockIdx.x * 128;

    const int wm = wid & 3;        // 0..3  (32 rows each)
    const int wn = wid >> 2;       // 0..1  (64 cols each)
    const int lr = lane >> 2;      // 0..7
    const int lc = (lane & 3) * 2; // 0,2,4,6

    const __nv_bfloat16* srcs[4] = {
        Ah + (size_t)m0 * DIMN, Al + (size_t)m0 * DIMN,
        Bh + (size_t)n0 * DIMN, Bl + (size_t)n0 * DIMN };

    const uint32_t smb = smem_u32(sm);

    auto load_chunk = [&](int c, int b) {
        const int k0 = c * GT_KC;
#pragma unroll
        for (int j = 0; j < 8; j++) {
            const int f = j * 256 + tid;          // 0..2047
            const int tile = f >> 9;              // 0..3
            const int w = f & 511;
            const int r = w >> 2;                 // 0..127
            const int cc = w & 3;                 // 16B chunk
            const __nv_bfloat16* sp = srcs[tile] + (size_t)r * DIMN + k0 + cc * 8;
            const uint32_t dp = smb + ((b * BUF_ELE + tile * TILE_ELE + r * LDAB + cc * 8) << 1);
            asm volatile("cp.async.cg.shared.global [%0], [%1], 16;"
                         :: "r"(dp), "l"(sp) : "memory");
        }
        asm volatile("cp.async.commit_group;" ::: "memory");
    };

    float acc[2][8][4];
#pragma unroll
    for (int i = 0; i < 2; i++)
#pragma unroll
        for (int j = 0; j < 8; j++)
#pragma unroll
            for (int q = 0; q < 4; q++) acc[i][j][q] = 0.f;

    load_chunk(0, 0);
    load_chunk(1, 1);

    for (int c = 0; c < NCHUNK; c++) {
        const int b = c & 1;
        if (c == NCHUNK - 1) asm volatile("cp.async.wait_group 0;" ::: "memory");
        else                 asm volatile("cp.async.wait_group 1;" ::: "memory");
        __syncthreads();

        const __nv_bfloat16* Ahs = sm + b * BUF_ELE;
        const __nv_bfloat16* Als = Ahs + TILE_ELE;
        const __nv_bfloat16* Bhs = Als + TILE_ELE;
        const __nv_bfloat16* Bls = Bhs + TILE_ELE;

#pragma unroll
        for (int s = 0; s < 2; s++) {
            const int ks = s * 16;
            uint32_t ah[2][4], al[2][4];
#pragma unroll
            for (int mt = 0; mt < 2; mt++) {
                const int rb = wm * 32 + mt * 16 + lr;
                ah[mt][0] = *(const uint32_t*)&Ahs[(rb)     * LDAB + ks + lc];
                ah[mt][1] = *(const uint32_t*)&Ahs[(rb + 8) * LDAB + ks + lc];
                ah[mt][2] = *(const uint32_t*)&Ahs[(rb)     * LDAB + ks + lc + 8];
                ah[mt][3] = *(const uint32_t*)&Ahs[(rb + 8) * LDAB + ks + lc + 8];
                al[mt][0] = *(const uint32_t*)&Als[(rb)     * LDAB + ks + lc];
                al[mt][1] = *(const uint32_t*)&Als[(rb + 8) * LDAB + ks + lc];
                al[mt][2] = *(const uint32_t*)&Als[(rb)     * LDAB + ks + lc + 8];
                al[mt][3] = *(const uint32_t*)&Als[(rb + 8) * LDAB + ks + lc + 8];
            }
#pragma unroll
            for (int nt = 0; nt < 8; nt++) {
                const int nb = wn * 64 + nt * 8 + lr;
                const uint32_t bh0 = *(const uint32_t*)&Bhs[nb * LDAB + ks + lc];
                const uint32_t bh1 = *(const uint32_t*)&Bhs[nb * LDAB + ks + lc + 8];
                const uint32_t bl0 = *(const uint32_t*)&Bls[nb * LDAB + ks + lc];
                const uint32_t bl1 = *(const uint32_t*)&Bls[nb * LDAB + ks + lc + 8];
#pragma unroll
                for (int mt = 0; mt < 2; mt++) {
                    mma16816(acc[mt][nt], ah[mt], bh0, bh1);
                    mma16816(acc[mt][nt], ah[mt], bl0, bl1);
                    mma16816(acc[mt][nt], al[mt], bh0, bh1);
                }
            }
        }
        __syncthreads();
        if (c + 2 < NCHUNK) load_chunk(c + 2, b);
    }

    // epilogue: d{0,1} -> (m = base+lr, n = nt*8+lc,+1); d{2,3} -> m+8
#pragma unroll
    for (int mt = 0; mt < 2; mt++) {
#pragma unroll
        for (int nt = 0; nt < 8; nt++) {
            const int n = n0 + wn * 64 + nt * 8 + lc;
            const float2 bv = *(const float2*)&bias[n];
            const int mA = m0 + wm * 32 + mt * 16 + lr;
            if (mA < Mvalid) {
                float2 o = make_float2(acc[mt][nt][0] + bv.x, acc[mt][nt][1] + bv.y);
                *(float2*)(C + (size_t)mA * DIMN + n) = o;
            }
            if (mA + 8 < Mvalid) {
                float2 o = make_float2(acc[mt][nt][2] + bv.x, acc[mt][nt][3] + bv.y);
                *(float2*)(C + (size_t)(mA + 8) * DIMN + n) = o;
            }
        }
    }
}

// ---------------- RMS norm over last dim (2048), in place ------------------
__global__ __launch_bounds__(256)
void rmsnorm_kernel(float* __restrict__ X, const float* __restrict__ g)
{
    const int row = blockIdx.x;
    float* xr = X + (long)row * DIMN;
    const int t = threadIdx.x;

    float4 v0 = *(float4*)&xr[t * 4];
    float4 v1 = *(float4*)&xr[1024 + t * 4];
    float ss = v0.x * v0.x + v0.y * v0.y + v0.z * v0.z + v0.w * v0.w
             + v1.x * v1.x + v1.y * v1.y + v1.z * v1.z + v1.w * v1.w;

#pragma unroll
    for (int o = 16; o > 0; o >>= 1) ss += __shfl_xor_sync(0xffffffffu, ss, o);

    __shared__ float red[8];
    if ((t & 31) == 0) red[t >> 5] = ss;
    __syncthreads();
    float total = 0.f;
#pragma unroll
    for (int i = 0; i < 8; i++) total += red[i];

    const float scale = rsqrtf(total * (1.0f / DIMN) + EPS_F);

    const float4 g0 = *(const float4*)&g[t * 4];
    const float4 g1 = *(const float4*)&g[1024 + t * 4];
    v0.x *= scale * g0.x; v0.y *= scale * g0.y; v0.z *= scale * g0.z; v0.w *= scale * g0.w;
    v1.x *= scale * g1.x; v1.y *= scale * g1.y; v1.z *= scale * g1.z; v1.w *= scale * g1.w;
    *(float4*)&xr[t * 4]        = v0;
    *(float4*)&xr[1024 + t * 4] = v1;
}

// ---------------- dual attention (img + txt), exact softmax ----------------
#define LDQ 132
#define LDK 132
#define LDS 516
#define SMEM_FLOATS (64 * LDQ + 64 * LDK + 64 * LDS)

#define DOT4(A, Bv) ((A).x * (Bv).x + (A).y * (Bv).y + (A).z * (Bv).z + (A).w * (Bv).w)

__global__ __launch_bounds__(256, 1)
void attn_kernel(const int* __restrict__ lens)
{
    extern __shared__ float smem[];
    float* Qs = smem;                 // [64][LDQ]
    float* Ks = Qs + 64 * LDQ;        // [64][LDK]  (also reused for V chunks)
    float* Ss = Ks + 64 * LDK;        // [64][LDS]

    const int qt = blockIdx.x, h = blockIdx.y, b = blockIdx.z;
    const int tid = threadIdx.x;
    const int q0 = qt * 64;

    for (int f = tid; f < 64 * 32; f += 256) {
        const int r = f >> 5, d4 = f & 31;
        const float4 v = *(const float4*)&g_Q[((long)(b * LQ + q0 + r)) * DIMN + h * HDIM + d4 * 4];
        *(float4*)&Qs[r * LDQ + d4 * 4] = v;
    }

    float o[4][8];
#pragma unroll
    for (int a = 0; a < 4; a++)
#pragma unroll
        for (int j = 0; j < 8; j++) o[a][j] = 0.f;

    const int ty = tid >> 4;  // 0..15
    const int tx = tid & 15;  // 0..15

    for (int ph = 0; ph < 2; ph++) {
        const float* Kp; const float* Vp; int Lk, valid;
        if (ph == 0) {
            Kp = g_Kimg + (long)b * IMG_T * DIMN;
            Vp = g_Vimg + (long)b * IMG_T * DIMN;
            Lk = IMG_T; valid = IMG_T;
        } else {
            Kp = g_Ktxt + (long)b * TXT_T * DIMN;
            Vp = g_Vtxt + (long)b * TXT_T * DIMN;
            Lk = TXT_T;
            valid = lens[b];
            if (valid > TXT_T) valid = TXT_T;
        }
        const int nch = (Lk + 63) >> 6;
        const int padded = nch * 64;

        // ---- scores ----
        for (int c = 0; c < nch; c++) {
            __syncthreads();
            for (int f = tid; f < 64 * 32; f += 256) {
                const int r = f >> 5, d4 = f & 31;
                const int kr = c * 64 + r;
                float4 v = make_float4(0.f, 0.f, 0.f, 0.f);
                if (kr < Lk)
                    v = *(const float4*)&Kp[(long)kr * DIMN + h * HDIM + d4 * 4];
                *(float4*)&Ks[r * LDK + d4 * 4] = v;
            }
            __syncthreads();

            float s[4][4];
#pragma unroll
            for (int a = 0; a < 4; a++)
#pragma unroll
                for (int cc = 0; cc < 4; cc++) s[a][cc] = 0.f;

#pragma unroll
            for (int d4 = 0; d4 < 32; d4++) {
                float4 qv[4], kv[4];
#pragma unroll
                for (int a = 0; a < 4; a++)
                    qv[a] = *(const float4*)&Qs[(ty + a * 16) * LDQ + d4 * 4];
#pragma unroll
                for (int cc = 0; cc < 4; cc++)
                    kv[cc] = *(const float4*)&Ks[(tx + cc * 16) * LDK + d4 * 4];
#pragma unroll
                for (int a = 0; a < 4; a++)
#pragma unroll
                    for (int cc = 0; cc < 4; cc++)
                        s[a][cc] += DOT4(qv[a], kv[cc]);
            }
#pragma unroll
            for (int a = 0; a < 4; a++)
#pragma unroll
                for (int cc = 0; cc < 4; cc++)
                    Ss[(ty + a * 16) * LDS + c * 64 + tx + cc * 16] = s[a][cc];
        }
        __syncthreads();

        // ---- softmax ----
        {
            const int row = tid >> 2;
            const int lane = tid & 3;
            float* Sr = Ss + row * LDS;
            float mx = -1e30f;
            for (int j = lane; j < valid; j += 4) mx = fmaxf(mx, Sr[j]);
            mx = fmaxf(mx, __shfl_xor_sync(0xffffffffu, mx, 1));
            mx = fmaxf(mx, __shfl_xor_sync(0xffffffffu, mx, 2));
            mx *= ATT_SCALE;
            float sum = 0.f;
            for (int j = lane; j < padded; j += 4) {
                float e = 0.f;
                if (j < valid) e = __expf(Sr[j] * ATT_SCALE - mx);
                Sr[j] = e;
                sum += e;
            }
            sum += __shfl_xor_sync(0xffffffffu, sum, 1);
            sum += __shfl_xor_sync(0xffffffffu, sum, 2);
            const float inv = 1.0f / sum;
            for (int j = lane; j < padded; j += 4) Sr[j] *= inv;
        }
        __syncthreads();

        // ---- P @ V ----
        for (int c = 0; c < nch; c++) {
            for (int f = tid; f < 64 * 32; f += 256) {
                const int r = f >> 5, d4 = f & 31;
                const int kr = c * 64 + r;
                float4 v = make_float4(0.f, 0.f, 0.f, 0.f);
                if (kr < Lk)
                    v = *(const float4*)&Vp[(long)kr * DIMN + h * HDIM + d4 * 4];
                *(float4*)&Ks[r * LDK + d4 * 4] = v;
            }
            __syncthreads();

            const int cb = c * 64;
#pragma unroll 8
            for (int kj = 0; kj < 64; kj++) {
                const float p0 = Ss[(ty)      * LDS + cb + kj];
                const float p1 = Ss[(ty + 16) * LDS + cb + kj];
                const float p2 = Ss[(ty + 32) * LDS + cb + kj];
                const float p3 = Ss[(ty + 48) * LDS + cb + kj];
                const float4 v0 = *(const float4*)&Ks[kj * LDK + tx * 8];
                const float4 v1 = *(const float4*)&Ks[kj * LDK + tx * 8 + 4];
#define PV_ACC(a, p)                                                      \
                o[a][0] += (p) * v0.x; o[a][1] += (p) * v0.y;             \
                o[a][2] += (p) * v0.z; o[a][3] += (p) * v0.w;             \
                o[a][4] += (p) * v1.x; o[a][5] += (p) * v1.y;             \
                o[a][6] += (p) * v1.z; o[a][7] += (p) * v1.w;
                PV_ACC(0, p0) PV_ACC(1, p1) PV_ACC(2, p2) PV_ACC(3, p3)
#undef PV_ACC
            }
            __syncthreads();
        }
    }

#pragma unroll
    for (int a = 0; a < 4; a++) {
        const long row = (long)(b * LQ + q0 + ty + a * 16);
        float4 w0 = make_float4(o[a][0], o[a][1], o[a][2], o[a][3]);
        float4 w1 = make_float4(o[a][4], o[a][5], o[a][6], o[a][7]);
        *(float4*)&g_attn[row * DIMN + h * HDIM + tx * 8]     = w0;
        *(float4*)&g_attn[row * DIMN + h * HDIM + tx * 8 + 4] = w1;
    }
}

// ---------------------------- launch ---------------------------------------
extern "C" void kernel_launch(void* const* d_in, const int* in_sizes, int n_in,
                              void* d_out, int out_size)
{
    const float* x        = (const float*)d_in[0];
    const float* context  = (const float*)d_in[1];
    const int*   lens     = (const int*)  d_in[2];
    const float* w_q      = (const float*)d_in[3];
    const float* b_q      = (const float*)d_in[4];
    const float* w_k      = (const float*)d_in[5];
    const float* b_k      = (const float*)d_in[6];
    const float* w_v      = (const float*)d_in[7];
    const float* b_v      = (const float*)d_in[8];
    const float* w_k_img  = (const float*)d_in[9];
    const float* b_k_img  = (const float*)d_in[10];
    const float* w_v_img  = (const float*)d_in[11];
    const float* b_v_img  = (const float*)d_in[12];
    const float* w_o      = (const float*)d_in[13];
    const float* b_o      = (const float*)d_in[14];
    const float* g_q      = (const float*)d_in[15];
    const float* g_k      = (const float*)d_in[16];
    const float* g_k_img  = (const float*)d_in[17];
    float* out = (float*)d_out;

    float *Qb, *Ktb, *Vtb, *Kib, *Vib, *Ab;
    cudaGetSymbolAddress((void**)&Qb,  g_Q);
    cudaGetSymbolAddress((void**)&Ktb, g_Ktxt);
    cudaGetSymbolAddress((void**)&Vtb, g_Vtxt);
    cudaGetSymbolAddress((void**)&Kib, g_Kimg);
    cudaGetSymbolAddress((void**)&Vib, g_Vimg);
    cudaGetSymbolAddress((void**)&Ab,  g_attn);

    __nv_bfloat16 *xh, *xl, *ah, *al, *cth, *ctl, *cih, *cil;
    __nv_bfloat16 *wqh, *wql, *wkh, *wkl, *wvh, *wvl, *wkih, *wkil, *wvih, *wvil, *woh, *wol;
    cudaGetSymbolAddress((void**)&xh,  g_xh);   cudaGetSymbolAddress((void**)&xl,  g_xl);
    cudaGetSymbolAddress((void**)&ah,  g_ah);   cudaGetSymbolAddress((void**)&al,  g_al);
    cudaGetSymbolAddress((void**)&cth, g_cth);  cudaGetSymbolAddress((void**)&ctl, g_ctl);
    cudaGetSymbolAddress((void**)&cih, g_cih);  cudaGetSymbolAddress((void**)&cil, g_cil);
    cudaGetSymbolAddress((void**)&wqh, g_wqh);  cudaGetSymbolAddress((void**)&wql, g_wql);
    cudaGetSymbolAddress((void**)&wkh, g_wkh);  cudaGetSymbolAddress((void**)&wkl, g_wkl);
    cudaGetSymbolAddress((void**)&wvh, g_wvh);  cudaGetSymbolAddress((void**)&wvl, g_wvl);
    cudaGetSymbolAddress((void**)&wkih, g_wkih); cudaGetSymbolAddress((void**)&wkil, g_wkil);
    cudaGetSymbolAddress((void**)&wvih, g_wvih); cudaGetSymbolAddress((void**)&wvil, g_wvil);
    cudaGetSymbolAddress((void**)&woh, g_woh);  cudaGetSymbolAddress((void**)&wol, g_wol);

    cudaFuncSetAttribute(gemm_tc, cudaFuncAttributeMaxDynamicSharedMemorySize, GEMM_SMEM);
    const int attn_smem = SMEM_FLOATS * (int)sizeof(float);
    cudaFuncSetAttribute(attn_kernel, cudaFuncAttributeMaxDynamicSharedMemorySize, attn_smem);

#define CVT_GRID(Mpad) ((Mpad) * (DIMN / 4) / 256)

    // conversions (hi/lo bf16 split)
    cvt_split<<<CVT_GRID(BATCH * LQ), 256>>>(x, xh, xl, BATCH * LQ, BATCH * LQ, 0, 0);
    cvt_split<<<CVT_GRID(DIMN), 256>>>(w_q, wqh, wql, DIMN, DIMN, 0, 0);
    cvt_split<<<CVT_GRID(DIMN), 256>>>(w_k, wkh, wkl, DIMN, DIMN, 0, 0);
    cvt_split<<<CVT_GRID(DIMN), 256>>>(w_v, wvh, wvl, DIMN, DIMN, 0, 0);
    cvt_split<<<CVT_GRID(DIMN), 256>>>(w_k_img, wkih, wkil, DIMN, DIMN, 0, 0);
    cvt_split<<<CVT_GRID(DIMN), 256>>>(w_v_img, wvih, wvil, DIMN, DIMN, 0, 0);
    cvt_split<<<CVT_GRID(DIMN), 256>>>(w_o, woh, wol, DIMN, DIMN, 0, 0);
    cvt_split<<<CVT_GRID(BATCH * TXT_T), 256>>>(context, cth, ctl,
                                                BATCH * TXT_T, TXT_T, LCTX, IMG_T);
    cvt_split<<<CVT_GRID(MPAD_IMG), 256>>>(context, cih, cil,
                                           BATCH * IMG_T, IMG_T, LCTX, 0);

    // Q = rmsnorm(x @ w_q^T + b_q)
    gemm_tc<<<dim3(16, 64), 256, GEMM_SMEM>>>(xh, xl, wqh, wql, b_q, Qb, BATCH * LQ);
    rmsnorm_kernel<<<BATCH * LQ, 256>>>(Qb, g_q);

    // K_txt / V_txt
    gemm_tc<<<dim3(16, 8), 256, GEMM_SMEM>>>(cth, ctl, wkh, wkl, b_k, Ktb, BATCH * TXT_T);
    rmsnorm_kernel<<<BATCH * TXT_T, 256>>>(Ktb, g_k);
    gemm_tc<<<dim3(16, 8), 256, GEMM_SMEM>>>(cth, ctl, wvh, wvl, b_v, Vtb, BATCH * TXT_T);

    // K_img / V_img (M=514, padded to 640)
    gemm_tc<<<dim3(16, 5), 256, GEMM_SMEM>>>(cih, cil, wkih, wkil, b_k_img, Kib, BATCH * IMG_T);
    rmsnorm_kernel<<<BATCH * IMG_T, 256>>>(Kib, g_k_img);
    gemm_tc<<<dim3(16, 5), 256, GEMM_SMEM>>>(cih, cil, wvih, wvil, b_v_img, Vib, BATCH * IMG_T);

    // attention (img + txt) -> g_attn
    attn_kernel<<<dim3(LQ / 64, NHEADS, BATCH), 256, attn_smem>>>(lens);

    // out = attn @ w_o^T + b_o
    cvt_split<<<CVT_GRID(BATCH * LQ), 256>>>(Ab, ah, al, BATCH * LQ, BATCH * LQ, 0, 0);
    gemm_tc<<<dim3(16, 64), 256, GEMM_SMEM>>>(ah, al, woh, wol, b_o, out, BATCH * LQ);
}

// round 4
// speedup vs baseline: 1.8371x; 1.0001x over previous
#include <cuda_runtime.h>
#include <cuda_bf16.h>
#include <math.h>
#include <stdint.h>

#define DIMN 2048
#define NHEADS 16
#define HDIM 128
#define BATCH 2
#define LQ 4096
#define LCTX 769
#define IMG_T 257
#define TXT_T 512
#define EPS_F 1e-6f
#define ATT_SCALE 0.08838834764831845f  /* 1/sqrt(128) */

// ---------------- scratch (device globals; no allocs allowed) --------------
__device__ float g_Q   [BATCH * LQ    * DIMN];
__device__ float g_Ktxt[BATCH * TXT_T * DIMN];
__device__ float g_Vtxt[BATCH * TXT_T * DIMN];
__device__ float g_Kimg[BATCH * IMG_T * DIMN];
__device__ float g_Vimg[BATCH * IMG_T * DIMN];
__device__ float g_attn[BATCH * LQ    * DIMN];

// bf16 hi/lo split buffers
#define MPAD_IMG 640
__device__ __nv_bfloat16 g_xh [BATCH * LQ * DIMN];
__device__ __nv_bfloat16 g_xl [BATCH * LQ * DIMN];
__device__ __nv_bfloat16 g_ah [BATCH * LQ * DIMN];
__device__ __nv_bfloat16 g_al [BATCH * LQ * DIMN];
__device__ __nv_bfloat16 g_cth[BATCH * TXT_T * DIMN];
__device__ __nv_bfloat16 g_ctl[BATCH * TXT_T * DIMN];
__device__ __nv_bfloat16 g_cih[MPAD_IMG * DIMN];
__device__ __nv_bfloat16 g_cil[MPAD_IMG * DIMN];
__device__ __nv_bfloat16 g_wqh [DIMN * DIMN], g_wql [DIMN * DIMN];
__device__ __nv_bfloat16 g_wkh [DIMN * DIMN], g_wkl [DIMN * DIMN];
__device__ __nv_bfloat16 g_wvh [DIMN * DIMN], g_wvl [DIMN * DIMN];
__device__ __nv_bfloat16 g_wkih[DIMN * DIMN], g_wkil[DIMN * DIMN];
__device__ __nv_bfloat16 g_wvih[DIMN * DIMN], g_wvil[DIMN * DIMN];
__device__ __nv_bfloat16 g_woh [DIMN * DIMN], g_wol [DIMN * DIMN];

// ---------------------------- helpers ---------------------------------------
__device__ __forceinline__ uint32_t smem_u32(const void* p) {
    uint32_t a;
    asm("{ .reg .u64 t; cvta.to.shared.u64 t, %1; cvt.u32.u64 %0, t; }"
        : "=r"(a) : "l"(p));
    return a;
}

__device__ __forceinline__ void mma16816(float* d, const uint32_t* a,
                                         const uint32_t b0, const uint32_t b1) {
    asm volatile(
        "mma.sync.aligned.m16n8k16.row.col.f32.bf16.bf16.f32 "
        "{%0,%1,%2,%3}, {%4,%5,%6,%7}, {%8,%9}, {%0,%1,%2,%3};"
        : "+f"(d[0]), "+f"(d[1]), "+f"(d[2]), "+f"(d[3])
        : "r"(a[0]), "r"(a[1]), "r"(a[2]), "r"(a[3]), "r"(b0), "r"(b1));
}

// -------------- fp32 -> bf16 hi/lo split (with row remap + pad) ------------
__global__ __launch_bounds__(256)
void cvt_split(const float* __restrict__ src,
               __nv_bfloat16* __restrict__ hi, __nv_bfloat16* __restrict__ lo,
               int Mvalid, int rows_pb, int bstride, int roff)
{
    const long i4 = (long)blockIdx.x * 256 + threadIdx.x;
    const long e  = i4 * 4;
    const int  m  = (int)(e >> 11);
    const int  col = (int)(e & 2047);

    float4 v = make_float4(0.f, 0.f, 0.f, 0.f);
    if (m < Mvalid) {
        const int bb = m / rows_pb;
        const long srow = (long)bb * bstride + roff + (m - bb * rows_pb);
        v = *(const float4*)(src + srow * DIMN + col);
    }
    __nv_bfloat16 h0 = __float2bfloat16(v.x);
    __nv_bfloat16 h1 = __float2bfloat16(v.y);
    __nv_bfloat16 h2 = __float2bfloat16(v.z);
    __nv_bfloat16 h3 = __float2bfloat16(v.w);
    __nv_bfloat16 l0 = __float2bfloat16(v.x - __bfloat162float(h0));
    __nv_bfloat16 l1 = __float2bfloat16(v.y - __bfloat162float(h1));
    __nv_bfloat16 l2 = __float2bfloat16(v.z - __bfloat162float(h2));
    __nv_bfloat16 l3 = __float2bfloat16(v.w - __bfloat162float(h3));
    ushort4 H = make_ushort4(__bfloat16_as_ushort(h0), __bfloat16_as_ushort(h1),
                             __bfloat16_as_ushort(h2), __bfloat16_as_ushort(h3));
    ushort4 L = make_ushort4(__bfloat16_as_ushort(l0), __bfloat16_as_ushort(l1),
                             __bfloat16_as_ushort(l2), __bfloat16_as_ushort(l3));
    *(ushort4*)(hi + e) = H;
    *(ushort4*)(lo + e) = L;
}

// ------------- HMMA GEMM: C = (Ah+Al)(Bh+Bl)^T + bias (3 terms) ------------
// Block 128x128, 8 warps (4x2), warp tile 32x64, K-chunk 32, double-buffered.
#define GT_KC 32
#define NCHUNK (DIMN / GT_KC)      /* 64 */
#define LDAB 40                    /* smem row stride in bf16 (80 B) */
#define TILE_ELE (128 * LDAB)      /* bf16 elems per tile */
#define BUF_ELE  (4 * TILE_ELE)
#define GEMM_SMEM (2 * BUF_ELE * 2)  /* bytes */

__global__ __launch_bounds__(256, 2)
void gemm_tc(const __nv_bfloat16* __restrict__ Ah, const __nv_bfloat16* __restrict__ Al,
             const __nv_bfloat16* __restrict__ Bh, const __nv_bfloat16* __restrict__ Bl,
             const float* __restrict__ bias, float* __restrict__ C, int Mvalid)
{
    extern __shared__ __nv_bfloat16 sm[];

    const int tid = threadIdx.x;
    const int wid = tid >> 5;
    const int lane = tid & 31;
    const int m0 = blockIdx.y * 128;
    const int n0 = blockIdx.x * 128;

    const int wm = wid & 3;        // 0..3  (32 rows each)
    const int wn = wid >> 2;       // 0..1  (64 cols each)
    const int lr = lane >> 2;      // 0..7
    const int lc = (lane & 3) * 2; // 0,2,4,6

    const __nv_bfloat16* srcs[4] = {
        Ah + (size_t)m0 * DIMN, Al + (size_t)m0 * DIMN,
        Bh + (size_t)n0 * DIMN, Bl + (size_t)n0 * DIMN };

    const uint32_t smb = smem_u32(sm);

    auto load_chunk = [&](int c, int b) {
        const int k0 = c * GT_KC;
#pragma unroll
        for (int j = 0; j < 8; j++) {
            const int f = j * 256 + tid;          // 0..2047
            const int tile = f >> 9;              // 0..3
            const int w = f & 511;
            const int r = w >> 2;                 // 0..127
            const int cc = w & 3;                 // 16B chunk
            const __nv_bfloat16* sp = srcs[tile] + (size_t)r * DIMN + k0 + cc * 8;
            const uint32_t dp = smb + ((b * BUF_ELE + tile * TILE_ELE + r * LDAB + cc * 8) << 1);
            asm volatile("cp.async.cg.shared.global [%0], [%1], 16;"
                         :: "r"(dp), "l"(sp) : "memory");
        }
        asm volatile("cp.async.commit_group;" ::: "memory");
    };

    float acc[2][8][4];
#pragma unroll
    for (int i = 0; i < 2; i++)
#pragma unroll
        for (int j = 0; j < 8; j++)
#pragma unroll
            for (int q = 0; q < 4; q++) acc[i][j][q] = 0.f;

    load_chunk(0, 0);
    load_chunk(1, 1);

    for (int c = 0; c < NCHUNK; c++) {
        const int b = c & 1;
        if (c == NCHUNK - 1) asm volatile("cp.async.wait_group 0;" ::: "memory");
        else                 asm volatile("cp.async.wait_group 1;" ::: "memory");
        __syncthreads();

        const __nv_bfloat16* Ahs = sm + b * BUF_ELE;
        const __nv_bfloat16* Als = Ahs + TILE_ELE;
        const __nv_bfloat16* Bhs = Als + TILE_ELE;
        const __nv_bfloat16* Bls = Bhs + TILE_ELE;

#pragma unroll
        for (int s = 0; s < 2; s++) {
            const int ks = s * 16;
            uint32_t ah[2][4], al[2][4];
#pragma unroll
            for (int mt = 0; mt < 2; mt++) {
                const int rb = wm * 32 + mt * 16 + lr;
                ah[mt][0] = *(const uint32_t*)&Ahs[(rb)     * LDAB + ks + lc];
                ah[mt][1] = *(const uint32_t*)&Ahs[(rb + 8) * LDAB + ks + lc];
                ah[mt][2] = *(const uint32_t*)&Ahs[(rb)     * LDAB + ks + lc + 8];
                ah[mt][3] = *(const uint32_t*)&Ahs[(rb + 8) * LDAB + ks + lc + 8];
                al[mt][0] = *(const uint32_t*)&Als[(rb)     * LDAB + ks + lc];
                al[mt][1] = *(const uint32_t*)&Als[(rb + 8) * LDAB + ks + lc];
                al[mt][2] = *(const uint32_t*)&Als[(rb)     * LDAB + ks + lc + 8];
                al[mt][3] = *(const uint32_t*)&Als[(rb + 8) * LDAB + ks + lc + 8];
            }
#pragma unroll
            for (int nt = 0; nt < 8; nt++) {
                const int nb = wn * 64 + nt * 8 + lr;
                const uint32_t bh0 = *(const uint32_t*)&Bhs[nb * LDAB + ks + lc];
                const uint32_t bh1 = *(const uint32_t*)&Bhs[nb * LDAB + ks + lc + 8];
                const uint32_t bl0 = *(const uint32_t*)&Bls[nb * LDAB + ks + lc];
                const uint32_t bl1 = *(const uint32_t*)&Bls[nb * LDAB + ks + lc + 8];
#pragma unroll
                for (int mt = 0; mt < 2; mt++) {
                    mma16816(acc[mt][nt], ah[mt], bh0, bh1);
                    mma16816(acc[mt][nt], ah[mt], bl0, bl1);
                    mma16816(acc[mt][nt], al[mt], bh0, bh1);
                }
            }
        }
        __syncthreads();
        if (c + 2 < NCHUNK) load_chunk(c + 2, b);
    }

    // epilogue: d{0,1} -> (m = base+lr, n = nt*8+lc,+1); d{2,3} -> m+8
#pragma unroll
    for (int mt = 0; mt < 2; mt++) {
#pragma unroll
        for (int nt = 0; nt < 8; nt++) {
            const int n = n0 + wn * 64 + nt * 8 + lc;
            const float2 bv = *(const float2*)&bias[n];
            const int mA = m0 + wm * 32 + mt * 16 + lr;
            if (mA < Mvalid) {
                float2 o = make_float2(acc[mt][nt][0] + bv.x, acc[mt][nt][1] + bv.y);
                *(float2*)(C + (size_t)mA * DIMN + n) = o;
            }
            if (mA + 8 < Mvalid) {
                float2 o = make_float2(acc[mt][nt][2] + bv.x, acc[mt][nt][3] + bv.y);
                *(float2*)(C + (size_t)(mA + 8) * DIMN + n) = o;
            }
        }
    }
}

// ---------------- RMS norm over last dim (2048), in place ------------------
__global__ __launch_bounds__(256)
void rmsnorm_kernel(float* __restrict__ X, const float* __restrict__ g)
{
    const int row = blockIdx.x;
    float* xr = X + (long)row * DIMN;
    const int t = threadIdx.x;

    float4 v0 = *(float4*)&xr[t * 4];
    float4 v1 = *(float4*)&xr[1024 + t * 4];
    float ss = v0.x * v0.x + v0.y * v0.y + v0.z * v0.z + v0.w * v0.w
             + v1.x * v1.x + v1.y * v1.y + v1.z * v1.z + v1.w * v1.w;

#pragma unroll
    for (int o = 16; o > 0; o >>= 1) ss += __shfl_xor_sync(0xffffffffu, ss, o);

    __shared__ float red[8];
    if ((t & 31) == 0) red[t >> 5] = ss;
    __syncthreads();
    float total = 0.f;
#pragma unroll
    for (int i = 0; i < 8; i++) total += red[i];

    const float scale = rsqrtf(total * (1.0f / DIMN) + EPS_F);

    const float4 g0 = *(const float4*)&g[t * 4];
    const float4 g1 = *(const float4*)&g[1024 + t * 4];
    v0.x *= scale * g0.x; v0.y *= scale * g0.y; v0.z *= scale * g0.z; v0.w *= scale * g0.w;
    v1.x *= scale * g1.x; v1.y *= scale * g1.y; v1.z *= scale * g1.z; v1.w *= scale * g1.w;
    *(float4*)&xr[t * 4]        = v0;
    *(float4*)&xr[1024 + t * 4] = v1;
}

// ---------------- dual attention (img + txt), exact softmax ----------------
#define LDQ 132
#define LDK 132
#define LDS 516
#define SMEM_FLOATS (64 * LDQ + 64 * LDK + 64 * LDS)

#define DOT4(A, Bv) ((A).x * (Bv).x + (A).y * (Bv).y + (A).z * (Bv).z + (A).w * (Bv).w)

__global__ __launch_bounds__(256, 1)
void attn_kernel(const int* __restrict__ lens)
{
    extern __shared__ float smem[];
    float* Qs = smem;                 // [64][LDQ]
    float* Ks = Qs + 64 * LDQ;        // [64][LDK]  (also reused for V chunks)
    float* Ss = Ks + 64 * LDK;        // [64][LDS]

    const int qt = blockIdx.x, h = blockIdx.y, b = blockIdx.z;
    const int tid = threadIdx.x;
    const int q0 = qt * 64;

    for (int f = tid; f < 64 * 32; f += 256) {
        const int r = f >> 5, d4 = f & 31;
        const float4 v = *(const float4*)&g_Q[((long)(b * LQ + q0 + r)) * DIMN + h * HDIM + d4 * 4];
        *(float4*)&Qs[r * LDQ + d4 * 4] = v;
    }

    float o[4][8];
#pragma unroll
    for (int a = 0; a < 4; a++)
#pragma unroll
        for (int j = 0; j < 8; j++) o[a][j] = 0.f;

    const int ty = tid >> 4;  // 0..15
    const int tx = tid & 15;  // 0..15

    for (int ph = 0; ph < 2; ph++) {
        const float* Kp; const float* Vp; int Lk, valid;
        if (ph == 0) {
            Kp = g_Kimg + (long)b * IMG_T * DIMN;
            Vp = g_Vimg + (long)b * IMG_T * DIMN;
            Lk = IMG_T; valid = IMG_T;
        } else {
            Kp = g_Ktxt + (long)b * TXT_T * DIMN;
            Vp = g_Vtxt + (long)b * TXT_T * DIMN;
            Lk = TXT_T;
            valid = lens[b];
            if (valid > TXT_T) valid = TXT_T;
        }
        const int nch = (Lk + 63) >> 6;
        const int padded = nch * 64;

        // ---- scores ----
        for (int c = 0; c < nch; c++) {
            __syncthreads();
            for (int f = tid; f < 64 * 32; f += 256) {
                const int r = f >> 5, d4 = f & 31;
                const int kr = c * 64 + r;
                float4 v = make_float4(0.f, 0.f, 0.f, 0.f);
                if (kr < Lk)
                    v = *(const float4*)&Kp[(long)kr * DIMN + h * HDIM + d4 * 4];
                *(float4*)&Ks[r * LDK + d4 * 4] = v;
            }
            __syncthreads();

            float s[4][4];
#pragma unroll
            for (int a = 0; a < 4; a++)
#pragma unroll
                for (int cc = 0; cc < 4; cc++) s[a][cc] = 0.f;

#pragma unroll
            for (int d4 = 0; d4 < 32; d4++) {
                float4 qv[4], kv[4];
#pragma unroll
                for (int a = 0; a < 4; a++)
                    qv[a] = *(const float4*)&Qs[(ty + a * 16) * LDQ + d4 * 4];
#pragma unroll
                for (int cc = 0; cc < 4; cc++)
                    kv[cc] = *(const float4*)&Ks[(tx + cc * 16) * LDK + d4 * 4];
#pragma unroll
                for (int a = 0; a < 4; a++)
#pragma unroll
                    for (int cc = 0; cc < 4; cc++)
                        s[a][cc] += DOT4(qv[a], kv[cc]);
            }
#pragma unroll
            for (int a = 0; a < 4; a++)
#pragma unroll
                for (int cc = 0; cc < 4; cc++)
                    Ss[(ty + a * 16) * LDS + c * 64 + tx + cc * 16] = s[a][cc];
        }
        __syncthreads();

        // ---- softmax ----
        {
            const int row = tid >> 2;
            const int lane = tid & 3;
            float* Sr = Ss + row * LDS;
            float mx = -1e30f;
            for (int j = lane; j < valid; j += 4) mx = fmaxf(mx, Sr[j]);
            mx = fmaxf(mx, __shfl_xor_sync(0xffffffffu, mx, 1));
            mx = fmaxf(mx, __shfl_xor_sync(0xffffffffu, mx, 2));
            mx *= ATT_SCALE;
            float sum = 0.f;
            for (int j = lane; j < padded; j += 4) {
                float e = 0.f;
                if (j < valid) e = __expf(Sr[j] * ATT_SCALE - mx);
                Sr[j] = e;
                sum += e;
            }
            sum += __shfl_xor_sync(0xffffffffu, sum, 1);
            sum += __shfl_xor_sync(0xffffffffu, sum, 2);
            const float inv = 1.0f / sum;
            for (int j = lane; j < padded; j += 4) Sr[j] *= inv;
        }
        __syncthreads();

        // ---- P @ V ----
        for (int c = 0; c < nch; c++) {
            for (int f = tid; f < 64 * 32; f += 256) {
                const int r = f >> 5, d4 = f & 31;
                const int kr = c * 64 + r;
                float4 v = make_float4(0.f, 0.f, 0.f, 0.f);
                if (kr < Lk)
                    v = *(const float4*)&Vp[(long)kr * DIMN + h * HDIM + d4 * 4];
                *(float4*)&Ks[r * LDK + d4 * 4] = v;
            }
            __syncthreads();

            const int cb = c * 64;
#pragma unroll 8
            for (int kj = 0; kj < 64; kj++) {
                const float p0 = Ss[(ty)      * LDS + cb + kj];
                const float p1 = Ss[(ty + 16) * LDS + cb + kj];
                const float p2 = Ss[(ty + 32) * LDS + cb + kj];
                const float p3 = Ss[(ty + 48) * LDS + cb + kj];
                const float4 v0 = *(const float4*)&Ks[kj * LDK + tx * 8];
                const float4 v1 = *(const float4*)&Ks[kj * LDK + tx * 8 + 4];
#define PV_ACC(a, p)                                                      \
                o[a][0] += (p) * v0.x; o[a][1] += (p) * v0.y;             \
                o[a][2] += (p) * v0.z; o[a][3] += (p) * v0.w;             \
                o[a][4] += (p) * v1.x; o[a][5] += (p) * v1.y;             \
                o[a][6] += (p) * v1.z; o[a][7] += (p) * v1.w;
                PV_ACC(0, p0) PV_ACC(1, p1) PV_ACC(2, p2) PV_ACC(3, p3)
#undef PV_ACC
            }
            __syncthreads();
        }
    }

#pragma unroll
    for (int a = 0; a < 4; a++) {
        const long row = (long)(b * LQ + q0 + ty + a * 16);
        float4 w0 = make_float4(o[a][0], o[a][1], o[a][2], o[a][3]);
        float4 w1 = make_float4(o[a][4], o[a][5], o[a][6], o[a][7]);
        *(float4*)&g_attn[row * DIMN + h * HDIM + tx * 8]     = w0;
        *(float4*)&g_attn[row * DIMN + h * HDIM + tx * 8 + 4] = w1;
    }
}

// ---------------------------- launch ---------------------------------------
extern "C" void kernel_launch(void* const* d_in, const int* in_sizes, int n_in,
                              void* d_out, int out_size)
{
    const float* x        = (const float*)d_in[0];
    const float* context  = (const float*)d_in[1];
    const int*   lens     = (const int*)  d_in[2];
    const float* w_q      = (const float*)d_in[3];
    const float* b_q      = (const float*)d_in[4];
    const float* w_k      = (const float*)d_in[5];
    const float* b_k      = (const float*)d_in[6];
    const float* w_v      = (const float*)d_in[7];
    const float* b_v      = (const float*)d_in[8];
    const float* w_k_img  = (const float*)d_in[9];
    const float* b_k_img  = (const float*)d_in[10];
    const float* w_v_img  = (const float*)d_in[11];
    const float* b_v_img  = (const float*)d_in[12];
    const float* w_o      = (const float*)d_in[13];
    const float* b_o      = (const float*)d_in[14];
    const float* g_q      = (const float*)d_in[15];
    const float* g_k      = (const float*)d_in[16];
    const float* g_k_img  = (const float*)d_in[17];
    float* out = (float*)d_out;

    float *Qb, *Ktb, *Vtb, *Kib, *Vib, *Ab;
    cudaGetSymbolAddress((void**)&Qb,  g_Q);
    cudaGetSymbolAddress((void**)&Ktb, g_Ktxt);
    cudaGetSymbolAddress((void**)&Vtb, g_Vtxt);
    cudaGetSymbolAddress((void**)&Kib, g_Kimg);
    cudaGetSymbolAddress((void**)&Vib, g_Vimg);
    cudaGetSymbolAddress((void**)&Ab,  g_attn);

    __nv_bfloat16 *xh, *xl, *ah, *al, *cth, *ctl, *cih, *cil;
    __nv_bfloat16 *wqh, *wql, *wkh, *wkl, *wvh, *wvl, *wkih, *wkil, *wvih, *wvil, *woh, *wol;
    cudaGetSymbolAddress((void**)&xh,  g_xh);   cudaGetSymbolAddress((void**)&xl,  g_xl);
    cudaGetSymbolAddress((void**)&ah,  g_ah);   cudaGetSymbolAddress((void**)&al,  g_al);
    cudaGetSymbolAddress((void**)&cth, g_cth);  cudaGetSymbolAddress((void**)&ctl, g_ctl);
    cudaGetSymbolAddress((void**)&cih, g_cih);  cudaGetSymbolAddress((void**)&cil, g_cil);
    cudaGetSymbolAddress((void**)&wqh, g_wqh);  cudaGetSymbolAddress((void**)&wql, g_wql);
    cudaGetSymbolAddress((void**)&wkh, g_wkh);  cudaGetSymbolAddress((void**)&wkl, g_wkl);
    cudaGetSymbolAddress((void**)&wvh, g_wvh);  cudaGetSymbolAddress((void**)&wvl, g_wvl);
    cudaGetSymbolAddress((void**)&wkih, g_wkih); cudaGetSymbolAddress((void**)&wkil, g_wkil);
    cudaGetSymbolAddress((void**)&wvih, g_wvih); cudaGetSymbolAddress((void**)&wvil, g_wvil);
    cudaGetSymbolAddress((void**)&woh, g_woh);  cudaGetSymbolAddress((void**)&wol, g_wol);

    cudaFuncSetAttribute(gemm_tc, cudaFuncAttributeMaxDynamicSharedMemorySize, GEMM_SMEM);
    const int attn_smem = SMEM_FLOATS * (int)sizeof(float);
    cudaFuncSetAttribute(attn_kernel, cudaFuncAttributeMaxDynamicSharedMemorySize, attn_smem);

#define CVT_GRID(Mpad) ((Mpad) * (DIMN / 4) / 256)

    // conversions (hi/lo bf16 split)
    cvt_split<<<CVT_GRID(BATCH * LQ), 256>>>(x, xh, xl, BATCH * LQ, BATCH * LQ, 0, 0);
    cvt_split<<<CVT_GRID(DIMN), 256>>>(w_q, wqh, wql, DIMN, DIMN, 0, 0);
    cvt_split<<<CVT_GRID(DIMN), 256>>>(w_k, wkh, wkl, DIMN, DIMN, 0, 0);
    cvt_split<<<CVT_GRID(DIMN), 256>>>(w_v, wvh, wvl, DIMN, DIMN, 0, 0);
    cvt_split<<<CVT_GRID(DIMN), 256>>>(w_k_img, wkih, wkil, DIMN, DIMN, 0, 0);
    cvt_split<<<CVT_GRID(DIMN), 256>>>(w_v_img, wvih, wvil, DIMN, DIMN, 0, 0);
    cvt_split<<<CVT_GRID(DIMN), 256>>>(w_o, woh, wol, DIMN, DIMN, 0, 0);
    cvt_split<<<CVT_GRID(BATCH * TXT_T), 256>>>(context, cth, ctl,
                                                BATCH * TXT_T, TXT_T, LCTX, IMG_T);
    cvt_split<<<CVT_GRID(MPAD_IMG), 256>>>(context, cih, cil,
                                           BATCH * IMG_T, IMG_T, LCTX, 0);

    // Q = rmsnorm(x @ w_q^T + b_q)
    gemm_tc<<<dim3(16, 64), 256, GEMM_SMEM>>>(xh, xl, wqh, wql, b_q, Qb, BATCH * LQ);
    rmsnorm_kernel<<<BATCH * LQ, 256>>>(Qb, g_q);

    // K_txt / V_txt
    gemm_tc<<<dim3(16, 8), 256, GEMM_SMEM>>>(cth, ctl, wkh, wkl, b_k, Ktb, BATCH * TXT_T);
    rmsnorm_kernel<<<BATCH * TXT_T, 256>>>(Ktb, g_k);
    gemm_tc<<<dim3(16, 8), 256, GEMM_SMEM>>>(cth, ctl, wvh, wvl, b_v, Vtb, BATCH * TXT_T);

    // K_img / V_img (M=514, padded to 640)
    gemm_tc<<<dim3(16, 5), 256, GEMM_SMEM>>>(cih, cil, wkih, wkil, b_k_img, Kib, BATCH * IMG_T);
    rmsnorm_kernel<<<BATCH * IMG_T, 256>>>(Kib, g_k_img);
    gemm_tc<<<dim3(16, 5), 256, GEMM_SMEM>>>(cih, cil, wvih, wvil, b_v_img, Vib, BATCH * IMG_T);

    // attention (img + txt) -> g_attn
    attn_kernel<<<dim3(LQ / 64, NHEADS, BATCH), 256, attn_smem>>>(lens);

    // out = attn @ w_o^T + b_o
    cvt_split<<<CVT_GRID(BATCH * LQ), 256>>>(Ab, ah, al, BATCH * LQ, BATCH * LQ, 0, 0);
    gemm_tc<<<dim3(16, 64), 256, GEMM_SMEM>>>(ah, al, woh, wol, b_o, out, BATCH * LQ);
}

// round 5
// speedup vs baseline: 2.8629x; 1.5584x over previous
#include <cuda_runtime.h>
#include <cuda_bf16.h>
#include <math.h>
#include <stdint.h>

#define DIMN 2048
#define NHEADS 16
#define HDIM 128
#define BATCH 2
#define LQ 4096
#define LCTX 769
#define IMG_T 257
#define TXT_T 512
#define EPS_F 1e-6f
#define ATT_SCALE 0.08838834764831845f  /* 1/sqrt(128) */

// ---------------- scratch (device globals; no allocs allowed) --------------
__device__ float g_Q   [BATCH * LQ    * DIMN];
__device__ float g_Ktxt[BATCH * TXT_T * DIMN];
__device__ float g_Vtxt[BATCH * TXT_T * DIMN];
__device__ float g_Kimg[BATCH * IMG_T * DIMN];
__device__ float g_Vimg[BATCH * IMG_T * DIMN];

// bf16 hi/lo split buffers
#define MPAD_IMG 640
__device__ __nv_bfloat16 g_xh [BATCH * LQ * DIMN];
__device__ __nv_bfloat16 g_xl [BATCH * LQ * DIMN];
__device__ __nv_bfloat16 g_ah [BATCH * LQ * DIMN];
__device__ __nv_bfloat16 g_al [BATCH * LQ * DIMN];
__device__ __nv_bfloat16 g_cth[BATCH * TXT_T * DIMN];
__device__ __nv_bfloat16 g_ctl[BATCH * TXT_T * DIMN];
__device__ __nv_bfloat16 g_cih[MPAD_IMG * DIMN];
__device__ __nv_bfloat16 g_cil[MPAD_IMG * DIMN];
__device__ __nv_bfloat16 g_wqh [DIMN * DIMN], g_wql [DIMN * DIMN];
__device__ __nv_bfloat16 g_wkh [DIMN * DIMN], g_wkl [DIMN * DIMN];
__device__ __nv_bfloat16 g_wvh [DIMN * DIMN], g_wvl [DIMN * DIMN];
__device__ __nv_bfloat16 g_wkih[DIMN * DIMN], g_wkil[DIMN * DIMN];
__device__ __nv_bfloat16 g_wvih[DIMN * DIMN], g_wvil[DIMN * DIMN];
__device__ __nv_bfloat16 g_woh [DIMN * DIMN], g_wol [DIMN * DIMN];

// attention-side hi/lo operands
__device__ __nv_bfloat16 g_Qh [BATCH * LQ * DIMN],    g_Ql [BATCH * LQ * DIMN];
__device__ __nv_bfloat16 g_Kth[BATCH * TXT_T * DIMN], g_Ktl[BATCH * TXT_T * DIMN];
__device__ __nv_bfloat16 g_Vth[BATCH * TXT_T * DIMN], g_Vtl[BATCH * TXT_T * DIMN];
__device__ __nv_bfloat16 g_Kih[BATCH * IMG_T * DIMN], g_Kil[BATCH * IMG_T * DIMN];
__device__ __nv_bfloat16 g_Vih[BATCH * IMG_T * DIMN], g_Vil[BATCH * IMG_T * DIMN];

// ---------------------------- helpers ---------------------------------------
__device__ __forceinline__ uint32_t smem_u32(const void* p) {
    uint32_t a;
    asm("{ .reg .u64 t; cvta.to.shared.u64 t, %1; cvt.u32.u64 %0, t; }"
        : "=r"(a) : "l"(p));
    return a;
}

__device__ __forceinline__ void mma16816(float* d, const uint32_t* a,
                                         const uint32_t b0, const uint32_t b1) {
    asm volatile(
        "mma.sync.aligned.m16n8k16.row.col.f32.bf16.bf16.f32 "
        "{%0,%1,%2,%3}, {%4,%5,%6,%7}, {%8,%9}, {%0,%1,%2,%3};"
        : "+f"(d[0]), "+f"(d[1]), "+f"(d[2]), "+f"(d[3])
        : "r"(a[0]), "r"(a[1]), "r"(a[2]), "r"(a[3]), "r"(b0), "r"(b1));
}

__device__ __forceinline__ void ldsm4(uint32_t* r, uint32_t a) {
    asm volatile("ldmatrix.sync.aligned.m8n8.x4.shared.b16 {%0,%1,%2,%3}, [%4];"
                 : "=r"(r[0]), "=r"(r[1]), "=r"(r[2]), "=r"(r[3]) : "r"(a));
}
__device__ __forceinline__ void ldsm4t(uint32_t* r, uint32_t a) {
    asm volatile("ldmatrix.sync.aligned.m8n8.x4.trans.shared.b16 {%0,%1,%2,%3}, [%4];"
                 : "=r"(r[0]), "=r"(r[1]), "=r"(r[2]), "=r"(r[3]) : "r"(a));
}
__device__ __forceinline__ void cp16(uint32_t d, const void* s) {
    asm volatile("cp.async.cg.shared.global [%0], [%1], 16;"
                 :: "r"(d), "l"(s) : "memory");
}
__device__ __forceinline__ void cp16z(uint32_t d, const void* s, int sz) {
    asm volatile("cp.async.cg.shared.global [%0], [%1], 16, %2;"
                 :: "r"(d), "l"(s), "r"(sz) : "memory");
}
#define CP_COMMIT() asm volatile("cp.async.commit_group;" ::: "memory")
#define CP_WAIT(n)  asm volatile("cp.async.wait_group %0;" :: "n"(n) : "memory")

// f32x2 -> bf16x2 hi + lo residual
__device__ __forceinline__ void split2(float2 f, uint32_t& h, uint32_t& l) {
    __nv_bfloat162 hb = __float22bfloat162_rn(f);
    float2 hf = __bfloat1622float2(hb);
    __nv_bfloat162 lb = __float22bfloat162_rn(make_float2(f.x - hf.x, f.y - hf.y));
    h = *(uint32_t*)&hb;
    l = *(uint32_t*)&lb;
}

// -------------- fp32 -> bf16 hi/lo split (with row remap + pad) ------------
__global__ __launch_bounds__(256)
void cvt_split(const float* __restrict__ src,
               __nv_bfloat16* __restrict__ hi, __nv_bfloat16* __restrict__ lo,
               int Mvalid, int rows_pb, int bstride, int roff)
{
    const long i4 = (long)blockIdx.x * 256 + threadIdx.x;
    const long e  = i4 * 4;
    const int  m  = (int)(e >> 11);
    const int  col = (int)(e & 2047);

    float4 v = make_float4(0.f, 0.f, 0.f, 0.f);
    if (m < Mvalid) {
        const int bb = m / rows_pb;
        const long srow = (long)bb * bstride + roff + (m - bb * rows_pb);
        v = *(const float4*)(src + srow * DIMN + col);
    }
    uint32_t h0, l0, h1, l1;
    split2(make_float2(v.x, v.y), h0, l0);
    split2(make_float2(v.z, v.w), h1, l1);
    *(uint2*)(hi + e) = make_uint2(h0, h1);
    *(uint2*)(lo + e) = make_uint2(l0, l1);
}

// ------------- HMMA GEMM: C = (Ah+Al)(Bh+Bl)^T + bias (3 terms) ------------
// Block 128x128, 8 warps (4x2), warp tile 32x64, K-chunk 32, double-buffered.
// smem tiles use 80-byte row stride -> ldmatrix phases conflict-free (5r+c).
#define GT_KC 32
#define NCHUNK (DIMN / GT_KC)        /* 64 */
#define LDAB 40                      /* bf16 elems per row (80 B) */
#define TILE_ELE (128 * LDAB)
#define TILE_B   (TILE_ELE * 2)      /* 10240 bytes */
#define BUF_B    (4 * TILE_B)        /* 40960 bytes */
#define GEMM_SMEM (2 * BUF_B)

__global__ __launch_bounds__(256, 2)
void gemm_tc(const __nv_bfloat16* __restrict__ Ah, const __nv_bfloat16* __restrict__ Al,
             const __nv_bfloat16* __restrict__ Bh, const __nv_bfloat16* __restrict__ Bl,
             const float* __restrict__ bias, float* __restrict__ C, int Mvalid)
{
    extern __shared__ __nv_bfloat16 sm[];

    const int tid = threadIdx.x;
    const int wid = tid >> 5;
    const int lane = tid & 31;
    const int m0 = blockIdx.y * 128;
    const int n0 = blockIdx.x * 128;

    const int wm = wid & 3;        // 0..3  (32 rows each)
    const int wn = wid >> 2;       // 0..1  (64 cols each)

    const __nv_bfloat16* srcs[4] = {
        Ah + (size_t)m0 * DIMN, Al + (size_t)m0 * DIMN,
        Bh + (size_t)n0 * DIMN, Bl + (size_t)n0 * DIMN };

    const uint32_t smb = smem_u32(sm);

    auto load_chunk = [&](int c, int b) {
        const int k0 = c * GT_KC;
#pragma unroll
        for (int j = 0; j < 8; j++) {
            const int f = j * 256 + tid;          // 0..2047
            const int tile = f >> 9;              // 0..3
            const int w = f & 511;
            const int r = w >> 2;                 // 0..127
            const int cc = w & 3;                 // 16B chunk
            const __nv_bfloat16* sp = srcs[tile] + (size_t)r * DIMN + k0 + cc * 8;
            cp16(smb + b * BUF_B + tile * TILE_B + r * 80 + cc * 16, sp);
        }
        CP_COMMIT();
    };

    float acc[2][8][4];
#pragma unroll
    for (int i = 0; i < 2; i++)
#pragma unroll
        for (int j = 0; j < 8; j++)
#pragma unroll
            for (int q = 0; q < 4; q++) acc[i][j][q] = 0.f;

    // per-lane ldmatrix address offsets (within a buffer)
    const uint32_t aOff = (uint32_t)(wm * 32 + (lane & 15)) * 80 + ((lane >> 4) * 16);
    const uint32_t bOff = (uint32_t)(wn * 64 + (lane & 7) + ((lane >> 4) << 3)) * 80
                        + (((lane >> 3) & 1) * 16) + 2 * TILE_B;

    load_chunk(0, 0);
    load_chunk(1, 1);

    for (int c = 0; c < NCHUNK; c++) {
        const int b = c & 1;
        if (c == NCHUNK - 1) CP_WAIT(0);
        else                 CP_WAIT(1);
        __syncthreads();

        const uint32_t buf = smb + b * BUF_B;

#pragma unroll
        for (int s = 0; s < 2; s++) {
            uint32_t ah_[2][4], al_[2][4];
#pragma unroll
            for (int mt = 0; mt < 2; mt++) {
                ldsm4(ah_[mt], buf + aOff + mt * 16 * 80 + s * 32);
                ldsm4(al_[mt], buf + aOff + mt * 16 * 80 + s * 32 + TILE_B);
            }
#pragma unroll
            for (int t = 0; t < 4; t++) {
                uint32_t bh_[4], bl_[4];
                ldsm4(bh_, buf + bOff + t * 16 * 80 + s * 32);
                ldsm4(bl_, buf + bOff + t * 16 * 80 + s * 32 + TILE_B);
#pragma unroll
                for (int mt = 0; mt < 2; mt++) {
                    mma16816(acc[mt][2 * t],     ah_[mt], bh_[0], bh_[1]);
                    mma16816(acc[mt][2 * t],     ah_[mt], bl_[0], bl_[1]);
                    mma16816(acc[mt][2 * t],     al_[mt], bh_[0], bh_[1]);
                    mma16816(acc[mt][2 * t + 1], ah_[mt], bh_[2], bh_[3]);
                    mma16816(acc[mt][2 * t + 1], ah_[mt], bl_[2], bl_[3]);
                    mma16816(acc[mt][2 * t + 1], al_[mt], bh_[2], bh_[3]);
                }
            }
        }
        __syncthreads();
        if (c + 2 < NCHUNK) load_chunk(c + 2, b);
    }

    const int lr = lane >> 2;
    const int lc = (lane & 3) * 2;
#pragma unroll
    for (int mt = 0; mt < 2; mt++) {
#pragma unroll
        for (int nt = 0; nt < 8; nt++) {
            const int n = n0 + wn * 64 + nt * 8 + lc;
            const float2 bv = *(const float2*)&bias[n];
            const int mA = m0 + wm * 32 + mt * 16 + lr;
            if (mA < Mvalid) {
                float2 o = make_float2(acc[mt][nt][0] + bv.x, acc[mt][nt][1] + bv.y);
                *(float2*)(C + (size_t)mA * DIMN + n) = o;
            }
            if (mA + 8 < Mvalid) {
                float2 o = make_float2(acc[mt][nt][2] + bv.x, acc[mt][nt][3] + bv.y);
                *(float2*)(C + (size_t)(mA + 8) * DIMN + n) = o;
            }
        }
    }
}

// ------------- RMS norm -> bf16 hi/lo split (fused) -------------------------
__global__ __launch_bounds__(256)
void rmsnorm_split(const float* __restrict__ X, const float* __restrict__ g,
                   __nv_bfloat16* __restrict__ H, __nv_bfloat16* __restrict__ L)
{
    const int row = blockIdx.x;
    const float* xr = X + (long)row * DIMN;
    const int t = threadIdx.x;

    float4 v0 = *(const float4*)&xr[t * 4];
    float4 v1 = *(const float4*)&xr[1024 + t * 4];
    float ss = v0.x * v0.x + v0.y * v0.y + v0.z * v0.z + v0.w * v0.w
             + v1.x * v1.x + v1.y * v1.y + v1.z * v1.z + v1.w * v1.w;

#pragma unroll
    for (int o = 16; o > 0; o >>= 1) ss += __shfl_xor_sync(0xffffffffu, ss, o);

    __shared__ float red[8];
    if ((t & 31) == 0) red[t >> 5] = ss;
    __syncthreads();
    float total = 0.f;
#pragma unroll
    for (int i = 0; i < 8; i++) total += red[i];

    const float scale = rsqrtf(total * (1.0f / DIMN) + EPS_F);

    const float4 g0 = *(const float4*)&g[t * 4];
    const float4 g1 = *(const float4*)&g[1024 + t * 4];
    v0.x *= scale * g0.x; v0.y *= scale * g0.y; v0.z *= scale * g0.z; v0.w *= scale * g0.w;
    v1.x *= scale * g1.x; v1.y *= scale * g1.y; v1.z *= scale * g1.z; v1.w *= scale * g1.w;

    uint32_t h0, l0, h1, l1;
    split2(make_float2(v0.x, v0.y), h0, l0);
    split2(make_float2(v0.z, v0.w), h1, l1);
    *(uint2*)(H + (long)row * DIMN + t * 4) = make_uint2(h0, h1);
    *(uint2*)(L + (long)row * DIMN + t * 4) = make_uint2(l0, l1);
    split2(make_float2(v1.x, v1.y), h0, l0);
    split2(make_float2(v1.z, v1.w), h1, l1);
    *(uint2*)(H + (long)row * DIMN + 1024 + t * 4) = make_uint2(h0, h1);
    *(uint2*)(L + (long)row * DIMN + 1024 + t * 4) = make_uint2(l0, l1);
}

// ---------------- dual attention (img + txt), HMMA 3-term -------------------
// Block: 64 q-rows x (head, batch). 8 warps: (wq 0..3) x (wk 0..1).
// smem rows: 272B stride (17 x 16B -> ldmatrix conflict-free).
#define ATT_LDS 516
#define ATT_Q_B  17408                     /* 64 * 272 */
#define ATT_SMEM (4 * ATT_Q_B + 64 * ATT_LDS * 4)

__global__ __launch_bounds__(256, 1)
void attn_kernel(const int* __restrict__ lens)
{
    extern __shared__ char smraw[];
    const uint32_t smb = smem_u32(smraw);
    const uint32_t QH = smb;
    const uint32_t QL = smb + ATT_Q_B;
    const uint32_t KH = smb + 2 * ATT_Q_B;
    const uint32_t KL = smb + 3 * ATT_Q_B;
    float* Ss = (float*)(smraw + 4 * ATT_Q_B);

    const int qt = blockIdx.x, h = blockIdx.y, b = blockIdx.z;
    const int tid = threadIdx.x;
    const int wid = tid >> 5;
    const int lane = tid & 31;
    const int q0 = qt * 64;
    const int wq = wid >> 1;   // 0..3 : q rows
    const int wk = wid & 1;    // 0..1 : key cols (QK) / dim half (PV)

    // load Q hi/lo tiles (64 x 128)
    for (int f = tid; f < 1024; f += 256) {
        const int r = f >> 4, c = f & 15;
        const size_t off = ((size_t)(b * LQ + q0 + r)) * DIMN + h * HDIM + c * 8;
        cp16(QH + r * 272 + c * 16, g_Qh + off);
        cp16(QL + r * 272 + c * 16, g_Ql + off);
    }
    CP_COMMIT();

    float o[8][4];
#pragma unroll
    for (int i = 0; i < 8; i++)
#pragma unroll
        for (int j = 0; j < 4; j++) o[i][j] = 0.f;

    // per-lane ldmatrix offsets
    const uint32_t aQ = (uint32_t)(wq * 16 + (lane & 15)) * 272 + ((lane >> 4) * 16);
    const uint32_t bK = (uint32_t)(wk * 32 + (lane & 7) + ((lane >> 4) << 3)) * 272
                      + (((lane >> 3) & 1) * 16);
    const uint32_t vV = (uint32_t)(lane & 15) * 272 + (wk * 128) + ((lane >> 4) * 16);

    for (int ph = 0; ph < 2; ph++) {
        const __nv_bfloat16 *Kh_g, *Kl_g, *Vh_g, *Vl_g;
        int Lk, valid;
        size_t kvb;
        if (ph == 0) {
            Kh_g = g_Kih; Kl_g = g_Kil; Vh_g = g_Vih; Vl_g = g_Vil;
            Lk = IMG_T; valid = IMG_T; kvb = (size_t)b * IMG_T * DIMN;
        } else {
            Kh_g = g_Kth; Kl_g = g_Ktl; Vh_g = g_Vth; Vl_g = g_Vtl;
            Lk = TXT_T; valid = lens[b]; if (valid > TXT_T) valid = TXT_T;
            kvb = (size_t)b * TXT_T * DIMN;
        }
        const int nch = (Lk + 63) >> 6;
        const int padded = nch * 64;

        // ---- scores ----
        for (int c = 0; c < nch; c++) {
            __syncthreads();
            for (int f = tid; f < 1024; f += 256) {
                const int r = f >> 4, cc = f & 15;
                const int kr = c * 64 + r;
                const int sz = (kr < Lk) ? 16 : 0;
                const int krc = kr < Lk ? kr : 0;
                const size_t off = kvb + (size_t)krc * DIMN + h * HDIM + cc * 8;
                cp16z(KH + r * 272 + cc * 16, Kh_g + off, sz);
                cp16z(KL + r * 272 + cc * 16, Kl_g + off, sz);
            }
            CP_COMMIT();
            CP_WAIT(0);
            __syncthreads();

            float s[4][4];
#pragma unroll
            for (int i = 0; i < 4; i++)
#pragma unroll
                for (int j = 0; j < 4; j++) s[i][j] = 0.f;

#pragma unroll
            for (int s8 = 0; s8 < 8; s8++) {
                uint32_t qh_[4], ql_[4];
                ldsm4(qh_, QH + aQ + s8 * 32);
                ldsm4(ql_, QL + aQ + s8 * 32);
#pragma unroll
                for (int t = 0; t < 2; t++) {
                    uint32_t kh_[4], kl_[4];
                    ldsm4(kh_, KH + bK + t * 16 * 272 + s8 * 32);
                    ldsm4(kl_, KL + bK + t * 16 * 272 + s8 * 32);
                    mma16816(s[2 * t],     qh_, kh_[0], kh_[1]);
                    mma16816(s[2 * t],     qh_, kl_[0], kl_[1]);
                    mma16816(s[2 * t],     ql_, kh_[0], kh_[1]);
                    mma16816(s[2 * t + 1], qh_, kh_[2], kh_[3]);
                    mma16816(s[2 * t + 1], qh_, kl_[2], kl_[3]);
                    mma16816(s[2 * t + 1], ql_, kh_[2], kh_[3]);
                }
            }
            const int row = wq * 16 + (lane >> 2);
            const int colb = c * 64 + wk * 32;
#pragma unroll
            for (int nt = 0; nt < 4; nt++) {
                const int col = colb + nt * 8 + 2 * (lane & 3);
                *(float2*)&Ss[row * ATT_LDS + col]       = make_float2(s[nt][0], s[nt][1]);
                *(float2*)&Ss[(row + 8) * ATT_LDS + col] = make_float2(s[nt][2], s[nt][3]);
            }
        }
        __syncthreads();

        // ---- softmax ----
        {
            const int row = tid >> 2;
            const int ln = tid & 3;
            float* Sr = Ss + row * ATT_LDS;
            float mx = -1e30f;
            for (int j = ln; j < valid; j += 4) mx = fmaxf(mx, Sr[j]);
            mx = fmaxf(mx, __shfl_xor_sync(0xffffffffu, mx, 1));
            mx = fmaxf(mx, __shfl_xor_sync(0xffffffffu, mx, 2));
            mx *= ATT_SCALE;
            float sum = 0.f;
            for (int j = ln; j < padded; j += 4) {
                float e = 0.f;
                if (j < valid) e = __expf(Sr[j] * ATT_SCALE - mx);
                Sr[j] = e;
                sum += e;
            }
            sum += __shfl_xor_sync(0xffffffffu, sum, 1);
            sum += __shfl_xor_sync(0xffffffffu, sum, 2);
            const float inv = 1.0f / sum;
            for (int j = ln; j < padded; j += 4) Sr[j] *= inv;
        }
        __syncthreads();

        // ---- P @ V ----
        for (int c = 0; c < nch; c++) {
            for (int f = tid; f < 1024; f += 256) {
                const int r = f >> 4, cc = f & 15;
                const int kr = c * 64 + r;
                const int sz = (kr < Lk) ? 16 : 0;
                const int krc = kr < Lk ? kr : 0;
                const size_t off = kvb + (size_t)krc * DIMN + h * HDIM + cc * 8;
                cp16z(KH + r * 272 + cc * 16, Vh_g + off, sz);
                cp16z(KL + r * 272 + cc * 16, Vl_g + off, sz);
            }
            CP_COMMIT();
            CP_WAIT(0);
            __syncthreads();

#pragma unroll
            for (int kk = 0; kk < 4; kk++) {
                const int prow = wq * 16 + (lane >> 2);
                const int pcol = c * 64 + kk * 16 + 2 * (lane & 3);
                const float2 p0 = *(const float2*)&Ss[prow * ATT_LDS + pcol];
                const float2 p1 = *(const float2*)&Ss[(prow + 8) * ATT_LDS + pcol];
                const float2 p2 = *(const float2*)&Ss[prow * ATT_LDS + pcol + 8];
                const float2 p3 = *(const float2*)&Ss[(prow + 8) * ATT_LDS + pcol + 8];
                uint32_t ph_[4], pl_[4];
                split2(p0, ph_[0], pl_[0]);
                split2(p1, ph_[1], pl_[1]);
                split2(p2, ph_[2], pl_[2]);
                split2(p3, ph_[3], pl_[3]);

                const uint32_t va = vV + kk * 16 * 272;
#pragma unroll
                for (int t = 0; t < 4; t++) {
                    uint32_t vh_[4], vl_[4];
                    ldsm4t(vh_, KH + va + t * 32);
                    ldsm4t(vl_, KL + va + t * 32);
                    mma16816(o[2 * t],     ph_, vh_[0], vh_[1]);
                    mma16816(o[2 * t],     ph_, vl_[0], vl_[1]);
                    mma16816(o[2 * t],     pl_, vh_[0], vh_[1]);
                    mma16816(o[2 * t + 1], ph_, vh_[2], vh_[3]);
                    mma16816(o[2 * t + 1], ph_, vl_[2], vl_[3]);
                    mma16816(o[2 * t + 1], pl_, vh_[2], vh_[3]);
                }
            }
            __syncthreads();
        }
    }

    // ---- epilogue: write hi/lo bf16 directly ----
    const int orow = wq * 16 + (lane >> 2);
    const int ocol = wk * 64 + 2 * (lane & 3);
#pragma unroll
    for (int nt = 0; nt < 8; nt++) {
        const int gcol = h * HDIM + ocol + nt * 8;
        const size_t r0 = (size_t)(b * LQ + q0 + orow) * DIMN + gcol;
        const size_t r1 = (size_t)(b * LQ + q0 + orow + 8) * DIMN + gcol;
        uint32_t hh, ll;
        split2(make_float2(o[nt][0], o[nt][1]), hh, ll);
        *(uint32_t*)&g_ah[r0] = hh;
        *(uint32_t*)&g_al[r0] = ll;
        split2(make_float2(o[nt][2], o[nt][3]), hh, ll);
        *(uint32_t*)&g_ah[r1] = hh;
        *(uint32_t*)&g_al[r1] = ll;
    }
}

// ---------------------------- launch ---------------------------------------
extern "C" void kernel_launch(void* const* d_in, const int* in_sizes, int n_in,
                              void* d_out, int out_size)
{
    const float* x        = (const float*)d_in[0];
    const float* context  = (const float*)d_in[1];
    const int*   lens     = (const int*)  d_in[2];
    const float* w_q      = (const float*)d_in[3];
    const float* b_q      = (const float*)d_in[4];
    const float* w_k      = (const float*)d_in[5];
    const float* b_k      = (const float*)d_in[6];
    const float* w_v      = (const float*)d_in[7];
    const float* b_v      = (const float*)d_in[8];
    const float* w_k_img  = (const float*)d_in[9];
    const float* b_k_img  = (const float*)d_in[10];
    const float* w_v_img  = (const float*)d_in[11];
    const float* b_v_img  = (const float*)d_in[12];
    const float* w_o      = (const float*)d_in[13];
    const float* b_o      = (const float*)d_in[14];
    const float* g_q      = (const float*)d_in[15];
    const float* g_k      = (const float*)d_in[16];
    const float* g_k_img  = (const float*)d_in[17];
    float* out = (float*)d_out;

    float *Qb, *Ktb, *Vtb, *Kib, *Vib;
    cudaGetSymbolAddress((void**)&Qb,  g_Q);
    cudaGetSymbolAddress((void**)&Ktb, g_Ktxt);
    cudaGetSymbolAddress((void**)&Vtb, g_Vtxt);
    cudaGetSymbolAddress((void**)&Kib, g_Kimg);
    cudaGetSymbolAddress((void**)&Vib, g_Vimg);

    __nv_bfloat16 *xh, *xl, *ah, *al, *cth, *ctl, *cih, *cil;
    __nv_bfloat16 *wqh, *wql, *wkh, *wkl, *wvh, *wvl, *wkih, *wkil, *wvih, *wvil, *woh, *wol;
    __nv_bfloat16 *Qhp, *Qlp, *Kthp, *Ktlp, *Vthp, *Vtlp, *Kihp, *Kilp, *Vihp, *Vilp;
    cudaGetSymbolAddress((void**)&xh,  g_xh);   cudaGetSymbolAddress((void**)&xl,  g_xl);
    cudaGetSymbolAddress((void**)&ah,  g_ah);   cudaGetSymbolAddress((void**)&al,  g_al);
    cudaGetSymbolAddress((void**)&cth, g_cth);  cudaGetSymbolAddress((void**)&ctl, g_ctl);
    cudaGetSymbolAddress((void**)&cih, g_cih);  cudaGetSymbolAddress((void**)&cil, g_cil);
    cudaGetSymbolAddress((void**)&wqh, g_wqh);  cudaGetSymbolAddress((void**)&wql, g_wql);
    cudaGetSymbolAddress((void**)&wkh, g_wkh);  cudaGetSymbolAddress((void**)&wkl, g_wkl);
    cudaGetSymbolAddress((void**)&wvh, g_wvh);  cudaGetSymbolAddress((void**)&wvl, g_wvl);
    cudaGetSymbolAddress((void**)&wkih, g_wkih); cudaGetSymbolAddress((void**)&wkil, g_wkil);
    cudaGetSymbolAddress((void**)&wvih, g_wvih); cudaGetSymbolAddress((void**)&wvil, g_wvil);
    cudaGetSymbolAddress((void**)&woh, g_woh);  cudaGetSymbolAddress((void**)&wol, g_wol);
    cudaGetSymbolAddress((void**)&Qhp, g_Qh);   cudaGetSymbolAddress((void**)&Qlp, g_Ql);
    cudaGetSymbolAddress((void**)&Kthp, g_Kth); cudaGetSymbolAddress((void**)&Ktlp, g_Ktl);
    cudaGetSymbolAddress((void**)&Vthp, g_Vth); cudaGetSymbolAddress((void**)&Vtlp, g_Vtl);
    cudaGetSymbolAddress((void**)&Kihp, g_Kih); cudaGetSymbolAddress((void**)&Kilp, g_Kil);
    cudaGetSymbolAddress((void**)&Vihp, g_Vih); cudaGetSymbolAddress((void**)&Vilp, g_Vil);

    cudaFuncSetAttribute(gemm_tc, cudaFuncAttributeMaxDynamicSharedMemorySize, GEMM_SMEM);
    cudaFuncSetAttribute(attn_kernel, cudaFuncAttributeMaxDynamicSharedMemorySize, ATT_SMEM);

#define CVT_GRID(Mrows) ((Mrows) * 2)

    // conversions (hi/lo bf16 split)
    cvt_split<<<CVT_GRID(BATCH * LQ), 256>>>(x, xh, xl, BATCH * LQ, BATCH * LQ, 0, 0);
    cvt_split<<<CVT_GRID(DIMN), 256>>>(w_q, wqh, wql, DIMN, DIMN, 0, 0);
    cvt_split<<<CVT_GRID(DIMN), 256>>>(w_k, wkh, wkl, DIMN, DIMN, 0, 0);
    cvt_split<<<CVT_GRID(DIMN), 256>>>(w_v, wvh, wvl, DIMN, DIMN, 0, 0);
    cvt_split<<<CVT_GRID(DIMN), 256>>>(w_k_img, wkih, wkil, DIMN, DIMN, 0, 0);
    cvt_split<<<CVT_GRID(DIMN), 256>>>(w_v_img, wvih, wvil, DIMN, DIMN, 0, 0);
    cvt_split<<<CVT_GRID(DIMN), 256>>>(w_o, woh, wol, DIMN, DIMN, 0, 0);
    cvt_split<<<CVT_GRID(BATCH * TXT_T), 256>>>(context, cth, ctl,
                                                BATCH * TXT_T, TXT_T, LCTX, IMG_T);
    cvt_split<<<CVT_GRID(MPAD_IMG), 256>>>(context, cih, cil,
                                           BATCH * IMG_T, IMG_T, LCTX, 0);

    // Q = rmsnorm(x @ w_q^T + b_q) -> hi/lo
    gemm_tc<<<dim3(16, 64), 256, GEMM_SMEM>>>(xh, xl, wqh, wql, b_q, Qb, BATCH * LQ);
    rmsnorm_split<<<BATCH * LQ, 256>>>(Qb, g_q, Qhp, Qlp);

    // K_txt / V_txt
    gemm_tc<<<dim3(16, 8), 256, GEMM_SMEM>>>(cth, ctl, wkh, wkl, b_k, Ktb, BATCH * TXT_T);
    rmsnorm_split<<<BATCH * TXT_T, 256>>>(Ktb, g_k, Kthp, Ktlp);
    gemm_tc<<<dim3(16, 8), 256, GEMM_SMEM>>>(cth, ctl, wvh, wvl, b_v, Vtb, BATCH * TXT_T);
    cvt_split<<<CVT_GRID(BATCH * TXT_T), 256>>>(Vtb, Vthp, Vtlp,
                                                BATCH * TXT_T, BATCH * TXT_T, 0, 0);

    // K_img / V_img (M=514, padded to 640 in GEMM)
    gemm_tc<<<dim3(16, 5), 256, GEMM_SMEM>>>(cih, cil, wkih, wkil, b_k_img, Kib, BATCH * IMG_T);
    rmsnorm_split<<<BATCH * IMG_T, 256>>>(Kib, g_k_img, Kihp, Kilp);
    gemm_tc<<<dim3(16, 5), 256, GEMM_SMEM>>>(cih, cil, wvih, wvil, b_v_img, Vib, BATCH * IMG_T);
    cvt_split<<<CVT_GRID(BATCH * IMG_T), 256>>>(Vib, Vihp, Vilp,
                                                BATCH * IMG_T, BATCH * IMG_T, 0, 0);

    // attention (img + txt) -> g_ah/g_al (bf16 hi/lo)
    attn_kernel<<<dim3(LQ / 64, NHEADS, BATCH), 256, ATT_SMEM>>>(lens);

    // out = attn @ w_o^T + b_o
    gemm_tc<<<dim3(16, 64), 256, GEMM_SMEM>>>(ah, al, woh, wol, b_o, out, BATCH * LQ);
}

// round 6
// speedup vs baseline: 3.7916x; 1.3244x over previous
#include <cuda_runtime.h>
#include <cuda_bf16.h>
#include <math.h>
#include <stdint.h>

#define DIMN 2048
#define NHEADS 16
#define HDIM 128
#define BATCH 2
#define LQ 4096
#define LCTX 769
#define IMG_T 257
#define TXT_T 512
#define EPS_F 1e-6f
#define ATT_SCALE 0.08838834764831845f  /* 1/sqrt(128) */

// ---------------- scratch (device globals; no allocs allowed) --------------
__device__ float g_Q   [BATCH * LQ    * DIMN];
__device__ float g_Ktxt[BATCH * TXT_T * DIMN];
__device__ float g_Kimg[BATCH * IMG_T * DIMN];

// bf16 hi/lo split buffers
#define MPAD_IMG 640
__device__ __nv_bfloat16 g_xh [BATCH * LQ * DIMN];
__device__ __nv_bfloat16 g_xl [BATCH * LQ * DIMN];
__device__ __nv_bfloat16 g_ah [BATCH * LQ * DIMN];
__device__ __nv_bfloat16 g_al [BATCH * LQ * DIMN];
__device__ __nv_bfloat16 g_cth[BATCH * TXT_T * DIMN];
__device__ __nv_bfloat16 g_ctl[BATCH * TXT_T * DIMN];
__device__ __nv_bfloat16 g_cih[MPAD_IMG * DIMN];
__device__ __nv_bfloat16 g_cil[MPAD_IMG * DIMN];
__device__ __nv_bfloat16 g_wqh [DIMN * DIMN], g_wql [DIMN * DIMN];
__device__ __nv_bfloat16 g_wkh [DIMN * DIMN], g_wkl [DIMN * DIMN];
__device__ __nv_bfloat16 g_wvh [DIMN * DIMN], g_wvl [DIMN * DIMN];
__device__ __nv_bfloat16 g_wkih[DIMN * DIMN], g_wkil[DIMN * DIMN];
__device__ __nv_bfloat16 g_wvih[DIMN * DIMN], g_wvil[DIMN * DIMN];
__device__ __nv_bfloat16 g_woh [DIMN * DIMN], g_wol [DIMN * DIMN];

// attention-side hi/lo operands
__device__ __nv_bfloat16 g_Qh [BATCH * LQ * DIMN],    g_Ql [BATCH * LQ * DIMN];
__device__ __nv_bfloat16 g_Kth[BATCH * TXT_T * DIMN], g_Ktl[BATCH * TXT_T * DIMN];
__device__ __nv_bfloat16 g_Vth[BATCH * TXT_T * DIMN], g_Vtl[BATCH * TXT_T * DIMN];
__device__ __nv_bfloat16 g_Kih[BATCH * IMG_T * DIMN], g_Kil[BATCH * IMG_T * DIMN];
__device__ __nv_bfloat16 g_Vih[MPAD_IMG * DIMN],      g_Vil[MPAD_IMG * DIMN];

// ---------------------------- helpers ---------------------------------------
__device__ __forceinline__ uint32_t smem_u32(const void* p) {
    uint32_t a;
    asm("{ .reg .u64 t; cvta.to.shared.u64 t, %1; cvt.u32.u64 %0, t; }"
        : "=r"(a) : "l"(p));
    return a;
}

__device__ __forceinline__ void mma16816(float* d, const uint32_t* a,
                                         const uint32_t b0, const uint32_t b1) {
    asm volatile(
        "mma.sync.aligned.m16n8k16.row.col.f32.bf16.bf16.f32 "
        "{%0,%1,%2,%3}, {%4,%5,%6,%7}, {%8,%9}, {%0,%1,%2,%3};"
        : "+f"(d[0]), "+f"(d[1]), "+f"(d[2]), "+f"(d[3])
        : "r"(a[0]), "r"(a[1]), "r"(a[2]), "r"(a[3]), "r"(b0), "r"(b1));
}

__device__ __forceinline__ void ldsm4(uint32_t* r, uint32_t a) {
    asm volatile("ldmatrix.sync.aligned.m8n8.x4.shared.b16 {%0,%1,%2,%3}, [%4];"
                 : "=r"(r[0]), "=r"(r[1]), "=r"(r[2]), "=r"(r[3]) : "r"(a));
}
__device__ __forceinline__ void ldsm4t(uint32_t* r, uint32_t a) {
    asm volatile("ldmatrix.sync.aligned.m8n8.x4.trans.shared.b16 {%0,%1,%2,%3}, [%4];"
                 : "=r"(r[0]), "=r"(r[1]), "=r"(r[2]), "=r"(r[3]) : "r"(a));
}
__device__ __forceinline__ void cp16(uint32_t d, const void* s) {
    asm volatile("cp.async.cg.shared.global [%0], [%1], 16;"
                 :: "r"(d), "l"(s) : "memory");
}
__device__ __forceinline__ void cp16z(uint32_t d, const void* s, int sz) {
    asm volatile("cp.async.cg.shared.global [%0], [%1], 16, %2;"
                 :: "r"(d), "l"(s), "r"(sz) : "memory");
}
#define CP_COMMIT() asm volatile("cp.async.commit_group;" ::: "memory")
#define CP_WAIT(n)  asm volatile("cp.async.wait_group %0;" :: "n"(n) : "memory")

// f32x2 -> bf16x2 hi + lo residual
__device__ __forceinline__ void split2(float2 f, uint32_t& h, uint32_t& l) {
    __nv_bfloat162 hb = __float22bfloat162_rn(f);
    float2 hf = __bfloat1622float2(hb);
    __nv_bfloat162 lb = __float22bfloat162_rn(make_float2(f.x - hf.x, f.y - hf.y));
    h = *(uint32_t*)&hb;
    l = *(uint32_t*)&lb;
}

// -------------- fp32 -> bf16 hi/lo split (with row remap + pad) ------------
__global__ __launch_bounds__(256)
void cvt_split(const float* __restrict__ src,
               __nv_bfloat16* __restrict__ hi, __nv_bfloat16* __restrict__ lo,
               int Mvalid, int rows_pb, int bstride, int roff)
{
    const long i4 = (long)blockIdx.x * 256 + threadIdx.x;
    const long e  = i4 * 4;
    const int  m  = (int)(e >> 11);
    const int  col = (int)(e & 2047);

    float4 v = make_float4(0.f, 0.f, 0.f, 0.f);
    if (m < Mvalid) {
        const int bb = m / rows_pb;
        const long srow = (long)bb * bstride + roff + (m - bb * rows_pb);
        v = *(const float4*)(src + srow * DIMN + col);
    }
    uint32_t h0, l0, h1, l1;
    split2(make_float2(v.x, v.y), h0, l0);
    split2(make_float2(v.z, v.w), h1, l1);
    *(uint2*)(hi + e) = make_uint2(h0, h1);
    *(uint2*)(lo + e) = make_uint2(l0, l1);
}

// ------------- batched HMMA GEMM: C = (Ah+Al)(Bh+Bl)^T + bias (3 terms) ----
#define GT_KC 32
#define NCHUNK (DIMN / GT_KC)        /* 64 */
#define TILE_B   10240               /* 128 x 80 bytes */
#define BUF_B    (4 * TILE_B)
#define GEMM_SMEM (2 * BUF_B)

struct GJob {
    const __nv_bfloat16 *Ah, *Al, *Bh, *Bl;
    const float *bias;
    float *C;                      // fp32 out (may be null)
    __nv_bfloat16 *Ch, *Cl;        // hi/lo out (may be null)
    int Mvalid;
    int cta0;
};
struct GParams { GJob j[5]; };

__global__ __launch_bounds__(256, 2)
void gemm_batch(GParams P)
{
    extern __shared__ __nv_bfloat16 sm[];

    const int bid = blockIdx.x;
    int ji = 0;
#pragma unroll
    for (int k = 1; k < 5; k++) if (bid >= P.j[k].cta0) ji = k;
    const GJob& J = P.j[ji];
    const int local = bid - J.cta0;
    const int n0 = (local & 15) * 128;
    const int m0 = (local >> 4) * 128;

    const int tid = threadIdx.x;
    const int wid = tid >> 5;
    const int lane = tid & 31;
    const int wm = wid & 3;
    const int wn = wid >> 2;

    const __nv_bfloat16* srcs[4] = {
        J.Ah + (size_t)m0 * DIMN, J.Al + (size_t)m0 * DIMN,
        J.Bh + (size_t)n0 * DIMN, J.Bl + (size_t)n0 * DIMN };

    const uint32_t smb = smem_u32(sm);

    auto load_chunk = [&](int c, int b) {
        const int k0 = c * GT_KC;
#pragma unroll
        for (int j = 0; j < 8; j++) {
            const int f = j * 256 + tid;
            const int tile = f >> 9;
            const int w = f & 511;
            const int r = w >> 2;
            const int cc = w & 3;
            const __nv_bfloat16* sp = srcs[tile] + (size_t)r * DIMN + k0 + cc * 8;
            cp16(smb + b * BUF_B + tile * TILE_B + r * 80 + cc * 16, sp);
        }
        CP_COMMIT();
    };

    float acc[2][8][4];
#pragma unroll
    for (int i = 0; i < 2; i++)
#pragma unroll
        for (int j = 0; j < 8; j++)
#pragma unroll
            for (int q = 0; q < 4; q++) acc[i][j][q] = 0.f;

    const uint32_t aOff = (uint32_t)(wm * 32 + (lane & 15)) * 80 + ((lane >> 4) * 16);
    const uint32_t bOff = (uint32_t)(wn * 64 + (lane & 7) + ((lane >> 4) << 3)) * 80
                        + (((lane >> 3) & 1) * 16) + 2 * TILE_B;

    load_chunk(0, 0);
    load_chunk(1, 1);

    for (int c = 0; c < NCHUNK; c++) {
        const int b = c & 1;
        if (c == NCHUNK - 1) CP_WAIT(0);
        else                 CP_WAIT(1);
        __syncthreads();

        const uint32_t buf = smb + b * BUF_B;

#pragma unroll
        for (int s = 0; s < 2; s++) {
            uint32_t ah_[2][4], al_[2][4];
#pragma unroll
            for (int mt = 0; mt < 2; mt++) {
                ldsm4(ah_[mt], buf + aOff + mt * 16 * 80 + s * 32);
                ldsm4(al_[mt], buf + aOff + mt * 16 * 80 + s * 32 + TILE_B);
            }
#pragma unroll
            for (int t = 0; t < 4; t++) {
                uint32_t bh_[4], bl_[4];
                ldsm4(bh_, buf + bOff + t * 16 * 80 + s * 32);
                ldsm4(bl_, buf + bOff + t * 16 * 80 + s * 32 + TILE_B);
#pragma unroll
                for (int mt = 0; mt < 2; mt++) {
                    mma16816(acc[mt][2 * t],     ah_[mt], bh_[0], bh_[1]);
                    mma16816(acc[mt][2 * t],     ah_[mt], bl_[0], bl_[1]);
                    mma16816(acc[mt][2 * t],     al_[mt], bh_[0], bh_[1]);
                    mma16816(acc[mt][2 * t + 1], ah_[mt], bh_[2], bh_[3]);
                    mma16816(acc[mt][2 * t + 1], ah_[mt], bl_[2], bl_[3]);
                    mma16816(acc[mt][2 * t + 1], al_[mt], bh_[2], bh_[3]);
                }
            }
        }
        __syncthreads();
        if (c + 2 < NCHUNK) load_chunk(c + 2, b);
    }

    const int lr = lane >> 2;
    const int lc = (lane & 3) * 2;
#pragma unroll
    for (int mt = 0; mt < 2; mt++) {
#pragma unroll
        for (int nt = 0; nt < 8; nt++) {
            const int n = n0 + wn * 64 + nt * 8 + lc;
            const float2 bv = *(const float2*)&J.bias[n];
            const int mA = m0 + wm * 32 + mt * 16 + lr;
            float2 o0 = make_float2(acc[mt][nt][0] + bv.x, acc[mt][nt][1] + bv.y);
            float2 o1 = make_float2(acc[mt][nt][2] + bv.x, acc[mt][nt][3] + bv.y);
            if (J.C) {
                if (mA < J.Mvalid)     *(float2*)(J.C + (size_t)mA * DIMN + n) = o0;
                if (mA + 8 < J.Mvalid) *(float2*)(J.C + (size_t)(mA + 8) * DIMN + n) = o1;
            }
            if (J.Ch) {
                uint32_t hh, ll;
                if (mA < J.Mvalid) {
                    split2(o0, hh, ll);
                    *(uint32_t*)(J.Ch + (size_t)mA * DIMN + n) = hh;
                    *(uint32_t*)(J.Cl + (size_t)mA * DIMN + n) = ll;
                }
                if (mA + 8 < J.Mvalid) {
                    split2(o1, hh, ll);
                    *(uint32_t*)(J.Ch + (size_t)(mA + 8) * DIMN + n) = hh;
                    *(uint32_t*)(J.Cl + (size_t)(mA + 8) * DIMN + n) = ll;
                }
            }
        }
    }
}

// ------------- RMS norm -> bf16 hi/lo split (fused) -------------------------
__global__ __launch_bounds__(256)
void rmsnorm_split(const float* __restrict__ X, const float* __restrict__ g,
                   __nv_bfloat16* __restrict__ H, __nv_bfloat16* __restrict__ L)
{
    const int row = blockIdx.x;
    const float* xr = X + (long)row * DIMN;
    const int t = threadIdx.x;

    float4 v0 = *(const float4*)&xr[t * 4];
    float4 v1 = *(const float4*)&xr[1024 + t * 4];
    float ss = v0.x * v0.x + v0.y * v0.y + v0.z * v0.z + v0.w * v0.w
             + v1.x * v1.x + v1.y * v1.y + v1.z * v1.z + v1.w * v1.w;

#pragma unroll
    for (int o = 16; o > 0; o >>= 1) ss += __shfl_xor_sync(0xffffffffu, ss, o);

    __shared__ float red[8];
    if ((t & 31) == 0) red[t >> 5] = ss;
    __syncthreads();
    float total = 0.f;
#pragma unroll
    for (int i = 0; i < 8; i++) total += red[i];

    const float scale = rsqrtf(total * (1.0f / DIMN) + EPS_F);

    const float4 g0 = *(const float4*)&g[t * 4];
    const float4 g1 = *(const float4*)&g[1024 + t * 4];
    v0.x *= scale * g0.x; v0.y *= scale * g0.y; v0.z *= scale * g0.z; v0.w *= scale * g0.w;
    v1.x *= scale * g1.x; v1.y *= scale * g1.y; v1.z *= scale * g1.z; v1.w *= scale * g1.w;

    uint32_t h0, l0, h1, l1;
    split2(make_float2(v0.x, v0.y), h0, l0);
    split2(make_float2(v0.z, v0.w), h1, l1);
    *(uint2*)(H + (long)row * DIMN + t * 4) = make_uint2(h0, h1);
    *(uint2*)(L + (long)row * DIMN + t * 4) = make_uint2(l0, l1);
    split2(make_float2(v1.x, v1.y), h0, l0);
    split2(make_float2(v1.z, v1.w), h1, l1);
    *(uint2*)(H + (long)row * DIMN + 1024 + t * 4) = make_uint2(h0, h1);
    *(uint2*)(L + (long)row * DIMN + 1024 + t * 4) = make_uint2(l0, l1);
}

// ---------------- flash attention (img + txt), HMMA 3-term ------------------
// q-tile 128, 8 warps (16 q-rows each, full 64-key chunk width).
// Q + online stats + O register-resident; K/V double-buffered cp.async.
// 13 static chunks: 5 img (valid 257) + 8 txt (valid lens[b]).
#define KVB 34816                    /* one K or V buffer: hi 64x272 + lo */
#define OST_OFF (4 * KVB)            /* 139264 */
#define ATT_SMEM (OST_OFF + 128 * 128 * 4)   /* 204800 */
#define NCHUNKS_ATT 13

__global__ __launch_bounds__(256, 1)
void attn_kernel(const int* __restrict__ lens)
{
    extern __shared__ char smraw[];
    const uint32_t smb = smem_u32(smraw);
    float* Ost = (float*)(smraw + OST_OFF);

    const int qt = blockIdx.x, h = blockIdx.y, b = blockIdx.z;
    const int tid = threadIdx.x;
    const int wq = tid >> 5;
    const int lane = tid & 31;
    const int q0 = qt * 128;

    const int vtxt = min(lens[b], TXT_T);
    const size_t ibase = (size_t)b * IMG_T * DIMN + h * HDIM;
    const size_t tbase = (size_t)b * TXT_T * DIMN + h * HDIM;

    // ---- stage Q hi/lo into smem (KB area), then ldmatrix into regs ----
    for (int f = tid; f < 2048; f += 256) {
        const int r = f >> 4, c = f & 15;
        const size_t off = ((size_t)(b * LQ + q0 + r)) * DIMN + h * HDIM + c * 8;
        cp16(smb + r * 272 + c * 16,         g_Qh + off);
        cp16(smb + KVB + r * 272 + c * 16,   g_Ql + off);
    }
    CP_COMMIT();
    CP_WAIT(0);
    __syncthreads();

    uint32_t qh[8][4], ql[8][4];
    {
        const uint32_t aQ = smb + (uint32_t)(wq * 16 + (lane & 15)) * 272
                          + ((lane >> 4) * 16);
#pragma unroll
        for (int s8 = 0; s8 < 8; s8++) {
            ldsm4(qh[s8], aQ + s8 * 32);
            ldsm4(ql[s8], aQ + s8 * 32 + KVB);
        }
    }
    __syncthreads();

    // ---- chunk loaders ----
    auto loadK = [&](int ci) {
        if (ci < NCHUNKS_ATT) {
            const __nv_bfloat16 *kh, *kl; int kbase, Lk; size_t base;
            if (ci < 5) { kh = g_Kih; kl = g_Kil; kbase = ci * 64; Lk = IMG_T; base = ibase; }
            else        { kh = g_Kth; kl = g_Ktl; kbase = (ci - 5) * 64; Lk = TXT_T; base = tbase; }
            const uint32_t dst = smb + (ci & 1) * KVB;
            for (int f = tid; f < 1024; f += 256) {
                const int r = f >> 4, cc = f & 15;
                const int kr = kbase + r;
                const int sz = (kr < Lk) ? 16 : 0;
                const int krc = (kr < Lk) ? kr : 0;
                const size_t off = base + (size_t)krc * DIMN + cc * 8;
                cp16z(dst + r * 272 + cc * 16,          kh + off, sz);
                cp16z(dst + 17408 + r * 272 + cc * 16,  kl + off, sz);
            }
        }
        CP_COMMIT();
    };
    auto loadV = [&](int ci) {
        if (ci < NCHUNKS_ATT) {
            const __nv_bfloat16 *vh, *vl; int kbase, Lk; size_t base;
            if (ci < 5) { vh = g_Vih; vl = g_Vil; kbase = ci * 64; Lk = IMG_T; base = ibase; }
            else        { vh = g_Vth; vl = g_Vtl; kbase = (ci - 5) * 64; Lk = TXT_T; base = tbase; }
            const uint32_t dst = smb + 2 * KVB + (ci & 1) * KVB;
            for (int f = tid; f < 1024; f += 256) {
                const int r = f >> 4, cc = f & 15;
                const int kr = kbase + r;
                const int sz = (kr < Lk) ? 16 : 0;
                const int krc = (kr < Lk) ? kr : 0;
                const size_t off = base + (size_t)krc * DIMN + cc * 8;
                cp16z(dst + r * 272 + cc * 16,          vh + off, sz);
                cp16z(dst + 17408 + r * 272 + cc * 16,  vl + off, sz);
            }
        }
        CP_COMMIT();
    };

    float o[16][4];
#pragma unroll
    for (int i = 0; i < 16; i++)
#pragma unroll
        for (int j = 0; j < 4; j++) o[i][j] = 0.f;
    float m0 = -1e30f, m1 = -1e30f, l0 = 0.f, l1 = 0.f;

    const uint32_t kbK = (uint32_t)((lane & 7) + ((lane >> 4) << 3)) * 272
                       + (((lane >> 3) & 1) * 16);
    const uint32_t vbV = (uint32_t)(lane & 15) * 272 + ((lane >> 4) * 16);
    const int qg = lane >> 2;             // row within 16
    const int qc = 2 * (lane & 3);        // col pair base

    // pipeline prologue: K0, V0, K1
    loadK(0); loadV(0); loadK(1);

    for (int ci = 0; ci < NCHUNKS_ATT; ci++) {
        const int buf = ci & 1;
        const int kbase = (ci < 5) ? ci * 64 : (ci - 5) * 64;
        const int valid = (ci < 5) ? IMG_T : vtxt;

        CP_WAIT(2);               // K(ci) ready
        __syncthreads();
        loadV(ci + 1);            // prefetch (VB[buf^1] free)

        // ---- QK scores (3-term) ----
        float s[8][4];
#pragma unroll
        for (int i = 0; i < 8; i++)
#pragma unroll
            for (int j = 0; j < 4; j++) s[i][j] = 0.f;

        const uint32_t KH = smb + buf * KVB;
#pragma unroll
        for (int s8 = 0; s8 < 8; s8++) {
#pragma unroll
            for (int t = 0; t < 4; t++) {
                uint32_t kh_[4], kl_[4];
                ldsm4(kh_, KH + kbK + t * 16 * 272 + s8 * 32);
                ldsm4(kl_, KH + kbK + t * 16 * 272 + s8 * 32 + 17408);
                mma16816(s[2 * t],     qh[s8], kh_[0], kh_[1]);
                mma16816(s[2 * t],     qh[s8], kl_[0], kl_[1]);
                mma16816(s[2 * t],     ql[s8], kh_[0], kh_[1]);
                mma16816(s[2 * t + 1], qh[s8], kh_[2], kh_[3]);
                mma16816(s[2 * t + 1], qh[s8], kl_[2], kl_[3]);
                mma16816(s[2 * t + 1], ql[s8], kh_[2], kh_[3]);
            }
        }

        // ---- online softmax (register-resident, quad reduce) ----
        float cm0 = -1e30f, cm1 = -1e30f;
#pragma unroll
        for (int nt = 0; nt < 8; nt++) {
            const int c0 = kbase + nt * 8 + qc;
#pragma unroll
            for (int j = 0; j < 2; j++) {
                const bool ok = (c0 + j) < valid;
                float t0 = ok ? s[nt][j] * ATT_SCALE : -1e30f;
                float t1 = ok ? s[nt][j + 2] * ATT_SCALE : -1e30f;
                s[nt][j] = t0; s[nt][j + 2] = t1;
                cm0 = fmaxf(cm0, t0); cm1 = fmaxf(cm1, t1);
            }
        }
        cm0 = fmaxf(cm0, __shfl_xor_sync(0xffffffffu, cm0, 1));
        cm0 = fmaxf(cm0, __shfl_xor_sync(0xffffffffu, cm0, 2));
        cm1 = fmaxf(cm1, __shfl_xor_sync(0xffffffffu, cm1, 1));
        cm1 = fmaxf(cm1, __shfl_xor_sync(0xffffffffu, cm1, 2));

        const float mn0 = fmaxf(m0, cm0), mn1 = fmaxf(m1, cm1);
        const float sc0 = __expf(m0 - mn0), sc1 = __expf(m1 - mn1);
        m0 = mn0; m1 = mn1;

        float sum0 = 0.f, sum1 = 0.f;
#pragma unroll
        for (int nt = 0; nt < 8; nt++) {
#pragma unroll
            for (int j = 0; j < 2; j++) {
                float p0 = __expf(s[nt][j] - m0);
                float p1 = __expf(s[nt][j + 2] - m1);
                s[nt][j] = p0; s[nt][j + 2] = p1;
                sum0 += p0; sum1 += p1;
            }
        }
        sum0 += __shfl_xor_sync(0xffffffffu, sum0, 1);
        sum0 += __shfl_xor_sync(0xffffffffu, sum0, 2);
        sum1 += __shfl_xor_sync(0xffffffffu, sum1, 1);
        sum1 += __shfl_xor_sync(0xffffffffu, sum1, 2);
        l0 = l0 * sc0 + sum0;
        l1 = l1 * sc1 + sum1;
#pragma unroll
        for (int nt = 0; nt < 16; nt++) {
            o[nt][0] *= sc0; o[nt][1] *= sc0;
            o[nt][2] *= sc1; o[nt][3] *= sc1;
        }

        CP_WAIT(2);               // V(ci) ready
        __syncthreads();
        loadK(ci + 2);            // prefetch (KB[buf] done)

        // ---- P @ V (3-term; P C-frags reused as A-frags) ----
        const uint32_t VH = smb + 2 * KVB + buf * KVB;
#pragma unroll
        for (int kk = 0; kk < 4; kk++) {
            uint32_t pah[4], pal[4];
            split2(make_float2(s[2 * kk][0],     s[2 * kk][1]),     pah[0], pal[0]);
            split2(make_float2(s[2 * kk][2],     s[2 * kk][3]),     pah[1], pal[1]);
            split2(make_float2(s[2 * kk + 1][0], s[2 * kk + 1][1]), pah[2], pal[2]);
            split2(make_float2(s[2 * kk + 1][2], s[2 * kk + 1][3]), pah[3], pal[3]);
            const uint32_t va = VH + vbV + kk * 16 * 272;
#pragma unroll
            for (int t = 0; t < 8; t++) {
                uint32_t vh_[4], vl_[4];
                ldsm4t(vh_, va + t * 32);
                ldsm4t(vl_, va + t * 32 + 17408);
                mma16816(o[2 * t],     pah, vh_[0], vh_[1]);
                mma16816(o[2 * t],     pah, vl_[0], vl_[1]);
                mma16816(o[2 * t],     pal, vh_[0], vh_[1]);
                mma16816(o[2 * t + 1], pah, vh_[2], vh_[3]);
                mma16816(o[2 * t + 1], pah, vl_[2], vl_[3]);
                mma16816(o[2 * t + 1], pal, vh_[2], vh_[3]);
            }
        }

        // ---- end of img phase: stash normalized output, reset stats ----
        if (ci == 4) {
            const float i0 = 1.f / l0, i1 = 1.f / l1;
            const int r0 = wq * 16 + qg;
#pragma unroll
            for (int nt = 0; nt < 16; nt++) {
                const int col = nt * 8 + qc;
                *(float2*)&Ost[r0 * 128 + col] =
                    make_float2(o[nt][0] * i0, o[nt][1] * i0);
                *(float2*)&Ost[(r0 + 8) * 128 + col] =
                    make_float2(o[nt][2] * i1, o[nt][3] * i1);
                o[nt][0] = o[nt][1] = o[nt][2] = o[nt][3] = 0.f;
            }
            m0 = m1 = -1e30f; l0 = l1 = 0.f;
        }
    }

    // ---- epilogue: out = img_stash + txt/l, write bf16 hi/lo ----
    const float i0 = 1.f / l0, i1 = 1.f / l1;
    const int r0 = wq * 16 + qg;
#pragma unroll
    for (int nt = 0; nt < 16; nt++) {
        const int col = nt * 8 + qc;
        const float2 e0 = *(const float2*)&Ost[r0 * 128 + col];
        const float2 e1 = *(const float2*)&Ost[(r0 + 8) * 128 + col];
        const int gcol = h * HDIM + col;
        const size_t a0 = (size_t)(b * LQ + q0 + r0) * DIMN + gcol;
        const size_t a1 = (size_t)(b * LQ + q0 + r0 + 8) * DIMN + gcol;
        uint32_t hh, ll;
        split2(make_float2(e0.x + o[nt][0] * i0, e0.y + o[nt][1] * i0), hh, ll);
        *(uint32_t*)&g_ah[a0] = hh;
        *(uint32_t*)&g_al[a0] = ll;
        split2(make_float2(e1.x + o[nt][2] * i1, e1.y + o[nt][3] * i1), hh, ll);
        *(uint32_t*)&g_ah[a1] = hh;
        *(uint32_t*)&g_al[a1] = ll;
    }
}

// ---------------------------- launch ---------------------------------------
extern "C" void kernel_launch(void* const* d_in, const int* in_sizes, int n_in,
                              void* d_out, int out_size)
{
    const float* x        = (const float*)d_in[0];
    const float* context  = (const float*)d_in[1];
    const int*   lens     = (const int*)  d_in[2];
    const float* w_q      = (const float*)d_in[3];
    const float* b_q      = (const float*)d_in[4];
    const float* w_k      = (const float*)d_in[5];
    const float* b_k      = (const float*)d_in[6];
    const float* w_v      = (const float*)d_in[7];
    const float* b_v      = (const float*)d_in[8];
    const float* w_k_img  = (const float*)d_in[9];
    const float* b_k_img  = (const float*)d_in[10];
    const float* w_v_img  = (const float*)d_in[11];
    const float* b_v_img  = (const float*)d_in[12];
    const float* w_o      = (const float*)d_in[13];
    const float* b_o      = (const float*)d_in[14];
    const float* g_q      = (const float*)d_in[15];
    const float* g_k      = (const float*)d_in[16];
    const float* g_k_img  = (const float*)d_in[17];
    float* out = (float*)d_out;

    float *Qb, *Ktb, *Kib;
    cudaGetSymbolAddress((void**)&Qb,  g_Q);
    cudaGetSymbolAddress((void**)&Ktb, g_Ktxt);
    cudaGetSymbolAddress((void**)&Kib, g_Kimg);

    __nv_bfloat16 *xh, *xl, *ah, *al, *cth, *ctl, *cih, *cil;
    __nv_bfloat16 *wqh, *wql, *wkh, *wkl, *wvh, *wvl, *wkih, *wkil, *wvih, *wvil, *woh, *wol;
    __nv_bfloat16 *Qhp, *Qlp, *Kthp, *Ktlp, *Vthp, *Vtlp, *Kihp, *Kilp, *Vihp, *Vilp;
    cudaGetSymbolAddress((void**)&xh,  g_xh);   cudaGetSymbolAddress((void**)&xl,  g_xl);
    cudaGetSymbolAddress((void**)&ah,  g_ah);   cudaGetSymbolAddress((void**)&al,  g_al);
    cudaGetSymbolAddress((void**)&cth, g_cth);  cudaGetSymbolAddress((void**)&ctl, g_ctl);
    cudaGetSymbolAddress((void**)&cih, g_cih);  cudaGetSymbolAddress((void**)&cil, g_cil);
    cudaGetSymbolAddress((void**)&wqh, g_wqh);  cudaGetSymbolAddress((void**)&wql, g_wql);
    cudaGetSymbolAddress((void**)&wkh, g_wkh);  cudaGetSymbolAddress((void**)&wkl, g_wkl);
    cudaGetSymbolAddress((void**)&wvh, g_wvh);  cudaGetSymbolAddress((void**)&wvl, g_wvl);
    cudaGetSymbolAddress((void**)&wkih, g_wkih); cudaGetSymbolAddress((void**)&wkil, g_wkil);
    cudaGetSymbolAddress((void**)&wvih, g_wvih); cudaGetSymbolAddress((void**)&wvil, g_wvil);
    cudaGetSymbolAddress((void**)&woh, g_woh);  cudaGetSymbolAddress((void**)&wol, g_wol);
    cudaGetSymbolAddress((void**)&Qhp, g_Qh);   cudaGetSymbolAddress((void**)&Qlp, g_Ql);
    cudaGetSymbolAddress((void**)&Kthp, g_Kth); cudaGetSymbolAddress((void**)&Ktlp, g_Ktl);
    cudaGetSymbolAddress((void**)&Vthp, g_Vth); cudaGetSymbolAddress((void**)&Vtlp, g_Vtl);
    cudaGetSymbolAddress((void**)&Kihp, g_Kih); cudaGetSymbolAddress((void**)&Kilp, g_Kil);
    cudaGetSymbolAddress((void**)&Vihp, g_Vih); cudaGetSymbolAddress((void**)&Vilp, g_Vil);

    cudaFuncSetAttribute(gemm_batch, cudaFuncAttributeMaxDynamicSharedMemorySize, GEMM_SMEM);
    cudaFuncSetAttribute(attn_kernel, cudaFuncAttributeMaxDynamicSharedMemorySize, ATT_SMEM);

#define CVT_GRID(Mrows) ((Mrows) * 2)

    // conversions (hi/lo bf16 split)
    cvt_split<<<CVT_GRID(BATCH * LQ), 256>>>(x, xh, xl, BATCH * LQ, BATCH * LQ, 0, 0);
    cvt_split<<<CVT_GRID(DIMN), 256>>>(w_q, wqh, wql, DIMN, DIMN, 0, 0);
    cvt_split<<<CVT_GRID(DIMN), 256>>>(w_k, wkh, wkl, DIMN, DIMN, 0, 0);
    cvt_split<<<CVT_GRID(DIMN), 256>>>(w_v, wvh, wvl, DIMN, DIMN, 0, 0);
    cvt_split<<<CVT_GRID(DIMN), 256>>>(w_k_img, wkih, wkil, DIMN, DIMN, 0, 0);
    cvt_split<<<CVT_GRID(DIMN), 256>>>(w_v_img, wvih, wvil, DIMN, DIMN, 0, 0);
    cvt_split<<<CVT_GRID(DIMN), 256>>>(w_o, woh, wol, DIMN, DIMN, 0, 0);
    cvt_split<<<CVT_GRID(BATCH * TXT_T), 256>>>(context, cth, ctl,
                                                BATCH * TXT_T, TXT_T, LCTX, IMG_T);
    cvt_split<<<CVT_GRID(MPAD_IMG), 256>>>(context, cih, cil,
                                           BATCH * IMG_T, IMG_T, LCTX, 0);

    // batched projection GEMMs: Q, K_txt, V_txt, K_img, V_img (one launch)
    GParams P;
    P.j[0] = { xh,  xl,  wqh,  wql,  b_q,     Qb,  nullptr, nullptr, BATCH * LQ,    0    };
    P.j[1] = { cth, ctl, wkh,  wkl,  b_k,     Ktb, nullptr, nullptr, BATCH * TXT_T, 1024 };
    P.j[2] = { cth, ctl, wvh,  wvl,  b_v,     nullptr, Vthp, Vtlp,   BATCH * TXT_T, 1152 };
    P.j[3] = { cih, cil, wkih, wkil, b_k_img, Kib, nullptr, nullptr, BATCH * IMG_T, 1280 };
    P.j[4] = { cih, cil, wvih, wvil, b_v_img, nullptr, Vihp, Vilp,   BATCH * IMG_T, 1360 };
    gemm_batch<<<1440, 256, GEMM_SMEM>>>(P);

    // rmsnorm + split for Q / K_txt / K_img
    rmsnorm_split<<<BATCH * LQ, 256>>>(Qb, g_q, Qhp, Qlp);
    rmsnorm_split<<<BATCH * TXT_T, 256>>>(Ktb, g_k, Kthp, Ktlp);
    rmsnorm_split<<<BATCH * IMG_T, 256>>>(Kib, g_k_img, Kihp, Kilp);

    // flash attention (img + txt) -> g_ah/g_al (bf16 hi/lo)
    attn_kernel<<<dim3(LQ / 128, NHEADS, BATCH), 256, ATT_SMEM>>>(lens);

    // out = attn @ w_o^T + b_o (single-job batched kernel)
    GParams PO;
    PO.j[0] = { ah, al, woh, wol, b_o, out, nullptr, nullptr, BATCH * LQ, 0 };
    PO.j[1] = PO.j[2] = PO.j[3] = PO.j[4] = PO.j[0];
    PO.j[1].cta0 = PO.j[2].cta0 = PO.j[3].cta0 = PO.j[4].cta0 = 1 << 30;
    gemm_batch<<<1024, 256, GEMM_SMEM>>>(PO);
}

// round 7
// speedup vs baseline: 3.7927x; 1.0003x over previous
#include <cuda_runtime.h>
#include <cuda_bf16.h>
#include <math.h>
#include <stdint.h>

#define DIMN 2048
#define NHEADS 16
#define HDIM 128
#define BATCH 2
#define LQ 4096
#define LCTX 769
#define IMG_T 257
#define TXT_T 512
#define EPS_F 1e-6f
#define ATT_SCALE 0.08838834764831845f  /* 1/sqrt(128) */

// ---------------- scratch (device globals; no allocs allowed) --------------
__device__ float g_Q   [BATCH * LQ    * DIMN];
__device__ float g_Ktxt[BATCH * TXT_T * DIMN];
__device__ float g_Kimg[BATCH * IMG_T * DIMN];

// bf16 hi/lo split buffers
#define MPAD_IMG 640
__device__ __nv_bfloat16 g_xh [BATCH * LQ * DIMN];
__device__ __nv_bfloat16 g_xl [BATCH * LQ * DIMN];
__device__ __nv_bfloat16 g_ah [BATCH * LQ * DIMN];
__device__ __nv_bfloat16 g_al [BATCH * LQ * DIMN];
__device__ __nv_bfloat16 g_cth[BATCH * TXT_T * DIMN];
__device__ __nv_bfloat16 g_ctl[BATCH * TXT_T * DIMN];
__device__ __nv_bfloat16 g_cih[MPAD_IMG * DIMN];
__device__ __nv_bfloat16 g_cil[MPAD_IMG * DIMN];
__device__ __nv_bfloat16 g_wqh [DIMN * DIMN], g_wql [DIMN * DIMN];
__device__ __nv_bfloat16 g_wkh [DIMN * DIMN], g_wkl [DIMN * DIMN];
__device__ __nv_bfloat16 g_wvh [DIMN * DIMN], g_wvl [DIMN * DIMN];
__device__ __nv_bfloat16 g_wkih[DIMN * DIMN], g_wkil[DIMN * DIMN];
__device__ __nv_bfloat16 g_wvih[DIMN * DIMN], g_wvil[DIMN * DIMN];
__device__ __nv_bfloat16 g_woh [DIMN * DIMN], g_wol [DIMN * DIMN];

// attention-side hi/lo operands
__device__ __nv_bfloat16 g_Qh [BATCH * LQ * DIMN],    g_Ql [BATCH * LQ * DIMN];
__device__ __nv_bfloat16 g_Kth[BATCH * TXT_T * DIMN], g_Ktl[BATCH * TXT_T * DIMN];
__device__ __nv_bfloat16 g_Vth[BATCH * TXT_T * DIMN], g_Vtl[BATCH * TXT_T * DIMN];
__device__ __nv_bfloat16 g_Kih[BATCH * IMG_T * DIMN], g_Kil[BATCH * IMG_T * DIMN];
__device__ __nv_bfloat16 g_Vih[MPAD_IMG * DIMN],      g_Vil[MPAD_IMG * DIMN];

// ---------------------------- helpers ---------------------------------------
__device__ __forceinline__ uint32_t smem_u32(const void* p) {
    uint32_t a;
    asm("{ .reg .u64 t; cvta.to.shared.u64 t, %1; cvt.u32.u64 %0, t; }"
        : "=r"(a) : "l"(p));
    return a;
}

__device__ __forceinline__ void mma16816(float* d, const uint32_t* a,
                                         const uint32_t b0, const uint32_t b1) {
    asm volatile(
        "mma.sync.aligned.m16n8k16.row.col.f32.bf16.bf16.f32 "
        "{%0,%1,%2,%3}, {%4,%5,%6,%7}, {%8,%9}, {%0,%1,%2,%3};"
        : "+f"(d[0]), "+f"(d[1]), "+f"(d[2]), "+f"(d[3])
        : "r"(a[0]), "r"(a[1]), "r"(a[2]), "r"(a[3]), "r"(b0), "r"(b1));
}

__device__ __forceinline__ void ldsm4(uint32_t* r, uint32_t a) {
    asm volatile("ldmatrix.sync.aligned.m8n8.x4.shared.b16 {%0,%1,%2,%3}, [%4];"
                 : "=r"(r[0]), "=r"(r[1]), "=r"(r[2]), "=r"(r[3]) : "r"(a));
}
__device__ __forceinline__ void ldsm4t(uint32_t* r, uint32_t a) {
    asm volatile("ldmatrix.sync.aligned.m8n8.x4.trans.shared.b16 {%0,%1,%2,%3}, [%4];"
                 : "=r"(r[0]), "=r"(r[1]), "=r"(r[2]), "=r"(r[3]) : "r"(a));
}
__device__ __forceinline__ void cp16(uint32_t d, const void* s) {
    asm volatile("cp.async.cg.shared.global [%0], [%1], 16;"
                 :: "r"(d), "l"(s) : "memory");
}
__device__ __forceinline__ void cp16z(uint32_t d, const void* s, int sz) {
    asm volatile("cp.async.cg.shared.global [%0], [%1], 16, %2;"
                 :: "r"(d), "l"(s), "r"(sz) : "memory");
}
#define CP_COMMIT() asm volatile("cp.async.commit_group;" ::: "memory")
#define CP_WAIT(n)  asm volatile("cp.async.wait_group %0;" :: "n"(n) : "memory")

// f32x2 -> bf16x2 hi + lo residual
__device__ __forceinline__ void split2(float2 f, uint32_t& h, uint32_t& l) {
    __nv_bfloat162 hb = __float22bfloat162_rn(f);
    float2 hf = __bfloat1622float2(hb);
    __nv_bfloat162 lb = __float22bfloat162_rn(make_float2(f.x - hf.x, f.y - hf.y));
    h = *(uint32_t*)&hb;
    l = *(uint32_t*)&lb;
}

// -------------- fp32 -> bf16 hi/lo split (with row remap + pad) ------------
__global__ __launch_bounds__(256)
void cvt_split(const float* __restrict__ src,
               __nv_bfloat16* __restrict__ hi, __nv_bfloat16* __restrict__ lo,
               int Mvalid, int rows_pb, int bstride, int roff)
{
    const long i4 = (long)blockIdx.x * 256 + threadIdx.x;
    const long e  = i4 * 4;
    const int  m  = (int)(e >> 11);
    const int  col = (int)(e & 2047);

    float4 v = make_float4(0.f, 0.f, 0.f, 0.f);
    if (m < Mvalid) {
        const int bb = m / rows_pb;
        const long srow = (long)bb * bstride + roff + (m - bb * rows_pb);
        v = *(const float4*)(src + srow * DIMN + col);
    }
    uint32_t h0, l0, h1, l1;
    split2(make_float2(v.x, v.y), h0, l0);
    split2(make_float2(v.z, v.w), h1, l1);
    *(uint2*)(hi + e) = make_uint2(h0, h1);
    *(uint2*)(lo + e) = make_uint2(l0, l1);
}

// ------------- batched HMMA GEMM: C = (Ah+Al)(Bh+Bl)^T + bias (3 terms) ----
#define GT_KC 32
#define NCHUNK (DIMN / GT_KC)        /* 64 */
#define TILE_B   10240               /* 128 x 80 bytes */
#define BUF_B    (4 * TILE_B)
#define GEMM_SMEM (2 * BUF_B)

struct GJob {
    const __nv_bfloat16 *Ah, *Al, *Bh, *Bl;
    const float *bias;
    float *C;                      // fp32 out (may be null)
    __nv_bfloat16 *Ch, *Cl;        // hi/lo out (may be null)
    int Mvalid;
    int cta0;
};
struct GParams { GJob j[5]; };

__global__ __launch_bounds__(256, 2)
void gemm_batch(GParams P)
{
    extern __shared__ __nv_bfloat16 sm[];

    const int bid = blockIdx.x;
    int ji = 0;
#pragma unroll
    for (int k = 1; k < 5; k++) if (bid >= P.j[k].cta0) ji = k;
    const GJob& J = P.j[ji];
    const int local = bid - J.cta0;
    const int n0 = (local & 15) * 128;
    const int m0 = (local >> 4) * 128;

    const int tid = threadIdx.x;
    const int wid = tid >> 5;
    const int lane = tid & 31;
    const int wm = wid & 3;
    const int wn = wid >> 2;

    const __nv_bfloat16* srcs[4] = {
        J.Ah + (size_t)m0 * DIMN, J.Al + (size_t)m0 * DIMN,
        J.Bh + (size_t)n0 * DIMN, J.Bl + (size_t)n0 * DIMN };

    const uint32_t smb = smem_u32(sm);

    auto load_chunk = [&](int c, int b) {
        const int k0 = c * GT_KC;
#pragma unroll
        for (int j = 0; j < 8; j++) {
            const int f = j * 256 + tid;
            const int tile = f >> 9;
            const int w = f & 511;
            const int r = w >> 2;
            const int cc = w & 3;
            const __nv_bfloat16* sp = srcs[tile] + (size_t)r * DIMN + k0 + cc * 8;
            cp16(smb + b * BUF_B + tile * TILE_B + r * 80 + cc * 16, sp);
        }
        CP_COMMIT();
    };

    float acc[2][8][4];
#pragma unroll
    for (int i = 0; i < 2; i++)
#pragma unroll
        for (int j = 0; j < 8; j++)
#pragma unroll
            for (int q = 0; q < 4; q++) acc[i][j][q] = 0.f;

    const uint32_t aOff = (uint32_t)(wm * 32 + (lane & 15)) * 80 + ((lane >> 4) * 16);
    const uint32_t bOff = (uint32_t)(wn * 64 + (lane & 7) + ((lane >> 4) << 3)) * 80
                        + (((lane >> 3) & 1) * 16) + 2 * TILE_B;

    load_chunk(0, 0);
    load_chunk(1, 1);

    for (int c = 0; c < NCHUNK; c++) {
        const int b = c & 1;
        if (c == NCHUNK - 1) CP_WAIT(0);
        else                 CP_WAIT(1);
        __syncthreads();

        const uint32_t buf = smb + b * BUF_B;

#pragma unroll
        for (int s = 0; s < 2; s++) {
            uint32_t ah_[2][4], al_[2][4];
#pragma unroll
            for (int mt = 0; mt < 2; mt++) {
                ldsm4(ah_[mt], buf + aOff + mt * 16 * 80 + s * 32);
                ldsm4(al_[mt], buf + aOff + mt * 16 * 80 + s * 32 + TILE_B);
            }
#pragma unroll
            for (int t = 0; t < 4; t++) {
                uint32_t bh_[4], bl_[4];
                ldsm4(bh_, buf + bOff + t * 16 * 80 + s * 32);
                ldsm4(bl_, buf + bOff + t * 16 * 80 + s * 32 + TILE_B);
#pragma unroll
                for (int mt = 0; mt < 2; mt++) {
                    mma16816(acc[mt][2 * t],     ah_[mt], bh_[0], bh_[1]);
                    mma16816(acc[mt][2 * t],     ah_[mt], bl_[0], bl_[1]);
                    mma16816(acc[mt][2 * t],     al_[mt], bh_[0], bh_[1]);
                    mma16816(acc[mt][2 * t + 1], ah_[mt], bh_[2], bh_[3]);
                    mma16816(acc[mt][2 * t + 1], ah_[mt], bl_[2], bl_[3]);
                    mma16816(acc[mt][2 * t + 1], al_[mt], bh_[2], bh_[3]);
                }
            }
        }
        __syncthreads();
        if (c + 2 < NCHUNK) load_chunk(c + 2, b);
    }

    const int lr = lane >> 2;
    const int lc = (lane & 3) * 2;
#pragma unroll
    for (int mt = 0; mt < 2; mt++) {
#pragma unroll
        for (int nt = 0; nt < 8; nt++) {
            const int n = n0 + wn * 64 + nt * 8 + lc;
            const float2 bv = *(const float2*)&J.bias[n];
            const int mA = m0 + wm * 32 + mt * 16 + lr;
            float2 o0 = make_float2(acc[mt][nt][0] + bv.x, acc[mt][nt][1] + bv.y);
            float2 o1 = make_float2(acc[mt][nt][2] + bv.x, acc[mt][nt][3] + bv.y);
            if (J.C) {
                if (mA < J.Mvalid)     *(float2*)(J.C + (size_t)mA * DIMN + n) = o0;
                if (mA + 8 < J.Mvalid) *(float2*)(J.C + (size_t)(mA + 8) * DIMN + n) = o1;
            }
            if (J.Ch) {
                uint32_t hh, ll;
                if (mA < J.Mvalid) {
                    split2(o0, hh, ll);
                    *(uint32_t*)(J.Ch + (size_t)mA * DIMN + n) = hh;
                    *(uint32_t*)(J.Cl + (size_t)mA * DIMN + n) = ll;
                }
                if (mA + 8 < J.Mvalid) {
                    split2(o1, hh, ll);
                    *(uint32_t*)(J.Ch + (size_t)(mA + 8) * DIMN + n) = hh;
                    *(uint32_t*)(J.Cl + (size_t)(mA + 8) * DIMN + n) = ll;
                }
            }
        }
    }
}

// ------------- RMS norm -> bf16 hi/lo split (fused) -------------------------
__global__ __launch_bounds__(256)
void rmsnorm_split(const float* __restrict__ X, const float* __restrict__ g,
                   __nv_bfloat16* __restrict__ H, __nv_bfloat16* __restrict__ L)
{
    const int row = blockIdx.x;
    const float* xr = X + (long)row * DIMN;
    const int t = threadIdx.x;

    float4 v0 = *(const float4*)&xr[t * 4];
    float4 v1 = *(const float4*)&xr[1024 + t * 4];
    float ss = v0.x * v0.x + v0.y * v0.y + v0.z * v0.z + v0.w * v0.w
             + v1.x * v1.x + v1.y * v1.y + v1.z * v1.z + v1.w * v1.w;

#pragma unroll
    for (int o = 16; o > 0; o >>= 1) ss += __shfl_xor_sync(0xffffffffu, ss, o);

    __shared__ float red[8];
    if ((t & 31) == 0) red[t >> 5] = ss;
    __syncthreads();
    float total = 0.f;
#pragma unroll
    for (int i = 0; i < 8; i++) total += red[i];

    const float scale = rsqrtf(total * (1.0f / DIMN) + EPS_F);

    const float4 g0 = *(const float4*)&g[t * 4];
    const float4 g1 = *(const float4*)&g[1024 + t * 4];
    v0.x *= scale * g0.x; v0.y *= scale * g0.y; v0.z *= scale * g0.z; v0.w *= scale * g0.w;
    v1.x *= scale * g1.x; v1.y *= scale * g1.y; v1.z *= scale * g1.z; v1.w *= scale * g1.w;

    uint32_t h0, l0, h1, l1;
    split2(make_float2(v0.x, v0.y), h0, l0);
    split2(make_float2(v0.z, v0.w), h1, l1);
    *(uint2*)(H + (long)row * DIMN + t * 4) = make_uint2(h0, h1);
    *(uint2*)(L + (long)row * DIMN + t * 4) = make_uint2(l0, l1);
    split2(make_float2(v1.x, v1.y), h0, l0);
    split2(make_float2(v1.z, v1.w), h1, l1);
    *(uint2*)(H + (long)row * DIMN + 1024 + t * 4) = make_uint2(h0, h1);
    *(uint2*)(L + (long)row * DIMN + 1024 + t * 4) = make_uint2(l0, l1);
}

// ---------------- flash attention (img + txt), HMMA 3-term ------------------
// q-tile 128, 8 warps (16 q-rows each, full 64-key chunk width).
// Q + online stats + O register-resident; K/V double-buffered cp.async.
// 13 static chunks: 5 img (valid 257) + 8 txt (valid lens[b]).
#define KVB 34816                    /* one K or V buffer: hi 64x272 + lo */
#define OST_OFF (4 * KVB)            /* 139264 */
#define ATT_SMEM (OST_OFF + 128 * 128 * 4)   /* 204800 */
#define NCHUNKS_ATT 13

__global__ __launch_bounds__(256, 1)
void attn_kernel(const int* __restrict__ lens)
{
    extern __shared__ char smraw[];
    const uint32_t smb = smem_u32(smraw);
    float* Ost = (float*)(smraw + OST_OFF);

    const int qt = blockIdx.x, h = blockIdx.y, b = blockIdx.z;
    const int tid = threadIdx.x;
    const int wq = tid >> 5;
    const int lane = tid & 31;
    const int q0 = qt * 128;

    const int vtxt = min(lens[b], TXT_T);
    const size_t ibase = (size_t)b * IMG_T * DIMN + h * HDIM;
    const size_t tbase = (size_t)b * TXT_T * DIMN + h * HDIM;

    // ---- stage Q hi/lo into smem (KB area), then ldmatrix into regs ----
    for (int f = tid; f < 2048; f += 256) {
        const int r = f >> 4, c = f & 15;
        const size_t off = ((size_t)(b * LQ + q0 + r)) * DIMN + h * HDIM + c * 8;
        cp16(smb + r * 272 + c * 16,         g_Qh + off);
        cp16(smb + KVB + r * 272 + c * 16,   g_Ql + off);
    }
    CP_COMMIT();
    CP_WAIT(0);
    __syncthreads();

    uint32_t qh[8][4], ql[8][4];
    {
        const uint32_t aQ = smb + (uint32_t)(wq * 16 + (lane & 15)) * 272
                          + ((lane >> 4) * 16);
#pragma unroll
        for (int s8 = 0; s8 < 8; s8++) {
            ldsm4(qh[s8], aQ + s8 * 32);
            ldsm4(ql[s8], aQ + s8 * 32 + KVB);
        }
    }
    __syncthreads();

    // ---- chunk loaders ----
    auto loadK = [&](int ci) {
        if (ci < NCHUNKS_ATT) {
            const __nv_bfloat16 *kh, *kl; int kbase, Lk; size_t base;
            if (ci < 5) { kh = g_Kih; kl = g_Kil; kbase = ci * 64; Lk = IMG_T; base = ibase; }
            else        { kh = g_Kth; kl = g_Ktl; kbase = (ci - 5) * 64; Lk = TXT_T; base = tbase; }
            const uint32_t dst = smb + (ci & 1) * KVB;
            for (int f = tid; f < 1024; f += 256) {
                const int r = f >> 4, cc = f & 15;
                const int kr = kbase + r;
                const int sz = (kr < Lk) ? 16 : 0;
                const int krc = (kr < Lk) ? kr : 0;
                const size_t off = base + (size_t)krc * DIMN + cc * 8;
                cp16z(dst + r * 272 + cc * 16,          kh + off, sz);
                cp16z(dst + 17408 + r * 272 + cc * 16,  kl + off, sz);
            }
        }
        CP_COMMIT();
    };
    auto loadV = [&](int ci) {
        if (ci < NCHUNKS_ATT) {
            const __nv_bfloat16 *vh, *vl; int kbase, Lk; size_t base;
            if (ci < 5) { vh = g_Vih; vl = g_Vil; kbase = ci * 64; Lk = IMG_T; base = ibase; }
            else        { vh = g_Vth; vl = g_Vtl; kbase = (ci - 5) * 64; Lk = TXT_T; base = tbase; }
            const uint32_t dst = smb + 2 * KVB + (ci & 1) * KVB;
            for (int f = tid; f < 1024; f += 256) {
                const int r = f >> 4, cc = f & 15;
                const int kr = kbase + r;
                const int sz = (kr < Lk) ? 16 : 0;
                const int krc = (kr < Lk) ? kr : 0;
                const size_t off = base + (size_t)krc * DIMN + cc * 8;
                cp16z(dst + r * 272 + cc * 16,          vh + off, sz);
                cp16z(dst + 17408 + r * 272 + cc * 16,  vl + off, sz);
            }
        }
        CP_COMMIT();
    };

    float o[16][4];
#pragma unroll
    for (int i = 0; i < 16; i++)
#pragma unroll
        for (int j = 0; j < 4; j++) o[i][j] = 0.f;
    float m0 = -1e30f, m1 = -1e30f, l0 = 0.f, l1 = 0.f;

    const uint32_t kbK = (uint32_t)((lane & 7) + ((lane >> 4) << 3)) * 272
                       + (((lane >> 3) & 1) * 16);
    const uint32_t vbV = (uint32_t)(lane & 15) * 272 + ((lane >> 4) * 16);
    const int qg = lane >> 2;             // row within 16
    const int qc = 2 * (lane & 3);        // col pair base

    // pipeline prologue: K0, V0, K1
    loadK(0); loadV(0); loadK(1);

    for (int ci = 0; ci < NCHUNKS_ATT; ci++) {
        const int buf = ci & 1;
        const int kbase = (ci < 5) ? ci * 64 : (ci - 5) * 64;
        const int valid = (ci < 5) ? IMG_T : vtxt;

        CP_WAIT(2);               // K(ci) ready
        __syncthreads();
        loadV(ci + 1);            // prefetch (VB[buf^1] free)

        // ---- QK scores (3-term) ----
        float s[8][4];
#pragma unroll
        for (int i = 0; i < 8; i++)
#pragma unroll
            for (int j = 0; j < 4; j++) s[i][j] = 0.f;

        const uint32_t KH = smb + buf * KVB;
#pragma unroll
        for (int s8 = 0; s8 < 8; s8++) {
#pragma unroll
            for (int t = 0; t < 4; t++) {
                uint32_t kh_[4], kl_[4];
                ldsm4(kh_, KH + kbK + t * 16 * 272 + s8 * 32);
                ldsm4(kl_, KH + kbK + t * 16 * 272 + s8 * 32 + 17408);
                mma16816(s[2 * t],     qh[s8], kh_[0], kh_[1]);
                mma16816(s[2 * t],     qh[s8], kl_[0], kl_[1]);
                mma16816(s[2 * t],     ql[s8], kh_[0], kh_[1]);
                mma16816(s[2 * t + 1], qh[s8], kh_[2], kh_[3]);
                mma16816(s[2 * t + 1], qh[s8], kl_[2], kl_[3]);
                mma16816(s[2 * t + 1], ql[s8], kh_[2], kh_[3]);
            }
        }

        // ---- online softmax (register-resident, quad reduce) ----
        float cm0 = -1e30f, cm1 = -1e30f;
#pragma unroll
        for (int nt = 0; nt < 8; nt++) {
            const int c0 = kbase + nt * 8 + qc;
#pragma unroll
            for (int j = 0; j < 2; j++) {
                const bool ok = (c0 + j) < valid;
                float t0 = ok ? s[nt][j] * ATT_SCALE : -1e30f;
                float t1 = ok ? s[nt][j + 2] * ATT_SCALE : -1e30f;
                s[nt][j] = t0; s[nt][j + 2] = t1;
                cm0 = fmaxf(cm0, t0); cm1 = fmaxf(cm1, t1);
            }
        }
        cm0 = fmaxf(cm0, __shfl_xor_sync(0xffffffffu, cm0, 1));
        cm0 = fmaxf(cm0, __shfl_xor_sync(0xffffffffu, cm0, 2));
        cm1 = fmaxf(cm1, __shfl_xor_sync(0xffffffffu, cm1, 1));
        cm1 = fmaxf(cm1, __shfl_xor_sync(0xffffffffu, cm1, 2));

        const float mn0 = fmaxf(m0, cm0), mn1 = fmaxf(m1, cm1);
        const float sc0 = __expf(m0 - mn0), sc1 = __expf(m1 - mn1);
        m0 = mn0; m1 = mn1;

        float sum0 = 0.f, sum1 = 0.f;
#pragma unroll
        for (int nt = 0; nt < 8; nt++) {
#pragma unroll
            for (int j = 0; j < 2; j++) {
                float p0 = __expf(s[nt][j] - m0);
                float p1 = __expf(s[nt][j + 2] - m1);
                s[nt][j] = p0; s[nt][j + 2] = p1;
                sum0 += p0; sum1 += p1;
            }
        }
        sum0 += __shfl_xor_sync(0xffffffffu, sum0, 1);
        sum0 += __shfl_xor_sync(0xffffffffu, sum0, 2);
        sum1 += __shfl_xor_sync(0xffffffffu, sum1, 1);
        sum1 += __shfl_xor_sync(0xffffffffu, sum1, 2);
        l0 = l0 * sc0 + sum0;
        l1 = l1 * sc1 + sum1;
#pragma unroll
        for (int nt = 0; nt < 16; nt++) {
            o[nt][0] *= sc0; o[nt][1] *= sc0;
            o[nt][2] *= sc1; o[nt][3] *= sc1;
        }

        CP_WAIT(2);               // V(ci) ready
        __syncthreads();
        loadK(ci + 2);            // prefetch (KB[buf] done)

        // ---- P @ V (3-term; P C-frags reused as A-frags) ----
        const uint32_t VH = smb + 2 * KVB + buf * KVB;
#pragma unroll
        for (int kk = 0; kk < 4; kk++) {
            uint32_t pah[4], pal[4];
            split2(make_float2(s[2 * kk][0],     s[2 * kk][1]),     pah[0], pal[0]);
            split2(make_float2(s[2 * kk][2],     s[2 * kk][3]),     pah[1], pal[1]);
            split2(make_float2(s[2 * kk + 1][0], s[2 * kk + 1][1]), pah[2], pal[2]);
            split2(make_float2(s[2 * kk + 1][2], s[2 * kk + 1][3]), pah[3], pal[3]);
            const uint32_t va = VH + vbV + kk * 16 * 272;
#pragma unroll
            for (int t = 0; t < 8; t++) {
                uint32_t vh_[4], vl_[4];
                ldsm4t(vh_, va + t * 32);
                ldsm4t(vl_, va + t * 32 + 17408);
                mma16816(o[2 * t],     pah, vh_[0], vh_[1]);
                mma16816(o[2 * t],     pah, vl_[0], vl_[1]);
                mma16816(o[2 * t],     pal, vh_[0], vh_[1]);
                mma16816(o[2 * t + 1], pah, vh_[2], vh_[3]);
                mma16816(o[2 * t + 1], pah, vl_[2], vl_[3]);
                mma16816(o[2 * t + 1], pal, vh_[2], vh_[3]);
            }
        }

        // ---- end of img phase: stash normalized output, reset stats ----
        if (ci == 4) {
            const float i0 = 1.f / l0, i1 = 1.f / l1;
            const int r0 = wq * 16 + qg;
#pragma unroll
            for (int nt = 0; nt < 16; nt++) {
                const int col = nt * 8 + qc;
                *(float2*)&Ost[r0 * 128 + col] =
                    make_float2(o[nt][0] * i0, o[nt][1] * i0);
                *(float2*)&Ost[(r0 + 8) * 128 + col] =
                    make_float2(o[nt][2] * i1, o[nt][3] * i1);
                o[nt][0] = o[nt][1] = o[nt][2] = o[nt][3] = 0.f;
            }
            m0 = m1 = -1e30f; l0 = l1 = 0.f;
        }
    }

    // ---- epilogue: out = img_stash + txt/l, write bf16 hi/lo ----
    const float i0 = 1.f / l0, i1 = 1.f / l1;
    const int r0 = wq * 16 + qg;
#pragma unroll
    for (int nt = 0; nt < 16; nt++) {
        const int col = nt * 8 + qc;
        const float2 e0 = *(const float2*)&Ost[r0 * 128 + col];
        const float2 e1 = *(const float2*)&Ost[(r0 + 8) * 128 + col];
        const int gcol = h * HDIM + col;
        const size_t a0 = (size_t)(b * LQ + q0 + r0) * DIMN + gcol;
        const size_t a1 = (size_t)(b * LQ + q0 + r0 + 8) * DIMN + gcol;
        uint32_t hh, ll;
        split2(make_float2(e0.x + o[nt][0] * i0, e0.y + o[nt][1] * i0), hh, ll);
        *(uint32_t*)&g_ah[a0] = hh;
        *(uint32_t*)&g_al[a0] = ll;
        split2(make_float2(e1.x + o[nt][2] * i1, e1.y + o[nt][3] * i1), hh, ll);
        *(uint32_t*)&g_ah[a1] = hh;
        *(uint32_t*)&g_al[a1] = ll;
    }
}

// ---------------------------- launch ---------------------------------------
extern "C" void kernel_launch(void* const* d_in, const int* in_sizes, int n_in,
                              void* d_out, int out_size)
{
    const float* x        = (const float*)d_in[0];
    const float* context  = (const float*)d_in[1];
    const int*   lens     = (const int*)  d_in[2];
    const float* w_q      = (const float*)d_in[3];
    const float* b_q      = (const float*)d_in[4];
    const float* w_k      = (const float*)d_in[5];
    const float* b_k      = (const float*)d_in[6];
    const float* w_v      = (const float*)d_in[7];
    const float* b_v      = (const float*)d_in[8];
    const float* w_k_img  = (const float*)d_in[9];
    const float* b_k_img  = (const float*)d_in[10];
    const float* w_v_img  = (const float*)d_in[11];
    const float* b_v_img  = (const float*)d_in[12];
    const float* w_o      = (const float*)d_in[13];
    const float* b_o      = (const float*)d_in[14];
    const float* g_q      = (const float*)d_in[15];
    const float* g_k      = (const float*)d_in[16];
    const float* g_k_img  = (const float*)d_in[17];
    float* out = (float*)d_out;

    float *Qb, *Ktb, *Kib;
    cudaGetSymbolAddress((void**)&Qb,  g_Q);
    cudaGetSymbolAddress((void**)&Ktb, g_Ktxt);
    cudaGetSymbolAddress((void**)&Kib, g_Kimg);

    __nv_bfloat16 *xh, *xl, *ah, *al, *cth, *ctl, *cih, *cil;
    __nv_bfloat16 *wqh, *wql, *wkh, *wkl, *wvh, *wvl, *wkih, *wkil, *wvih, *wvil, *woh, *wol;
    __nv_bfloat16 *Qhp, *Qlp, *Kthp, *Ktlp, *Vthp, *Vtlp, *Kihp, *Kilp, *Vihp, *Vilp;
    cudaGetSymbolAddress((void**)&xh,  g_xh);   cudaGetSymbolAddress((void**)&xl,  g_xl);
    cudaGetSymbolAddress((void**)&ah,  g_ah);   cudaGetSymbolAddress((void**)&al,  g_al);
    cudaGetSymbolAddress((void**)&cth, g_cth);  cudaGetSymbolAddress((void**)&ctl, g_ctl);
    cudaGetSymbolAddress((void**)&cih, g_cih);  cudaGetSymbolAddress((void**)&cil, g_cil);
    cudaGetSymbolAddress((void**)&wqh, g_wqh);  cudaGetSymbolAddress((void**)&wql, g_wql);
    cudaGetSymbolAddress((void**)&wkh, g_wkh);  cudaGetSymbolAddress((void**)&wkl, g_wkl);
    cudaGetSymbolAddress((void**)&wvh, g_wvh);  cudaGetSymbolAddress((void**)&wvl, g_wvl);
    cudaGetSymbolAddress((void**)&wkih, g_wkih); cudaGetSymbolAddress((void**)&wkil, g_wkil);
    cudaGetSymbolAddress((void**)&wvih, g_wvih); cudaGetSymbolAddress((void**)&wvil, g_wvil);
    cudaGetSymbolAddress((void**)&woh, g_woh);  cudaGetSymbolAddress((void**)&wol, g_wol);
    cudaGetSymbolAddress((void**)&Qhp, g_Qh);   cudaGetSymbolAddress((void**)&Qlp, g_Ql);
    cudaGetSymbolAddress((void**)&Kthp, g_Kth); cudaGetSymbolAddress((void**)&Ktlp, g_Ktl);
    cudaGetSymbolAddress((void**)&Vthp, g_Vth); cudaGetSymbolAddress((void**)&Vtlp, g_Vtl);
    cudaGetSymbolAddress((void**)&Kihp, g_Kih); cudaGetSymbolAddress((void**)&Kilp, g_Kil);
    cudaGetSymbolAddress((void**)&Vihp, g_Vih); cudaGetSymbolAddress((void**)&Vilp, g_Vil);

    cudaFuncSetAttribute(gemm_batch, cudaFuncAttributeMaxDynamicSharedMemorySize, GEMM_SMEM);
    cudaFuncSetAttribute(attn_kernel, cudaFuncAttributeMaxDynamicSharedMemorySize, ATT_SMEM);

#define CVT_GRID(Mrows) ((Mrows) * 2)

    // conversions (hi/lo bf16 split)
    cvt_split<<<CVT_GRID(BATCH * LQ), 256>>>(x, xh, xl, BATCH * LQ, BATCH * LQ, 0, 0);
    cvt_split<<<CVT_GRID(DIMN), 256>>>(w_q, wqh, wql, DIMN, DIMN, 0, 0);
    cvt_split<<<CVT_GRID(DIMN), 256>>>(w_k, wkh, wkl, DIMN, DIMN, 0, 0);
    cvt_split<<<CVT_GRID(DIMN), 256>>>(w_v, wvh, wvl, DIMN, DIMN, 0, 0);
    cvt_split<<<CVT_GRID(DIMN), 256>>>(w_k_img, wkih, wkil, DIMN, DIMN, 0, 0);
    cvt_split<<<CVT_GRID(DIMN), 256>>>(w_v_img, wvih, wvil, DIMN, DIMN, 0, 0);
    cvt_split<<<CVT_GRID(DIMN), 256>>>(w_o, woh, wol, DIMN, DIMN, 0, 0);
    cvt_split<<<CVT_GRID(BATCH * TXT_T), 256>>>(context, cth, ctl,
                                                BATCH * TXT_T, TXT_T, LCTX, IMG_T);
    cvt_split<<<CVT_GRID(MPAD_IMG), 256>>>(context, cih, cil,
                                           BATCH * IMG_T, IMG_T, LCTX, 0);

    // batched projection GEMMs: Q, K_txt, V_txt, K_img, V_img (one launch)
    GParams P;
    P.j[0] = { xh,  xl,  wqh,  wql,  b_q,     Qb,  nullptr, nullptr, BATCH * LQ,    0    };
    P.j[1] = { cth, ctl, wkh,  wkl,  b_k,     Ktb, nullptr, nullptr, BATCH * TXT_T, 1024 };
    P.j[2] = { cth, ctl, wvh,  wvl,  b_v,     nullptr, Vthp, Vtlp,   BATCH * TXT_T, 1152 };
    P.j[3] = { cih, cil, wkih, wkil, b_k_img, Kib, nullptr, nullptr, BATCH * IMG_T, 1280 };
    P.j[4] = { cih, cil, wvih, wvil, b_v_img, nullptr, Vihp, Vilp,   BATCH * IMG_T, 1360 };
    gemm_batch<<<1440, 256, GEMM_SMEM>>>(P);

    // rmsnorm + split for Q / K_txt / K_img
    rmsnorm_split<<<BATCH * LQ, 256>>>(Qb, g_q, Qhp, Qlp);
    rmsnorm_split<<<BATCH * TXT_T, 256>>>(Ktb, g_k, Kthp, Ktlp);
    rmsnorm_split<<<BATCH * IMG_T, 256>>>(Kib, g_k_img, Kihp, Kilp);

    // flash attention (img + txt) -> g_ah/g_al (bf16 hi/lo)
    attn_kernel<<<dim3(LQ / 128, NHEADS, BATCH), 256, ATT_SMEM>>>(lens);

    // out = attn @ w_o^T + b_o (single-job batched kernel)
    GParams PO;
    PO.j[0] = { ah, al, woh, wol, b_o, out, nullptr, nullptr, BATCH * LQ, 0 };
    PO.j[1] = PO.j[2] = PO.j[3] = PO.j[4] = PO.j[0];
    PO.j[1].cta0 = PO.j[2].cta0 = PO.j[3].cta0 = PO.j[4].cta0 = 1 << 30;
    gemm_batch<<<1024, 256, GEMM_SMEM>>>(PO);
}

// round 8
// speedup vs baseline: 3.8538x; 1.0161x over previous
#include <cuda_runtime.h>
#include <cuda_bf16.h>
#include <math.h>
#include <stdint.h>

#define DIMN 2048
#define NHEADS 16
#define HDIM 128
#define BATCH 2
#define LQ 4096
#define LCTX 769
#define IMG_T 257
#define TXT_T 512
#define EPS_F 1e-6f
#define ATT_SCALE 0.08838834764831845f  /* 1/sqrt(128) */

// ---------------- scratch (device globals; no allocs allowed) --------------
__device__ float g_Q   [BATCH * LQ    * DIMN];
__device__ float g_Ktxt[BATCH * TXT_T * DIMN];
__device__ float g_Kimg[BATCH * IMG_T * DIMN];

// bf16 hi/lo split buffers
#define MPAD_IMG 640
__device__ __nv_bfloat16 g_xh [BATCH * LQ * DIMN];
__device__ __nv_bfloat16 g_xl [BATCH * LQ * DIMN];
__device__ __nv_bfloat16 g_ah [BATCH * LQ * DIMN];
__device__ __nv_bfloat16 g_al [BATCH * LQ * DIMN];
__device__ __nv_bfloat16 g_cth[BATCH * TXT_T * DIMN];
__device__ __nv_bfloat16 g_ctl[BATCH * TXT_T * DIMN];
__device__ __nv_bfloat16 g_cih[MPAD_IMG * DIMN];
__device__ __nv_bfloat16 g_cil[MPAD_IMG * DIMN];
__device__ __nv_bfloat16 g_wqh [DIMN * DIMN], g_wql [DIMN * DIMN];
__device__ __nv_bfloat16 g_wkh [DIMN * DIMN], g_wkl [DIMN * DIMN];
__device__ __nv_bfloat16 g_wvh [DIMN * DIMN], g_wvl [DIMN * DIMN];
__device__ __nv_bfloat16 g_wkih[DIMN * DIMN], g_wkil[DIMN * DIMN];
__device__ __nv_bfloat16 g_wvih[DIMN * DIMN], g_wvil[DIMN * DIMN];
__device__ __nv_bfloat16 g_woh [DIMN * DIMN], g_wol [DIMN * DIMN];

// attention-side hi/lo operands
__device__ __nv_bfloat16 g_Qh [BATCH * LQ * DIMN],    g_Ql [BATCH * LQ * DIMN];
__device__ __nv_bfloat16 g_Kth[BATCH * TXT_T * DIMN], g_Ktl[BATCH * TXT_T * DIMN];
__device__ __nv_bfloat16 g_Vth[BATCH * TXT_T * DIMN], g_Vtl[BATCH * TXT_T * DIMN];
__device__ __nv_bfloat16 g_Kih[BATCH * IMG_T * DIMN], g_Kil[BATCH * IMG_T * DIMN];
__device__ __nv_bfloat16 g_Vih[MPAD_IMG * DIMN],      g_Vil[MPAD_IMG * DIMN];

// ---------------------------- helpers ---------------------------------------
__device__ __forceinline__ uint32_t smem_u32(const void* p) {
    uint32_t a;
    asm("{ .reg .u64 t; cvta.to.shared.u64 t, %1; cvt.u32.u64 %0, t; }"
        : "=r"(a) : "l"(p));
    return a;
}

__device__ __forceinline__ void mma16816(float* d, const uint32_t* a,
                                         const uint32_t b0, const uint32_t b1) {
    asm volatile(
        "mma.sync.aligned.m16n8k16.row.col.f32.bf16.bf16.f32 "
        "{%0,%1,%2,%3}, {%4,%5,%6,%7}, {%8,%9}, {%0,%1,%2,%3};"
        : "+f"(d[0]), "+f"(d[1]), "+f"(d[2]), "+f"(d[3])
        : "r"(a[0]), "r"(a[1]), "r"(a[2]), "r"(a[3]), "r"(b0), "r"(b1));
}

__device__ __forceinline__ void ldsm4(uint32_t* r, uint32_t a) {
    asm volatile("ldmatrix.sync.aligned.m8n8.x4.shared.b16 {%0,%1,%2,%3}, [%4];"
                 : "=r"(r[0]), "=r"(r[1]), "=r"(r[2]), "=r"(r[3]) : "r"(a));
}
__device__ __forceinline__ void ldsm4t(uint32_t* r, uint32_t a) {
    asm volatile("ldmatrix.sync.aligned.m8n8.x4.trans.shared.b16 {%0,%1,%2,%3}, [%4];"
                 : "=r"(r[0]), "=r"(r[1]), "=r"(r[2]), "=r"(r[3]) : "r"(a));
}
__device__ __forceinline__ void cp16(uint32_t d, const void* s) {
    asm volatile("cp.async.cg.shared.global [%0], [%1], 16;"
                 :: "r"(d), "l"(s) : "memory");
}
__device__ __forceinline__ void cp16z(uint32_t d, const void* s, int sz) {
    asm volatile("cp.async.cg.shared.global [%0], [%1], 16, %2;"
                 :: "r"(d), "l"(s), "r"(sz) : "memory");
}
#define CP_COMMIT() asm volatile("cp.async.commit_group;" ::: "memory")
#define CP_WAIT(n)  asm volatile("cp.async.wait_group %0;" :: "n"(n) : "memory")

// f32x2 -> bf16x2 hi + lo residual
__device__ __forceinline__ void split2(float2 f, uint32_t& h, uint32_t& l) {
    __nv_bfloat162 hb = __float22bfloat162_rn(f);
    float2 hf = __bfloat1622float2(hb);
    __nv_bfloat162 lb = __float22bfloat162_rn(make_float2(f.x - hf.x, f.y - hf.y));
    h = *(uint32_t*)&hb;
    l = *(uint32_t*)&lb;
}

// -------------- batched fp32 -> bf16 hi/lo split (9 jobs, one launch) ------
struct CJob {
    const float* src;
    __nv_bfloat16 *hi, *lo;
    int Mvalid, rows_pb, bstride, roff, blk0;
};
struct CParams { CJob j[9]; };

__global__ __launch_bounds__(256)
void cvt_batch(CParams P)
{
    const int bid = blockIdx.x;
    int ji = 0;
#pragma unroll
    for (int k = 1; k < 9; k++) if (bid >= P.j[k].blk0) ji = k;
    const CJob& J = P.j[ji];

    const long e = (long)(bid - J.blk0) * 1024 + threadIdx.x * 4;
    const int m = (int)(e >> 11);
    const int col = (int)(e & 2047);

    float4 v = make_float4(0.f, 0.f, 0.f, 0.f);
    if (m < J.Mvalid) {
        const int bb = m / J.rows_pb;
        const long srow = (long)bb * J.bstride + J.roff + (m - bb * J.rows_pb);
        v = *(const float4*)(J.src + srow * DIMN + col);
    }
    uint32_t h0, l0, h1, l1;
    split2(make_float2(v.x, v.y), h0, l0);
    split2(make_float2(v.z, v.w), h1, l1);
    *(uint2*)(J.hi + e) = make_uint2(h0, h1);
    *(uint2*)(J.lo + e) = make_uint2(l0, l1);
}

// ------------- batched HMMA GEMM: C = (Ah+Al)(Bh+Bl)^T + bias (3 terms) ----
#define GT_KC 32
#define NCHUNK (DIMN / GT_KC)        /* 64 */
#define TILE_B   10240               /* 128 x 80 bytes */
#define BUF_B    (4 * TILE_B)
#define GEMM_SMEM (2 * BUF_B)

struct GJob {
    const __nv_bfloat16 *Ah, *Al, *Bh, *Bl;
    const float *bias;
    float *C;                      // fp32 out (may be null)
    __nv_bfloat16 *Ch, *Cl;        // hi/lo out (may be null)
    int Mvalid;
    int cta0;
};
struct GParams { GJob j[5]; };

__global__ __launch_bounds__(256, 2)
void gemm_batch(GParams P)
{
    extern __shared__ __nv_bfloat16 sm[];

    const int bid = blockIdx.x;
    int ji = 0;
#pragma unroll
    for (int k = 1; k < 5; k++) if (bid >= P.j[k].cta0) ji = k;
    const GJob& J = P.j[ji];
    const int local = bid - J.cta0;
    const int n0 = (local & 15) * 128;
    const int m0 = (local >> 4) * 128;

    const int tid = threadIdx.x;
    const int wid = tid >> 5;
    const int lane = tid & 31;
    const int wm = wid & 3;
    const int wn = wid >> 2;

    const __nv_bfloat16* srcs[4] = {
        J.Ah + (size_t)m0 * DIMN, J.Al + (size_t)m0 * DIMN,
        J.Bh + (size_t)n0 * DIMN, J.Bl + (size_t)n0 * DIMN };

    const uint32_t smb = smem_u32(sm);

    auto load_chunk = [&](int c, int b) {
        const int k0 = c * GT_KC;
#pragma unroll
        for (int j = 0; j < 8; j++) {
            const int f = j * 256 + tid;
            const int tile = f >> 9;
            const int w = f & 511;
            const int r = w >> 2;
            const int cc = w & 3;
            const __nv_bfloat16* sp = srcs[tile] + (size_t)r * DIMN + k0 + cc * 8;
            cp16(smb + b * BUF_B + tile * TILE_B + r * 80 + cc * 16, sp);
        }
        CP_COMMIT();
    };

    float acc[2][8][4];
#pragma unroll
    for (int i = 0; i < 2; i++)
#pragma unroll
        for (int j = 0; j < 8; j++)
#pragma unroll
            for (int q = 0; q < 4; q++) acc[i][j][q] = 0.f;

    const uint32_t aOff = (uint32_t)(wm * 32 + (lane & 15)) * 80 + ((lane >> 4) * 16);
    const uint32_t bOff = (uint32_t)(wn * 64 + (lane & 7) + ((lane >> 4) << 3)) * 80
                        + (((lane >> 3) & 1) * 16) + 2 * TILE_B;

    load_chunk(0, 0);
    load_chunk(1, 1);

    for (int c = 0; c < NCHUNK; c++) {
        const int b = c & 1;
        if (c == NCHUNK - 1) CP_WAIT(0);
        else                 CP_WAIT(1);
        __syncthreads();

        const uint32_t buf = smb + b * BUF_B;

#pragma unroll
        for (int s = 0; s < 2; s++) {
            uint32_t ah_[2][4], al_[2][4];
#pragma unroll
            for (int mt = 0; mt < 2; mt++) {
                ldsm4(ah_[mt], buf + aOff + mt * 16 * 80 + s * 32);
                ldsm4(al_[mt], buf + aOff + mt * 16 * 80 + s * 32 + TILE_B);
            }
#pragma unroll
            for (int t = 0; t < 4; t++) {
                uint32_t bh_[4], bl_[4];
                ldsm4(bh_, buf + bOff + t * 16 * 80 + s * 32);
                ldsm4(bl_, buf + bOff + t * 16 * 80 + s * 32 + TILE_B);
#pragma unroll
                for (int mt = 0; mt < 2; mt++) {
                    mma16816(acc[mt][2 * t],     ah_[mt], bh_[0], bh_[1]);
                    mma16816(acc[mt][2 * t],     ah_[mt], bl_[0], bl_[1]);
                    mma16816(acc[mt][2 * t],     al_[mt], bh_[0], bh_[1]);
                    mma16816(acc[mt][2 * t + 1], ah_[mt], bh_[2], bh_[3]);
                    mma16816(acc[mt][2 * t + 1], ah_[mt], bl_[2], bl_[3]);
                    mma16816(acc[mt][2 * t + 1], al_[mt], bh_[2], bh_[3]);
                }
            }
        }
        __syncthreads();
        if (c + 2 < NCHUNK) load_chunk(c + 2, b);
    }

    const int lr = lane >> 2;
    const int lc = (lane & 3) * 2;
#pragma unroll
    for (int mt = 0; mt < 2; mt++) {
#pragma unroll
        for (int nt = 0; nt < 8; nt++) {
            const int n = n0 + wn * 64 + nt * 8 + lc;
            const float2 bv = *(const float2*)&J.bias[n];
            const int mA = m0 + wm * 32 + mt * 16 + lr;
            float2 o0 = make_float2(acc[mt][nt][0] + bv.x, acc[mt][nt][1] + bv.y);
            float2 o1 = make_float2(acc[mt][nt][2] + bv.x, acc[mt][nt][3] + bv.y);
            if (J.C) {
                if (mA < J.Mvalid)     *(float2*)(J.C + (size_t)mA * DIMN + n) = o0;
                if (mA + 8 < J.Mvalid) *(float2*)(J.C + (size_t)(mA + 8) * DIMN + n) = o1;
            }
            if (J.Ch) {
                uint32_t hh, ll;
                if (mA < J.Mvalid) {
                    split2(o0, hh, ll);
                    *(uint32_t*)(J.Ch + (size_t)mA * DIMN + n) = hh;
                    *(uint32_t*)(J.Cl + (size_t)mA * DIMN + n) = ll;
                }
                if (mA + 8 < J.Mvalid) {
                    split2(o1, hh, ll);
                    *(uint32_t*)(J.Ch + (size_t)(mA + 8) * DIMN + n) = hh;
                    *(uint32_t*)(J.Cl + (size_t)(mA + 8) * DIMN + n) = ll;
                }
            }
        }
    }
}

// ------------- batched RMS norm -> bf16 hi/lo split (3 jobs) ---------------
struct RJob {
    const float* X;
    const float* g;
    __nv_bfloat16 *H, *L;
    int row0;
};
struct RParams { RJob j[3]; };

__global__ __launch_bounds__(256)
void rmsnorm_batch(RParams P)
{
    const int bid = blockIdx.x;
    int ji = 0;
#pragma unroll
    for (int k = 1; k < 3; k++) if (bid >= P.j[k].row0) ji = k;
    const RJob& J = P.j[ji];
    const int row = bid - J.row0;

    const float* xr = J.X + (long)row * DIMN;
    const int t = threadIdx.x;

    float4 v0 = *(const float4*)&xr[t * 4];
    float4 v1 = *(const float4*)&xr[1024 + t * 4];
    float ss = v0.x * v0.x + v0.y * v0.y + v0.z * v0.z + v0.w * v0.w
             + v1.x * v1.x + v1.y * v1.y + v1.z * v1.z + v1.w * v1.w;

#pragma unroll
    for (int o = 16; o > 0; o >>= 1) ss += __shfl_xor_sync(0xffffffffu, ss, o);

    __shared__ float red[8];
    if ((t & 31) == 0) red[t >> 5] = ss;
    __syncthreads();
    float total = 0.f;
#pragma unroll
    for (int i = 0; i < 8; i++) total += red[i];

    const float scale = rsqrtf(total * (1.0f / DIMN) + EPS_F);

    const float4 g0 = *(const float4*)&J.g[t * 4];
    const float4 g1 = *(const float4*)&J.g[1024 + t * 4];
    v0.x *= scale * g0.x; v0.y *= scale * g0.y; v0.z *= scale * g0.z; v0.w *= scale * g0.w;
    v1.x *= scale * g1.x; v1.y *= scale * g1.y; v1.z *= scale * g1.z; v1.w *= scale * g1.w;

    uint32_t h0, l0, h1, l1;
    split2(make_float2(v0.x, v0.y), h0, l0);
    split2(make_float2(v0.z, v0.w), h1, l1);
    *(uint2*)(J.H + (long)row * DIMN + t * 4) = make_uint2(h0, h1);
    *(uint2*)(J.L + (long)row * DIMN + t * 4) = make_uint2(l0, l1);
    split2(make_float2(v1.x, v1.y), h0, l0);
    split2(make_float2(v1.z, v1.w), h1, l1);
    *(uint2*)(J.H + (long)row * DIMN + 1024 + t * 4) = make_uint2(h0, h1);
    *(uint2*)(J.L + (long)row * DIMN + 1024 + t * 4) = make_uint2(l0, l1);
}

// ---------------- flash attention (img + txt), HMMA 3-term ------------------
// q-tile 128, 8 warps (16 q-rows each, full 64-key chunk width).
// Q + online stats + O register-resident; K/V double-buffered cp.async.
// chunks: 5 img (valid 257) + ceil(lens[b]/64) txt chunks (lens-trimmed).
#define KVB 34816                    /* one K or V buffer: hi 64x272 + lo */
#define OST_OFF (4 * KVB)            /* 139264 */
#define ATT_SMEM (OST_OFF + 128 * 128 * 4)   /* 204800 */

__global__ __launch_bounds__(256, 1)
void attn_kernel(const int* __restrict__ lens)
{
    extern __shared__ char smraw[];
    const uint32_t smb = smem_u32(smraw);
    float* Ost = (float*)(smraw + OST_OFF);

    const int qt = blockIdx.x, h = blockIdx.y, b = blockIdx.z;
    const int tid = threadIdx.x;
    const int wq = tid >> 5;
    const int lane = tid & 31;
    const int q0 = qt * 128;

    const int vtxt = min(lens[b], TXT_T);
    const int nch = 5 + ((vtxt + 63) >> 6);       // 9..13 chunks
    const size_t ibase = (size_t)b * IMG_T * DIMN + h * HDIM;
    const size_t tbase = (size_t)b * TXT_T * DIMN + h * HDIM;

    // ---- stage Q hi/lo into smem (KB area), then ldmatrix into regs ----
    for (int f = tid; f < 2048; f += 256) {
        const int r = f >> 4, c = f & 15;
        const size_t off = ((size_t)(b * LQ + q0 + r)) * DIMN + h * HDIM + c * 8;
        cp16(smb + r * 272 + c * 16,         g_Qh + off);
        cp16(smb + KVB + r * 272 + c * 16,   g_Ql + off);
    }
    CP_COMMIT();
    CP_WAIT(0);
    __syncthreads();

    uint32_t qh[8][4], ql[8][4];
    {
        const uint32_t aQ = smb + (uint32_t)(wq * 16 + (lane & 15)) * 272
                          + ((lane >> 4) * 16);
#pragma unroll
        for (int s8 = 0; s8 < 8; s8++) {
            ldsm4(qh[s8], aQ + s8 * 32);
            ldsm4(ql[s8], aQ + s8 * 32 + KVB);
        }
    }
    __syncthreads();

    // ---- chunk loaders ----
    auto loadK = [&](int ci) {
        if (ci < nch) {
            const __nv_bfloat16 *kh, *kl; int kbase, Lk; size_t base;
            if (ci < 5) { kh = g_Kih; kl = g_Kil; kbase = ci * 64; Lk = IMG_T; base = ibase; }
            else        { kh = g_Kth; kl = g_Ktl; kbase = (ci - 5) * 64; Lk = TXT_T; base = tbase; }
            const uint32_t dst = smb + (ci & 1) * KVB;
            for (int f = tid; f < 1024; f += 256) {
                const int r = f >> 4, cc = f & 15;
                const int kr = kbase + r;
                const int sz = (kr < Lk) ? 16 : 0;
                const int krc = (kr < Lk) ? kr : 0;
                const size_t off = base + (size_t)krc * DIMN + cc * 8;
                cp16z(dst + r * 272 + cc * 16,          kh + off, sz);
                cp16z(dst + 17408 + r * 272 + cc * 16,  kl + off, sz);
            }
        }
        CP_COMMIT();
    };
    auto loadV = [&](int ci) {
        if (ci < nch) {
            const __nv_bfloat16 *vh, *vl; int kbase, Lk; size_t base;
            if (ci < 5) { vh = g_Vih; vl = g_Vil; kbase = ci * 64; Lk = IMG_T; base = ibase; }
            else        { vh = g_Vth; vl = g_Vtl; kbase = (ci - 5) * 64; Lk = TXT_T; base = tbase; }
            const uint32_t dst = smb + 2 * KVB + (ci & 1) * KVB;
            for (int f = tid; f < 1024; f += 256) {
                const int r = f >> 4, cc = f & 15;
                const int kr = kbase + r;
                const int sz = (kr < Lk) ? 16 : 0;
                const int krc = (kr < Lk) ? kr : 0;
                const size_t off = base + (size_t)krc * DIMN + cc * 8;
                cp16z(dst + r * 272 + cc * 16,          vh + off, sz);
                cp16z(dst + 17408 + r * 272 + cc * 16,  vl + off, sz);
            }
        }
        CP_COMMIT();
    };

    float o[16][4];
#pragma unroll
    for (int i = 0; i < 16; i++)
#pragma unroll
        for (int j = 0; j < 4; j++) o[i][j] = 0.f;
    float m0 = -1e30f, m1 = -1e30f, l0 = 0.f, l1 = 0.f;

    const uint32_t kbK = (uint32_t)((lane & 7) + ((lane >> 4) << 3)) * 272
                       + (((lane >> 3) & 1) * 16);
    const uint32_t vbV = (uint32_t)(lane & 15) * 272 + ((lane >> 4) * 16);
    const int qg = lane >> 2;             // row within 16
    const int qc = 2 * (lane & 3);        // col pair base

    // pipeline prologue: K0, V0, K1
    loadK(0); loadV(0); loadK(1);

    for (int ci = 0; ci < nch; ci++) {
        const int buf = ci & 1;
        const int kbase = (ci < 5) ? ci * 64 : (ci - 5) * 64;
        const int valid = (ci < 5) ? IMG_T : vtxt;

        CP_WAIT(2);               // K(ci) ready
        __syncthreads();
        loadV(ci + 1);            // prefetch (VB[buf^1] free)

        // ---- QK scores (3-term) ----
        float s[8][4];
#pragma unroll
        for (int i = 0; i < 8; i++)
#pragma unroll
            for (int j = 0; j < 4; j++) s[i][j] = 0.f;

        const uint32_t KH = smb + buf * KVB;
#pragma unroll
        for (int s8 = 0; s8 < 8; s8++) {
#pragma unroll
            for (int t = 0; t < 4; t++) {
                uint32_t kh_[4], kl_[4];
                ldsm4(kh_, KH + kbK + t * 16 * 272 + s8 * 32);
                ldsm4(kl_, KH + kbK + t * 16 * 272 + s8 * 32 + 17408);
                mma16816(s[2 * t],     qh[s8], kh_[0], kh_[1]);
                mma16816(s[2 * t],     qh[s8], kl_[0], kl_[1]);
                mma16816(s[2 * t],     ql[s8], kh_[0], kh_[1]);
                mma16816(s[2 * t + 1], qh[s8], kh_[2], kh_[3]);
                mma16816(s[2 * t + 1], qh[s8], kl_[2], kl_[3]);
                mma16816(s[2 * t + 1], ql[s8], kh_[2], kh_[3]);
            }
        }

        // ---- online softmax (register-resident, quad reduce) ----
        float cm0 = -1e30f, cm1 = -1e30f;
#pragma unroll
        for (int nt = 0; nt < 8; nt++) {
            const int c0 = kbase + nt * 8 + qc;
#pragma unroll
            for (int j = 0; j < 2; j++) {
                const bool ok = (c0 + j) < valid;
                float t0 = ok ? s[nt][j] * ATT_SCALE : -1e30f;
                float t1 = ok ? s[nt][j + 2] * ATT_SCALE : -1e30f;
                s[nt][j] = t0; s[nt][j + 2] = t1;
                cm0 = fmaxf(cm0, t0); cm1 = fmaxf(cm1, t1);
            }
        }
        cm0 = fmaxf(cm0, __shfl_xor_sync(0xffffffffu, cm0, 1));
        cm0 = fmaxf(cm0, __shfl_xor_sync(0xffffffffu, cm0, 2));
        cm1 = fmaxf(cm1, __shfl_xor_sync(0xffffffffu, cm1, 1));
        cm1 = fmaxf(cm1, __shfl_xor_sync(0xffffffffu, cm1, 2));

        const float mn0 = fmaxf(m0, cm0), mn1 = fmaxf(m1, cm1);
        const float sc0 = __expf(m0 - mn0), sc1 = __expf(m1 - mn1);
        m0 = mn0; m1 = mn1;

        float sum0 = 0.f, sum1 = 0.f;
#pragma unroll
        for (int nt = 0; nt < 8; nt++) {
#pragma unroll
            for (int j = 0; j < 2; j++) {
                float p0 = __expf(s[nt][j] - m0);
                float p1 = __expf(s[nt][j + 2] - m1);
                s[nt][j] = p0; s[nt][j + 2] = p1;
                sum0 += p0; sum1 += p1;
            }
        }
        sum0 += __shfl_xor_sync(0xffffffffu, sum0, 1);
        sum0 += __shfl_xor_sync(0xffffffffu, sum0, 2);
        sum1 += __shfl_xor_sync(0xffffffffu, sum1, 1);
        sum1 += __shfl_xor_sync(0xffffffffu, sum1, 2);
        l0 = l0 * sc0 + sum0;
        l1 = l1 * sc1 + sum1;
#pragma unroll
        for (int nt = 0; nt < 16; nt++) {
            o[nt][0] *= sc0; o[nt][1] *= sc0;
            o[nt][2] *= sc1; o[nt][3] *= sc1;
        }

        CP_WAIT(2);               // V(ci) ready
        __syncthreads();
        loadK(ci + 2);            // prefetch (KB[buf] done)

        // ---- P @ V (3-term; P C-frags reused as A-frags) ----
        const uint32_t VH = smb + 2 * KVB + buf * KVB;
#pragma unroll
        for (int kk = 0; kk < 4; kk++) {
            uint32_t pah[4], pal[4];
            split2(make_float2(s[2 * kk][0],     s[2 * kk][1]),     pah[0], pal[0]);
            split2(make_float2(s[2 * kk][2],     s[2 * kk][3]),     pah[1], pal[1]);
            split2(make_float2(s[2 * kk + 1][0], s[2 * kk + 1][1]), pah[2], pal[2]);
            split2(make_float2(s[2 * kk + 1][2], s[2 * kk + 1][3]), pah[3], pal[3]);
            const uint32_t va = VH + vbV + kk * 16 * 272;
#pragma unroll
            for (int t = 0; t < 8; t++) {
                uint32_t vh_[4], vl_[4];
                ldsm4t(vh_, va + t * 32);
                ldsm4t(vl_, va + t * 32 + 17408);
                mma16816(o[2 * t],     pah, vh_[0], vh_[1]);
                mma16816(o[2 * t],     pah, vl_[0], vl_[1]);
                mma16816(o[2 * t],     pal, vh_[0], vh_[1]);
                mma16816(o[2 * t + 1], pah, vh_[2], vh_[3]);
                mma16816(o[2 * t + 1], pah, vl_[2], vl_[3]);
                mma16816(o[2 * t + 1], pal, vh_[2], vh_[3]);
            }
        }

        // ---- end of img phase: stash normalized output, reset stats ----
        if (ci == 4) {
            const float i0 = 1.f / l0, i1 = 1.f / l1;
            const int r0 = wq * 16 + qg;
#pragma unroll
            for (int nt = 0; nt < 16; nt++) {
                const int col = nt * 8 + qc;
                *(float2*)&Ost[r0 * 128 + col] =
                    make_float2(o[nt][0] * i0, o[nt][1] * i0);
                *(float2*)&Ost[(r0 + 8) * 128 + col] =
                    make_float2(o[nt][2] * i1, o[nt][3] * i1);
                o[nt][0] = o[nt][1] = o[nt][2] = o[nt][3] = 0.f;
            }
            m0 = m1 = -1e30f; l0 = l1 = 0.f;
        }
    }

    // ---- epilogue: out = img_stash + txt/l, write bf16 hi/lo ----
    const float i0 = 1.f / l0, i1 = 1.f / l1;
    const int r0 = wq * 16 + qg;
#pragma unroll
    for (int nt = 0; nt < 16; nt++) {
        const int col = nt * 8 + qc;
        const float2 e0 = *(const float2*)&Ost[r0 * 128 + col];
        const float2 e1 = *(const float2*)&Ost[(r0 + 8) * 128 + col];
        const int gcol = h * HDIM + col;
        const size_t a0 = (size_t)(b * LQ + q0 + r0) * DIMN + gcol;
        const size_t a1 = (size_t)(b * LQ + q0 + r0 + 8) * DIMN + gcol;
        uint32_t hh, ll;
        split2(make_float2(e0.x + o[nt][0] * i0, e0.y + o[nt][1] * i0), hh, ll);
        *(uint32_t*)&g_ah[a0] = hh;
        *(uint32_t*)&g_al[a0] = ll;
        split2(make_float2(e1.x + o[nt][2] * i1, e1.y + o[nt][3] * i1), hh, ll);
        *(uint32_t*)&g_ah[a1] = hh;
        *(uint32_t*)&g_al[a1] = ll;
    }
}

// ---------------------------- launch ---------------------------------------
extern "C" void kernel_launch(void* const* d_in, const int* in_sizes, int n_in,
                              void* d_out, int out_size)
{
    const float* x        = (const float*)d_in[0];
    const float* context  = (const float*)d_in[1];
    const int*   lens     = (const int*)  d_in[2];
    const float* w_q      = (const float*)d_in[3];
    const float* b_q      = (const float*)d_in[4];
    const float* w_k      = (const float*)d_in[5];
    const float* b_k      = (const float*)d_in[6];
    const float* w_v      = (const float*)d_in[7];
    const float* b_v      = (const float*)d_in[8];
    const float* w_k_img  = (const float*)d_in[9];
    const float* b_k_img  = (const float*)d_in[10];
    const float* w_v_img  = (const float*)d_in[11];
    const float* b_v_img  = (const float*)d_in[12];
    const float* w_o      = (const float*)d_in[13];
    const float* b_o      = (const float*)d_in[14];
    const float* g_q      = (const float*)d_in[15];
    const float* g_k      = (const float*)d_in[16];
    const float* g_k_img  = (const float*)d_in[17];
    float* out = (float*)d_out;

    float *Qb, *Ktb, *Kib;
    cudaGetSymbolAddress((void**)&Qb,  g_Q);
    cudaGetSymbolAddress((void**)&Ktb, g_Ktxt);
    cudaGetSymbolAddress((void**)&Kib, g_Kimg);

    __nv_bfloat16 *xh, *xl, *ah, *al, *cth, *ctl, *cih, *cil;
    __nv_bfloat16 *wqh, *wql, *wkh, *wkl, *wvh, *wvl, *wkih, *wkil, *wvih, *wvil, *woh, *wol;
    __nv_bfloat16 *Qhp, *Qlp, *Kthp, *Ktlp, *Vthp, *Vtlp, *Kihp, *Kilp, *Vihp, *Vilp;
    cudaGetSymbolAddress((void**)&xh,  g_xh);   cudaGetSymbolAddress((void**)&xl,  g_xl);
    cudaGetSymbolAddress((void**)&ah,  g_ah);   cudaGetSymbolAddress((void**)&al,  g_al);
    cudaGetSymbolAddress((void**)&cth, g_cth);  cudaGetSymbolAddress((void**)&ctl, g_ctl);
    cudaGetSymbolAddress((void**)&cih, g_cih);  cudaGetSymbolAddress((void**)&cil, g_cil);
    cudaGetSymbolAddress((void**)&wqh, g_wqh);  cudaGetSymbolAddress((void**)&wql, g_wql);
    cudaGetSymbolAddress((void**)&wkh, g_wkh);  cudaGetSymbolAddress((void**)&wkl, g_wkl);
    cudaGetSymbolAddress((void**)&wvh, g_wvh);  cudaGetSymbolAddress((void**)&wvl, g_wvl);
    cudaGetSymbolAddress((void**)&wkih, g_wkih); cudaGetSymbolAddress((void**)&wkil, g_wkil);
    cudaGetSymbolAddress((void**)&wvih, g_wvih); cudaGetSymbolAddress((void**)&wvil, g_wvil);
    cudaGetSymbolAddress((void**)&woh, g_woh);  cudaGetSymbolAddress((void**)&wol, g_wol);
    cudaGetSymbolAddress((void**)&Qhp, g_Qh);   cudaGetSymbolAddress((void**)&Qlp, g_Ql);
    cudaGetSymbolAddress((void**)&Kthp, g_Kth); cudaGetSymbolAddress((void**)&Ktlp, g_Ktl);
    cudaGetSymbolAddress((void**)&Vthp, g_Vth); cudaGetSymbolAddress((void**)&Vtlp, g_Vtl);
    cudaGetSymbolAddress((void**)&Kihp, g_Kih); cudaGetSymbolAddress((void**)&Kilp, g_Kil);
    cudaGetSymbolAddress((void**)&Vihp, g_Vih); cudaGetSymbolAddress((void**)&Vilp, g_Vil);

    cudaFuncSetAttribute(gemm_batch, cudaFuncAttributeMaxDynamicSharedMemorySize, GEMM_SMEM);
    cudaFuncSetAttribute(attn_kernel, cudaFuncAttributeMaxDynamicSharedMemorySize, ATT_SMEM);

    // one batched conversion launch (9 jobs)
    // blocks per job = rows * 2  (1024 elems per block)
    CParams CP;
    int blk = 0;
    auto addc = [&](const float* s, __nv_bfloat16* H, __nv_bfloat16* L,
                    int Mvalid, int Mpad, int rows_pb, int bstride, int roff, int idx) {
        CP.j[idx] = { s, H, L, Mvalid, rows_pb, bstride, roff, blk };
        blk += Mpad * 2;
    };
    addc(x,       xh,   xl,   BATCH * LQ,    BATCH * LQ,    BATCH * LQ, 0, 0, 0);
    addc(w_q,     wqh,  wql,  DIMN, DIMN, DIMN, 0, 0, 1);
    addc(w_k,     wkh,  wkl,  DIMN, DIMN, DIMN, 0, 0, 2);
    addc(w_v,     wvh,  wvl,  DIMN, DIMN, DIMN, 0, 0, 3);
    addc(w_k_img, wkih, wkil, DIMN, DIMN, DIMN, 0, 0, 4);
    addc(w_v_img, wvih, wvil, DIMN, DIMN, DIMN, 0, 0, 5);
    addc(w_o,     woh,  wol,  DIMN, DIMN, DIMN, 0, 0, 6);
    addc(context, cth,  ctl,  BATCH * TXT_T, BATCH * TXT_T, TXT_T, LCTX, IMG_T, 7);
    addc(context, cih,  cil,  BATCH * IMG_T, MPAD_IMG,      IMG_T, LCTX, 0, 8);
    cvt_batch<<<blk, 256>>>(CP);

    // batched projection GEMMs: Q, K_txt, V_txt, K_img, V_img (one launch)
    GParams P;
    P.j[0] = { xh,  xl,  wqh,  wql,  b_q,     Qb,  nullptr, nullptr, BATCH * LQ,    0    };
    P.j[1] = { cth, ctl, wkh,  wkl,  b_k,     Ktb, nullptr, nullptr, BATCH * TXT_T, 1024 };
    P.j[2] = { cth, ctl, wvh,  wvl,  b_v,     nullptr, Vthp, Vtlp,   BATCH * TXT_T, 1152 };
    P.j[3] = { cih, cil, wkih, wkil, b_k_img, Kib, nullptr, nullptr, BATCH * IMG_T, 1280 };
    P.j[4] = { cih, cil, wvih, wvil, b_v_img, nullptr, Vihp, Vilp,   BATCH * IMG_T, 1360 };
    gemm_batch<<<1440, 256, GEMM_SMEM>>>(P);

    // one batched rmsnorm+split launch (Q, K_txt, K_img)
    RParams RP;
    RP.j[0] = { Qb,  g_q,     Qhp,  Qlp,  0 };
    RP.j[1] = { Ktb, g_k,     Kthp, Ktlp, BATCH * LQ };
    RP.j[2] = { Kib, g_k_img, Kihp, Kilp, BATCH * LQ + BATCH * TXT_T };
    rmsnorm_batch<<<BATCH * LQ + BATCH * TXT_T + BATCH * IMG_T, 256>>>(RP);

    // flash attention (img + txt, lens-trimmed) -> g_ah/g_al (bf16 hi/lo)
    attn_kernel<<<dim3(LQ / 128, NHEADS, BATCH), 256, ATT_SMEM>>>(lens);

    // out = attn @ w_o^T + b_o (single-job batched kernel)
    GParams PO;
    PO.j[0] = { ah, al, woh, wol, b_o, out, nullptr, nullptr, BATCH * LQ, 0 };
    PO.j[1] = PO.j[2] = PO.j[3] = PO.j[4] = PO.j[0];
    PO.j[1].cta0 = PO.j[2].cta0 = PO.j[3].cta0 = PO.j[4].cta0 = 1 << 30;
    gemm_batch<<<1024, 256, GEMM_SMEM>>>(PO);
}

// round 9
// speedup vs baseline: 3.8550x; 1.0003x over previous
#include <cuda_runtime.h>
#include <cuda_bf16.h>
#include <math.h>
#include <stdint.h>

#define DIMN 2048
#define NHEADS 16
#define HDIM 128
#define BATCH 2
#define LQ 4096
#define LCTX 769
#define IMG_T 257
#define TXT_T 512
#define EPS_F 1e-6f
#define ATT_SCALE 0.08838834764831845f  /* 1/sqrt(128) */

// ---------------- scratch (device globals; no allocs allowed) --------------
__device__ float g_Q   [BATCH * LQ    * DIMN];
__device__ float g_Ktxt[BATCH * TXT_T * DIMN];
__device__ float g_Kimg[BATCH * IMG_T * DIMN];

// bf16 hi/lo split buffers
#define MPAD_IMG 640
__device__ __nv_bfloat16 g_xh [BATCH * LQ * DIMN];
__device__ __nv_bfloat16 g_xl [BATCH * LQ * DIMN];
__device__ __nv_bfloat16 g_ah [BATCH * LQ * DIMN];
__device__ __nv_bfloat16 g_al [BATCH * LQ * DIMN];
__device__ __nv_bfloat16 g_cth[BATCH * TXT_T * DIMN];
__device__ __nv_bfloat16 g_ctl[BATCH * TXT_T * DIMN];
__device__ __nv_bfloat16 g_cih[MPAD_IMG * DIMN];
__device__ __nv_bfloat16 g_cil[MPAD_IMG * DIMN];
__device__ __nv_bfloat16 g_wqh [DIMN * DIMN], g_wql [DIMN * DIMN];
__device__ __nv_bfloat16 g_wkh [DIMN * DIMN], g_wkl [DIMN * DIMN];
__device__ __nv_bfloat16 g_wvh [DIMN * DIMN], g_wvl [DIMN * DIMN];
__device__ __nv_bfloat16 g_wkih[DIMN * DIMN], g_wkil[DIMN * DIMN];
__device__ __nv_bfloat16 g_wvih[DIMN * DIMN], g_wvil[DIMN * DIMN];
__device__ __nv_bfloat16 g_woh [DIMN * DIMN], g_wol [DIMN * DIMN];

// attention-side hi/lo operands
__device__ __nv_bfloat16 g_Qh [BATCH * LQ * DIMN],    g_Ql [BATCH * LQ * DIMN];
__device__ __nv_bfloat16 g_Kth[BATCH * TXT_T * DIMN], g_Ktl[BATCH * TXT_T * DIMN];
__device__ __nv_bfloat16 g_Vth[BATCH * TXT_T * DIMN], g_Vtl[BATCH * TXT_T * DIMN];
__device__ __nv_bfloat16 g_Kih[BATCH * IMG_T * DIMN], g_Kil[BATCH * IMG_T * DIMN];
__device__ __nv_bfloat16 g_Vih[MPAD_IMG * DIMN],      g_Vil[MPAD_IMG * DIMN];

// ---------------------------- helpers ---------------------------------------
__device__ __forceinline__ uint32_t smem_u32(const void* p) {
    uint32_t a;
    asm("{ .reg .u64 t; cvta.to.shared.u64 t, %1; cvt.u32.u64 %0, t; }"
        : "=r"(a) : "l"(p));
    return a;
}

__device__ __forceinline__ void mma16816(float* d, const uint32_t* a,
                                         const uint32_t b0, const uint32_t b1) {
    asm volatile(
        "mma.sync.aligned.m16n8k16.row.col.f32.bf16.bf16.f32 "
        "{%0,%1,%2,%3}, {%4,%5,%6,%7}, {%8,%9}, {%0,%1,%2,%3};"
        : "+f"(d[0]), "+f"(d[1]), "+f"(d[2]), "+f"(d[3])
        : "r"(a[0]), "r"(a[1]), "r"(a[2]), "r"(a[3]), "r"(b0), "r"(b1));
}

__device__ __forceinline__ void ldsm4(uint32_t* r, uint32_t a) {
    asm volatile("ldmatrix.sync.aligned.m8n8.x4.shared.b16 {%0,%1,%2,%3}, [%4];"
                 : "=r"(r[0]), "=r"(r[1]), "=r"(r[2]), "=r"(r[3]) : "r"(a));
}
__device__ __forceinline__ void ldsm4t(uint32_t* r, uint32_t a) {
    asm volatile("ldmatrix.sync.aligned.m8n8.x4.trans.shared.b16 {%0,%1,%2,%3}, [%4];"
                 : "=r"(r[0]), "=r"(r[1]), "=r"(r[2]), "=r"(r[3]) : "r"(a));
}
__device__ __forceinline__ void cp16(uint32_t d, const void* s) {
    asm volatile("cp.async.cg.shared.global [%0], [%1], 16;"
                 :: "r"(d), "l"(s) : "memory");
}
__device__ __forceinline__ void cp16z(uint32_t d, const void* s, int sz) {
    asm volatile("cp.async.cg.shared.global [%0], [%1], 16, %2;"
                 :: "r"(d), "l"(s), "r"(sz) : "memory");
}
#define CP_COMMIT() asm volatile("cp.async.commit_group;" ::: "memory")
#define CP_WAIT(n)  asm volatile("cp.async.wait_group %0;" :: "n"(n) : "memory")

// f32x2 -> bf16x2 hi + lo residual
__device__ __forceinline__ void split2(float2 f, uint32_t& h, uint32_t& l) {
    __nv_bfloat162 hb = __float22bfloat162_rn(f);
    float2 hf = __bfloat1622float2(hb);
    __nv_bfloat162 lb = __float22bfloat162_rn(make_float2(f.x - hf.x, f.y - hf.y));
    h = *(uint32_t*)&hb;
    l = *(uint32_t*)&lb;
}

// -------------- batched fp32 -> bf16 hi/lo split (9 jobs, one launch) ------
struct CJob {
    const float* src;
    __nv_bfloat16 *hi, *lo;
    int Mvalid, rows_pb, bstride, roff, blk0;
};
struct CParams { CJob j[9]; };

__global__ __launch_bounds__(256)
void cvt_batch(CParams P)
{
    const int bid = blockIdx.x;
    int ji = 0;
#pragma unroll
    for (int k = 1; k < 9; k++) if (bid >= P.j[k].blk0) ji = k;
    const CJob& J = P.j[ji];

    const long e = (long)(bid - J.blk0) * 1024 + threadIdx.x * 4;
    const int m = (int)(e >> 11);
    const int col = (int)(e & 2047);

    float4 v = make_float4(0.f, 0.f, 0.f, 0.f);
    if (m < J.Mvalid) {
        const int bb = m / J.rows_pb;
        const long srow = (long)bb * J.bstride + J.roff + (m - bb * J.rows_pb);
        v = *(const float4*)(J.src + srow * DIMN + col);
    }
    uint32_t h0, l0, h1, l1;
    split2(make_float2(v.x, v.y), h0, l0);
    split2(make_float2(v.z, v.w), h1, l1);
    *(uint2*)(J.hi + e) = make_uint2(h0, h1);
    *(uint2*)(J.lo + e) = make_uint2(l0, l1);
}

// ------------- batched HMMA GEMM: C = (Ah+Al)(Bh+Bl)^T + bias (3 terms) ----
#define GT_KC 32
#define NCHUNK (DIMN / GT_KC)        /* 64 */
#define TILE_B   10240               /* 128 x 80 bytes */
#define BUF_B    (4 * TILE_B)
#define GEMM_SMEM (2 * BUF_B)

struct GJob {
    const __nv_bfloat16 *Ah, *Al, *Bh, *Bl;
    const float *bias;
    float *C;                      // fp32 out (may be null)
    __nv_bfloat16 *Ch, *Cl;        // hi/lo out (may be null)
    int Mvalid;
    int cta0;
};
struct GParams { GJob j[5]; };

__global__ __launch_bounds__(256, 2)
void gemm_batch(GParams P)
{
    extern __shared__ __nv_bfloat16 sm[];

    const int bid = blockIdx.x;
    int ji = 0;
#pragma unroll
    for (int k = 1; k < 5; k++) if (bid >= P.j[k].cta0) ji = k;
    const GJob& J = P.j[ji];
    const int local = bid - J.cta0;
    const int n0 = (local & 15) * 128;
    const int m0 = (local >> 4) * 128;

    const int tid = threadIdx.x;
    const int wid = tid >> 5;
    const int lane = tid & 31;
    const int wm = wid & 3;
    const int wn = wid >> 2;

    const __nv_bfloat16* srcs[4] = {
        J.Ah + (size_t)m0 * DIMN, J.Al + (size_t)m0 * DIMN,
        J.Bh + (size_t)n0 * DIMN, J.Bl + (size_t)n0 * DIMN };

    const uint32_t smb = smem_u32(sm);

    auto load_chunk = [&](int c, int b) {
        const int k0 = c * GT_KC;
#pragma unroll
        for (int j = 0; j < 8; j++) {
            const int f = j * 256 + tid;
            const int tile = f >> 9;
            const int w = f & 511;
            const int r = w >> 2;
            const int cc = w & 3;
            const __nv_bfloat16* sp = srcs[tile] + (size_t)r * DIMN + k0 + cc * 8;
            cp16(smb + b * BUF_B + tile * TILE_B + r * 80 + cc * 16, sp);
        }
        CP_COMMIT();
    };

    float acc[2][8][4];
#pragma unroll
    for (int i = 0; i < 2; i++)
#pragma unroll
        for (int j = 0; j < 8; j++)
#pragma unroll
            for (int q = 0; q < 4; q++) acc[i][j][q] = 0.f;

    const uint32_t aOff = (uint32_t)(wm * 32 + (lane & 15)) * 80 + ((lane >> 4) * 16);
    const uint32_t bOff = (uint32_t)(wn * 64 + (lane & 7) + ((lane >> 4) << 3)) * 80
                        + (((lane >> 3) & 1) * 16) + 2 * TILE_B;

    load_chunk(0, 0);
    load_chunk(1, 1);

    for (int c = 0; c < NCHUNK; c++) {
        const int b = c & 1;
        if (c == NCHUNK - 1) CP_WAIT(0);
        else                 CP_WAIT(1);
        __syncthreads();

        const uint32_t buf = smb + b * BUF_B;

#pragma unroll
        for (int s = 0; s < 2; s++) {
            uint32_t ah_[2][4], al_[2][4];
#pragma unroll
            for (int mt = 0; mt < 2; mt++) {
                ldsm4(ah_[mt], buf + aOff + mt * 16 * 80 + s * 32);
                ldsm4(al_[mt], buf + aOff + mt * 16 * 80 + s * 32 + TILE_B);
            }
#pragma unroll
            for (int t = 0; t < 4; t++) {
                uint32_t bh_[4], bl_[4];
                ldsm4(bh_, buf + bOff + t * 16 * 80 + s * 32);
                ldsm4(bl_, buf + bOff + t * 16 * 80 + s * 32 + TILE_B);
#pragma unroll
                for (int mt = 0; mt < 2; mt++) {
                    mma16816(acc[mt][2 * t],     ah_[mt], bh_[0], bh_[1]);
                    mma16816(acc[mt][2 * t],     ah_[mt], bl_[0], bl_[1]);
                    mma16816(acc[mt][2 * t],     al_[mt], bh_[0], bh_[1]);
                    mma16816(acc[mt][2 * t + 1], ah_[mt], bh_[2], bh_[3]);
                    mma16816(acc[mt][2 * t + 1], ah_[mt], bl_[2], bl_[3]);
                    mma16816(acc[mt][2 * t + 1], al_[mt], bh_[2], bh_[3]);
                }
            }
        }
        __syncthreads();
        if (c + 2 < NCHUNK) load_chunk(c + 2, b);
    }

    const int lr = lane >> 2;
    const int lc = (lane & 3) * 2;
#pragma unroll
    for (int mt = 0; mt < 2; mt++) {
#pragma unroll
        for (int nt = 0; nt < 8; nt++) {
            const int n = n0 + wn * 64 + nt * 8 + lc;
            const float2 bv = *(const float2*)&J.bias[n];
            const int mA = m0 + wm * 32 + mt * 16 + lr;
            float2 o0 = make_float2(acc[mt][nt][0] + bv.x, acc[mt][nt][1] + bv.y);
            float2 o1 = make_float2(acc[mt][nt][2] + bv.x, acc[mt][nt][3] + bv.y);
            if (J.C) {
                if (mA < J.Mvalid)     *(float2*)(J.C + (size_t)mA * DIMN + n) = o0;
                if (mA + 8 < J.Mvalid) *(float2*)(J.C + (size_t)(mA + 8) * DIMN + n) = o1;
            }
            if (J.Ch) {
                uint32_t hh, ll;
                if (mA < J.Mvalid) {
                    split2(o0, hh, ll);
                    *(uint32_t*)(J.Ch + (size_t)mA * DIMN + n) = hh;
                    *(uint32_t*)(J.Cl + (size_t)mA * DIMN + n) = ll;
                }
                if (mA + 8 < J.Mvalid) {
                    split2(o1, hh, ll);
                    *(uint32_t*)(J.Ch + (size_t)(mA + 8) * DIMN + n) = hh;
                    *(uint32_t*)(J.Cl + (size_t)(mA + 8) * DIMN + n) = ll;
                }
            }
        }
    }
}

// ------------- batched RMS norm -> bf16 hi/lo split (3 jobs) ---------------
struct RJob {
    const float* X;
    const float* g;
    __nv_bfloat16 *H, *L;
    int row0;
};
struct RParams { RJob j[3]; };

__global__ __launch_bounds__(256)
void rmsnorm_batch(RParams P)
{
    const int bid = blockIdx.x;
    int ji = 0;
#pragma unroll
    for (int k = 1; k < 3; k++) if (bid >= P.j[k].row0) ji = k;
    const RJob& J = P.j[ji];
    const int row = bid - J.row0;

    const float* xr = J.X + (long)row * DIMN;
    const int t = threadIdx.x;

    float4 v0 = *(const float4*)&xr[t * 4];
    float4 v1 = *(const float4*)&xr[1024 + t * 4];
    float ss = v0.x * v0.x + v0.y * v0.y + v0.z * v0.z + v0.w * v0.w
             + v1.x * v1.x + v1.y * v1.y + v1.z * v1.z + v1.w * v1.w;

#pragma unroll
    for (int o = 16; o > 0; o >>= 1) ss += __shfl_xor_sync(0xffffffffu, ss, o);

    __shared__ float red[8];
    if ((t & 31) == 0) red[t >> 5] = ss;
    __syncthreads();
    float total = 0.f;
#pragma unroll
    for (int i = 0; i < 8; i++) total += red[i];

    const float scale = rsqrtf(total * (1.0f / DIMN) + EPS_F);

    const float4 g0 = *(const float4*)&J.g[t * 4];
    const float4 g1 = *(const float4*)&J.g[1024 + t * 4];
    v0.x *= scale * g0.x; v0.y *= scale * g0.y; v0.z *= scale * g0.z; v0.w *= scale * g0.w;
    v1.x *= scale * g1.x; v1.y *= scale * g1.y; v1.z *= scale * g1.z; v1.w *= scale * g1.w;

    uint32_t h0, l0, h1, l1;
    split2(make_float2(v0.x, v0.y), h0, l0);
    split2(make_float2(v0.z, v0.w), h1, l1);
    *(uint2*)(J.H + (long)row * DIMN + t * 4) = make_uint2(h0, h1);
    *(uint2*)(J.L + (long)row * DIMN + t * 4) = make_uint2(l0, l1);
    split2(make_float2(v1.x, v1.y), h0, l0);
    split2(make_float2(v1.z, v1.w), h1, l1);
    *(uint2*)(J.H + (long)row * DIMN + 1024 + t * 4) = make_uint2(h0, h1);
    *(uint2*)(J.L + (long)row * DIMN + 1024 + t * 4) = make_uint2(l0, l1);
}

// ---------------- flash attention (img + txt), HMMA 3-term ------------------
// q-tile 128, 8 warps (16 q-rows each, full 64-key chunk width).
// Q + online stats + O register-resident; K/V double-buffered cp.async.
// chunks: 5 img (valid 257) + ceil(lens[b]/64) txt chunks (lens-trimmed).
#define KVB 34816                    /* one K or V buffer: hi 64x272 + lo */
#define OST_OFF (4 * KVB)            /* 139264 */
#define ATT_SMEM (OST_OFF + 128 * 128 * 4)   /* 204800 */

__global__ __launch_bounds__(256, 1)
void attn_kernel(const int* __restrict__ lens)
{
    extern __shared__ char smraw[];
    const uint32_t smb = smem_u32(smraw);
    float* Ost = (float*)(smraw + OST_OFF);

    const int qt = blockIdx.x, h = blockIdx.y, b = blockIdx.z;
    const int tid = threadIdx.x;
    const int wq = tid >> 5;
    const int lane = tid & 31;
    const int q0 = qt * 128;

    const int vtxt = min(lens[b], TXT_T);
    const int nch = 5 + ((vtxt + 63) >> 6);       // 9..13 chunks
    const size_t ibase = (size_t)b * IMG_T * DIMN + h * HDIM;
    const size_t tbase = (size_t)b * TXT_T * DIMN + h * HDIM;

    // ---- stage Q hi/lo into smem (KB area), then ldmatrix into regs ----
    for (int f = tid; f < 2048; f += 256) {
        const int r = f >> 4, c = f & 15;
        const size_t off = ((size_t)(b * LQ + q0 + r)) * DIMN + h * HDIM + c * 8;
        cp16(smb + r * 272 + c * 16,         g_Qh + off);
        cp16(smb + KVB + r * 272 + c * 16,   g_Ql + off);
    }
    CP_COMMIT();
    CP_WAIT(0);
    __syncthreads();

    uint32_t qh[8][4], ql[8][4];
    {
        const uint32_t aQ = smb + (uint32_t)(wq * 16 + (lane & 15)) * 272
                          + ((lane >> 4) * 16);
#pragma unroll
        for (int s8 = 0; s8 < 8; s8++) {
            ldsm4(qh[s8], aQ + s8 * 32);
            ldsm4(ql[s8], aQ + s8 * 32 + KVB);
        }
    }
    __syncthreads();

    // ---- chunk loaders ----
    auto loadK = [&](int ci) {
        if (ci < nch) {
            const __nv_bfloat16 *kh, *kl; int kbase, Lk; size_t base;
            if (ci < 5) { kh = g_Kih; kl = g_Kil; kbase = ci * 64; Lk = IMG_T; base = ibase; }
            else        { kh = g_Kth; kl = g_Ktl; kbase = (ci - 5) * 64; Lk = TXT_T; base = tbase; }
            const uint32_t dst = smb + (ci & 1) * KVB;
            for (int f = tid; f < 1024; f += 256) {
                const int r = f >> 4, cc = f & 15;
                const int kr = kbase + r;
                const int sz = (kr < Lk) ? 16 : 0;
                const int krc = (kr < Lk) ? kr : 0;
                const size_t off = base + (size_t)krc * DIMN + cc * 8;
                cp16z(dst + r * 272 + cc * 16,          kh + off, sz);
                cp16z(dst + 17408 + r * 272 + cc * 16,  kl + off, sz);
            }
        }
        CP_COMMIT();
    };
    auto loadV = [&](int ci) {
        if (ci < nch) {
            const __nv_bfloat16 *vh, *vl; int kbase, Lk; size_t base;
            if (ci < 5) { vh = g_Vih; vl = g_Vil; kbase = ci * 64; Lk = IMG_T; base = ibase; }
            else        { vh = g_Vth; vl = g_Vtl; kbase = (ci - 5) * 64; Lk = TXT_T; base = tbase; }
            const uint32_t dst = smb + 2 * KVB + (ci & 1) * KVB;
            for (int f = tid; f < 1024; f += 256) {
                const int r = f >> 4, cc = f & 15;
                const int kr = kbase + r;
                const int sz = (kr < Lk) ? 16 : 0;
                const int krc = (kr < Lk) ? kr : 0;
                const size_t off = base + (size_t)krc * DIMN + cc * 8;
                cp16z(dst + r * 272 + cc * 16,          vh + off, sz);
                cp16z(dst + 17408 + r * 272 + cc * 16,  vl + off, sz);
            }
        }
        CP_COMMIT();
    };

    float o[16][4];
#pragma unroll
    for (int i = 0; i < 16; i++)
#pragma unroll
        for (int j = 0; j < 4; j++) o[i][j] = 0.f;
    float m0 = -1e30f, m1 = -1e30f, l0 = 0.f, l1 = 0.f;

    const uint32_t kbK = (uint32_t)((lane & 7) + ((lane >> 4) << 3)) * 272
                       + (((lane >> 3) & 1) * 16);
    const uint32_t vbV = (uint32_t)(lane & 15) * 272 + ((lane >> 4) * 16);
    const int qg = lane >> 2;             // row within 16
    const int qc = 2 * (lane & 3);        // col pair base

    // pipeline prologue: K0, V0, K1
    loadK(0); loadV(0); loadK(1);

    for (int ci = 0; ci < nch; ci++) {
        const int buf = ci & 1;
        const int kbase = (ci < 5) ? ci * 64 : (ci - 5) * 64;
        const int valid = (ci < 5) ? IMG_T : vtxt;

        CP_WAIT(2);               // K(ci) ready
        __syncthreads();
        loadV(ci + 1);            // prefetch (VB[buf^1] free)

        // ---- QK scores (3-term) ----
        float s[8][4];
#pragma unroll
        for (int i = 0; i < 8; i++)
#pragma unroll
            for (int j = 0; j < 4; j++) s[i][j] = 0.f;

        const uint32_t KH = smb + buf * KVB;
#pragma unroll
        for (int s8 = 0; s8 < 8; s8++) {
#pragma unroll
            for (int t = 0; t < 4; t++) {
                uint32_t kh_[4], kl_[4];
                ldsm4(kh_, KH + kbK + t * 16 * 272 + s8 * 32);
                ldsm4(kl_, KH + kbK + t * 16 * 272 + s8 * 32 + 17408);
                mma16816(s[2 * t],     qh[s8], kh_[0], kh_[1]);
                mma16816(s[2 * t],     qh[s8], kl_[0], kl_[1]);
                mma16816(s[2 * t],     ql[s8], kh_[0], kh_[1]);
                mma16816(s[2 * t + 1], qh[s8], kh_[2], kh_[3]);
                mma16816(s[2 * t + 1], qh[s8], kl_[2], kl_[3]);
                mma16816(s[2 * t + 1], ql[s8], kh_[2], kh_[3]);
            }
        }

        // ---- online softmax (register-resident, quad reduce) ----
        float cm0 = -1e30f, cm1 = -1e30f;
#pragma unroll
        for (int nt = 0; nt < 8; nt++) {
            const int c0 = kbase + nt * 8 + qc;
#pragma unroll
            for (int j = 0; j < 2; j++) {
                const bool ok = (c0 + j) < valid;
                float t0 = ok ? s[nt][j] * ATT_SCALE : -1e30f;
                float t1 = ok ? s[nt][j + 2] * ATT_SCALE : -1e30f;
                s[nt][j] = t0; s[nt][j + 2] = t1;
                cm0 = fmaxf(cm0, t0); cm1 = fmaxf(cm1, t1);
            }
        }
        cm0 = fmaxf(cm0, __shfl_xor_sync(0xffffffffu, cm0, 1));
        cm0 = fmaxf(cm0, __shfl_xor_sync(0xffffffffu, cm0, 2));
        cm1 = fmaxf(cm1, __shfl_xor_sync(0xffffffffu, cm1, 1));
        cm1 = fmaxf(cm1, __shfl_xor_sync(0xffffffffu, cm1, 2));

        const float mn0 = fmaxf(m0, cm0), mn1 = fmaxf(m1, cm1);
        const float sc0 = __expf(m0 - mn0), sc1 = __expf(m1 - mn1);
        m0 = mn0; m1 = mn1;

        float sum0 = 0.f, sum1 = 0.f;
#pragma unroll
        for (int nt = 0; nt < 8; nt++) {
#pragma unroll
            for (int j = 0; j < 2; j++) {
                float p0 = __expf(s[nt][j] - m0);
                float p1 = __expf(s[nt][j + 2] - m1);
                s[nt][j] = p0; s[nt][j + 2] = p1;
                sum0 += p0; sum1 += p1;
            }
        }
        sum0 += __shfl_xor_sync(0xffffffffu, sum0, 1);
        sum0 += __shfl_xor_sync(0xffffffffu, sum0, 2);
        sum1 += __shfl_xor_sync(0xffffffffu, sum1, 1);
        sum1 += __shfl_xor_sync(0xffffffffu, sum1, 2);
        l0 = l0 * sc0 + sum0;
        l1 = l1 * sc1 + sum1;
#pragma unroll
        for (int nt = 0; nt < 16; nt++) {
            o[nt][0] *= sc0; o[nt][1] *= sc0;
            o[nt][2] *= sc1; o[nt][3] *= sc1;
        }

        CP_WAIT(2);               // V(ci) ready
        __syncthreads();
        loadK(ci + 2);            // prefetch (KB[buf] done)

        // ---- P @ V (3-term; P C-frags reused as A-frags) ----
        const uint32_t VH = smb + 2 * KVB + buf * KVB;
#pragma unroll
        for (int kk = 0; kk < 4; kk++) {
            uint32_t pah[4], pal[4];
            split2(make_float2(s[2 * kk][0],     s[2 * kk][1]),     pah[0], pal[0]);
            split2(make_float2(s[2 * kk][2],     s[2 * kk][3]),     pah[1], pal[1]);
            split2(make_float2(s[2 * kk + 1][0], s[2 * kk + 1][1]), pah[2], pal[2]);
            split2(make_float2(s[2 * kk + 1][2], s[2 * kk + 1][3]), pah[3], pal[3]);
            const uint32_t va = VH + vbV + kk * 16 * 272;
#pragma unroll
            for (int t = 0; t < 8; t++) {
                uint32_t vh_[4], vl_[4];
                ldsm4t(vh_, va + t * 32);
                ldsm4t(vl_, va + t * 32 + 17408);
                mma16816(o[2 * t],     pah, vh_[0], vh_[1]);
                mma16816(o[2 * t],     pah, vl_[0], vl_[1]);
                mma16816(o[2 * t],     pal, vh_[0], vh_[1]);
                mma16816(o[2 * t + 1], pah, vh_[2], vh_[3]);
                mma16816(o[2 * t + 1], pah, vl_[2], vl_[3]);
                mma16816(o[2 * t + 1], pal, vh_[2], vh_[3]);
            }
        }

        // ---- end of img phase: stash normalized output, reset stats ----
        if (ci == 4) {
            const float i0 = 1.f / l0, i1 = 1.f / l1;
            const int r0 = wq * 16 + qg;
#pragma unroll
            for (int nt = 0; nt < 16; nt++) {
                const int col = nt * 8 + qc;
                *(float2*)&Ost[r0 * 128 + col] =
                    make_float2(o[nt][0] * i0, o[nt][1] * i0);
                *(float2*)&Ost[(r0 + 8) * 128 + col] =
                    make_float2(o[nt][2] * i1, o[nt][3] * i1);
                o[nt][0] = o[nt][1] = o[nt][2] = o[nt][3] = 0.f;
            }
            m0 = m1 = -1e30f; l0 = l1 = 0.f;
        }
    }

    // ---- epilogue: out = img_stash + txt/l, write bf16 hi/lo ----
    const float i0 = 1.f / l0, i1 = 1.f / l1;
    const int r0 = wq * 16 + qg;
#pragma unroll
    for (int nt = 0; nt < 16; nt++) {
        const int col = nt * 8 + qc;
        const float2 e0 = *(const float2*)&Ost[r0 * 128 + col];
        const float2 e1 = *(const float2*)&Ost[(r0 + 8) * 128 + col];
        const int gcol = h * HDIM + col;
        const size_t a0 = (size_t)(b * LQ + q0 + r0) * DIMN + gcol;
        const size_t a1 = (size_t)(b * LQ + q0 + r0 + 8) * DIMN + gcol;
        uint32_t hh, ll;
        split2(make_float2(e0.x + o[nt][0] * i0, e0.y + o[nt][1] * i0), hh, ll);
        *(uint32_t*)&g_ah[a0] = hh;
        *(uint32_t*)&g_al[a0] = ll;
        split2(make_float2(e1.x + o[nt][2] * i1, e1.y + o[nt][3] * i1), hh, ll);
        *(uint32_t*)&g_ah[a1] = hh;
        *(uint32_t*)&g_al[a1] = ll;
    }
}

// ---------------------------- launch ---------------------------------------
extern "C" void kernel_launch(void* const* d_in, const int* in_sizes, int n_in,
                              void* d_out, int out_size)
{
    const float* x        = (const float*)d_in[0];
    const float* context  = (const float*)d_in[1];
    const int*   lens     = (const int*)  d_in[2];
    const float* w_q      = (const float*)d_in[3];
    const float* b_q      = (const float*)d_in[4];
    const float* w_k      = (const float*)d_in[5];
    const float* b_k      = (const float*)d_in[6];
    const float* w_v      = (const float*)d_in[7];
    const float* b_v      = (const float*)d_in[8];
    const float* w_k_img  = (const float*)d_in[9];
    const float* b_k_img  = (const float*)d_in[10];
    const float* w_v_img  = (const float*)d_in[11];
    const float* b_v_img  = (const float*)d_in[12];
    const float* w_o      = (const float*)d_in[13];
    const float* b_o      = (const float*)d_in[14];
    const float* g_q      = (const float*)d_in[15];
    const float* g_k      = (const float*)d_in[16];
    const float* g_k_img  = (const float*)d_in[17];
    float* out = (float*)d_out;

    float *Qb, *Ktb, *Kib;
    cudaGetSymbolAddress((void**)&Qb,  g_Q);
    cudaGetSymbolAddress((void**)&Ktb, g_Ktxt);
    cudaGetSymbolAddress((void**)&Kib, g_Kimg);

    __nv_bfloat16 *xh, *xl, *ah, *al, *cth, *ctl, *cih, *cil;
    __nv_bfloat16 *wqh, *wql, *wkh, *wkl, *wvh, *wvl, *wkih, *wkil, *wvih, *wvil, *woh, *wol;
    __nv_bfloat16 *Qhp, *Qlp, *Kthp, *Ktlp, *Vthp, *Vtlp, *Kihp, *Kilp, *Vihp, *Vilp;
    cudaGetSymbolAddress((void**)&xh,  g_xh);   cudaGetSymbolAddress((void**)&xl,  g_xl);
    cudaGetSymbolAddress((void**)&ah,  g_ah);   cudaGetSymbolAddress((void**)&al,  g_al);
    cudaGetSymbolAddress((void**)&cth, g_cth);  cudaGetSymbolAddress((void**)&ctl, g_ctl);
    cudaGetSymbolAddress((void**)&cih, g_cih);  cudaGetSymbolAddress((void**)&cil, g_cil);
    cudaGetSymbolAddress((void**)&wqh, g_wqh);  cudaGetSymbolAddress((void**)&wql, g_wql);
    cudaGetSymbolAddress((void**)&wkh, g_wkh);  cudaGetSymbolAddress((void**)&wkl, g_wkl);
    cudaGetSymbolAddress((void**)&wvh, g_wvh);  cudaGetSymbolAddress((void**)&wvl, g_wvl);
    cudaGetSymbolAddress((void**)&wkih, g_wkih); cudaGetSymbolAddress((void**)&wkil, g_wkil);
    cudaGetSymbolAddress((void**)&wvih, g_wvih); cudaGetSymbolAddress((void**)&wvil, g_wvil);
    cudaGetSymbolAddress((void**)&woh, g_woh);  cudaGetSymbolAddress((void**)&wol, g_wol);
    cudaGetSymbolAddress((void**)&Qhp, g_Qh);   cudaGetSymbolAddress((void**)&Qlp, g_Ql);
    cudaGetSymbolAddress((void**)&Kthp, g_Kth); cudaGetSymbolAddress((void**)&Ktlp, g_Ktl);
    cudaGetSymbolAddress((void**)&Vthp, g_Vth); cudaGetSymbolAddress((void**)&Vtlp, g_Vtl);
    cudaGetSymbolAddress((void**)&Kihp, g_Kih); cudaGetSymbolAddress((void**)&Kilp, g_Kil);
    cudaGetSymbolAddress((void**)&Vihp, g_Vih); cudaGetSymbolAddress((void**)&Vilp, g_Vil);

    cudaFuncSetAttribute(gemm_batch, cudaFuncAttributeMaxDynamicSharedMemorySize, GEMM_SMEM);
    cudaFuncSetAttribute(attn_kernel, cudaFuncAttributeMaxDynamicSharedMemorySize, ATT_SMEM);

    // one batched conversion launch (9 jobs)
    // blocks per job = rows * 2  (1024 elems per block)
    CParams CP;
    int blk = 0;
    auto addc = [&](const float* s, __nv_bfloat16* H, __nv_bfloat16* L,
                    int Mvalid, int Mpad, int rows_pb, int bstride, int roff, int idx) {
        CP.j[idx] = { s, H, L, Mvalid, rows_pb, bstride, roff, blk };
        blk += Mpad * 2;
    };
    addc(x,       xh,   xl,   BATCH * LQ,    BATCH * LQ,    BATCH * LQ, 0, 0, 0);
    addc(w_q,     wqh,  wql,  DIMN, DIMN, DIMN, 0, 0, 1);
    addc(w_k,     wkh,  wkl,  DIMN, DIMN, DIMN, 0, 0, 2);
    addc(w_v,     wvh,  wvl,  DIMN, DIMN, DIMN, 0, 0, 3);
    addc(w_k_img, wkih, wkil, DIMN, DIMN, DIMN, 0, 0, 4);
    addc(w_v_img, wvih, wvil, DIMN, DIMN, DIMN, 0, 0, 5);
    addc(w_o,     woh,  wol,  DIMN, DIMN, DIMN, 0, 0, 6);
    addc(context, cth,  ctl,  BATCH * TXT_T, BATCH * TXT_T, TXT_T, LCTX, IMG_T, 7);
    addc(context, cih,  cil,  BATCH * IMG_T, MPAD_IMG,      IMG_T, LCTX, 0, 8);
    cvt_batch<<<blk, 256>>>(CP);

    // batched projection GEMMs: Q, K_txt, V_txt, K_img, V_img (one launch)
    GParams P;
    P.j[0] = { xh,  xl,  wqh,  wql,  b_q,     Qb,  nullptr, nullptr, BATCH * LQ,    0    };
    P.j[1] = { cth, ctl, wkh,  wkl,  b_k,     Ktb, nullptr, nullptr, BATCH * TXT_T, 1024 };
    P.j[2] = { cth, ctl, wvh,  wvl,  b_v,     nullptr, Vthp, Vtlp,   BATCH * TXT_T, 1152 };
    P.j[3] = { cih, cil, wkih, wkil, b_k_img, Kib, nullptr, nullptr, BATCH * IMG_T, 1280 };
    P.j[4] = { cih, cil, wvih, wvil, b_v_img, nullptr, Vihp, Vilp,   BATCH * IMG_T, 1360 };
    gemm_batch<<<1440, 256, GEMM_SMEM>>>(P);

    // one batched rmsnorm+split launch (Q, K_txt, K_img)
    RParams RP;
    RP.j[0] = { Qb,  g_q,     Qhp,  Qlp,  0 };
    RP.j[1] = { Ktb, g_k,     Kthp, Ktlp, BATCH * LQ };
    RP.j[2] = { Kib, g_k_img, Kihp, Kilp, BATCH * LQ + BATCH * TXT_T };
    rmsnorm_batch<<<BATCH * LQ + BATCH * TXT_T + BATCH * IMG_T, 256>>>(RP);

    // flash attention (img + txt, lens-trimmed) -> g_ah/g_al (bf16 hi/lo)
    attn_kernel<<<dim3(LQ / 128, NHEADS, BATCH), 256, ATT_SMEM>>>(lens);

    // out = attn @ w_o^T + b_o (single-job batched kernel)
    GParams PO;
    PO.j[0] = { ah, al, woh, wol, b_o, out, nullptr, nullptr, BATCH * LQ, 0 };
    PO.j[1] = PO.j[2] = PO.j[3] = PO.j[4] = PO.j[0];
    PO.j[1].cta0 = PO.j[2].cta0 = PO.j[3].cta0 = PO.j[4].cta0 = 1 << 30;
    gemm_batch<<<1024, 256, GEMM_SMEM>>>(PO);
}